// round 7
// baseline (speedup 1.0000x reference)
#include <cuda_runtime.h>
#include <stdint.h>
#include <math.h>

// Problem constants
#define Bb 4
#define Nn 128
#define Kk 250
#define Ss 250
#define Mm 32
#define NSEQ 1000
#define LSEQ 250
#define SEQ_STRIDE 32000
#define TOT 32000000
#define PER_B 8000000
#define NM 4096

__device__ float g_y[TOT];
__device__ float g_g[TOT];
__device__ float g_b2[TOT];
__device__ float g_X1[TOT];
__device__ float g_P[2 * 6 * NM];           // planes: a_re,a_im,c2r,c2i,dre,dim
__device__ float g_kern[2 * 128 * 384];     // [path][h][128 pad + 250 taps + 6 pad]
__device__ float g_redl[4000 * 2];
__device__ float g_stats[Bb * 2];

__device__ __forceinline__ unsigned int f2tf32(float f)
{
    unsigned int u;
    asm("cvt.rna.tf32.f32 %0, %1;" : "=r"(u) : "f"(f));
    return u;
}

__device__ __forceinline__ void mma_tf32(float& c0, float& c1, float& c2, float& c3,
                                         unsigned int fa0, unsigned int fa1,
                                         unsigned int fa2, unsigned int fa3,
                                         unsigned int fb0, unsigned int fb1)
{
    asm volatile("mma.sync.aligned.m16n8k8.row.col.f32.tf32.tf32.f32 "
                 "{%0,%1,%2,%3}, {%4,%5,%6,%7}, {%8,%9}, {%0,%1,%2,%3};"
                 : "+f"(c0), "+f"(c1), "+f"(c2), "+f"(c3)
                 : "r"(fa0), "r"(fa1), "r"(fa2), "r"(fa3), "r"(fb0), "r"(fb1));
}

// ---------------- parameter prep ---------------------------------------------
__global__ void prep_params(const float* __restrict__ log_dt,
                            const float* __restrict__ logA_re,
                            const float* __restrict__ A_im,
                            const float* __restrict__ C_re,
                            const float* __restrict__ C_im,
                            int path)
{
    int h = blockIdx.x;
    int m = threadIdx.x;
    float dt  = expf(log_dt[h]);
    float Are = -expf(logA_re[h * Mm + m]);
    float Aim = A_im[h * Mm + m];
    float dre = dt * Are, dim = dt * Aim;
    float e   = expf(dre);
    float vre = e * cosf(dim);
    float vim = e * sinf(dim);
    float nre = vre - 1.0f, nim = vim;
    float d2  = Are * Are + Aim * Aim;
    float qre = (nre * Are + nim * Aim) / d2;
    float qim = (nim * Are - nre * Aim) / d2;
    float cr  = C_re[h * Mm + m], ci = C_im[h * Mm + m];
    float c2r = 2.0f * (cr * qre - ci * qim);
    float c2i = 2.0f * (cr * qim + ci * qre);
    int base = path * 6 * NM + h * Mm + m;
    g_P[base + 0 * NM] = vre;
    g_P[base + 1 * NM] = vim;
    g_P[base + 2 * NM] = c2r;
    g_P[base + 3 * NM] = c2i;
    g_P[base + 4 * NM] = dre;
    g_P[base + 5 * NM] = dim;
}

// --------- kernel taps: kern[d] = Re(sum_m C'_m a_m^d) -----------------------
__global__ void kern_gen(int path)
{
    int h = blockIdx.x;
    int tid = threadIdx.x;
    int w = tid >> 5, m = tid & 31;
    int base = path * 6 * NM + h * Mm + m;
    float ar  = g_P[base + 0 * NM];
    float ai  = g_P[base + 1 * NM];
    float c2r = g_P[base + 2 * NM];
    float c2i = g_P[base + 3 * NM];
    float dre = g_P[base + 4 * NM];
    float dim = g_P[base + 5 * NM];
    float l0 = (float)(w * 32);
    float e = expf(l0 * dre);
    float pr = e * cosf(l0 * dim);
    float pi = e * sinf(l0 * dim);
    float* kout = &g_kern[(path * 128 + h) * 384];
    if (tid < 128) kout[tid] = 0.f;
    if (tid < 6)   kout[378 + tid] = 0.f;
    for (int i = 0; i < 32; i++) {
        int l = w * 32 + i;
        float v = fmaf(c2r, pr, -c2i * pi);
        v += __shfl_xor_sync(0xffffffffu, v, 1);
        v += __shfl_xor_sync(0xffffffffu, v, 2);
        v += __shfl_xor_sync(0xffffffffu, v, 4);
        v += __shfl_xor_sync(0xffffffffu, v, 8);
        v += __shfl_xor_sync(0xffffffffu, v, 16);
        if (m == 0 && l < 250) kout[128 + l] = v;
        float t = pr;
        pr = fmaf(ar, t, -ai * pi);
        pi = fmaf(ai, t,  ar * pi);
    }
}

// ------- conv as causal Toeplitz GEMM v2: full 250 kout per block ------------
// grid (h, 16 seq-tiles). u staged once; path0 reads x directly (transposed
// smem store); path1 reads g_X1. Epilogue in 4 quarters, u from smem buffer.
__global__ void conv_gemm(int path, const float* __restrict__ x,
                          const float* __restrict__ Dv)
{
    __shared__ unsigned int ksm[384];
    __shared__ unsigned int usm[64 * 36];
    __shared__ float osm[64 * 68];
    __shared__ float ubuf[64 * 68];

    int h   = blockIdx.x;
    int s0  = blockIdx.y * 64;
    int tid = threadIdx.x;
    int w = tid >> 5, lane = tid & 31;
    int g = lane >> 2, tg = lane & 3;

    const float* kern = &g_kern[(path * 128 + h) * 384];
    for (int i = tid; i < 384; i += 256) ksm[i] = f2tf32(kern[i]);

    float c[2][8][4];
    #pragma unroll
    for (int mh = 0; mh < 2; mh++)
        #pragma unroll
        for (int nt = 0; nt < 8; nt++)
            #pragma unroll
            for (int i = 0; i < 4; i++)
                c[mh][nt][i] = 0.f;

    for (int ch = 0; ch < 8; ch++) {
        int ki0 = ch * 32;
        __syncthreads();
        if (path == 0) {
            // x[b][h][l][s]: coalesced along s; transposed store to usm
            for (int idx = tid; idx < 32 * 64; idx += 256) {
                int kk = idx >> 6, srow = idx & 63;
                int seq = s0 + srow;
                int l = ki0 + kk;
                float v = 0.f;
                if (seq < 1000 && l < 250) {
                    int b = seq / 250, s = seq - b * 250;
                    v = x[((b * 128 + h) * 250 + l) * 250 + s];
                }
                usm[srow * 36 + kk] = f2tf32(v);
            }
        } else {
            // g_X1[b][h][kq][l]: coalesced along l
            for (int idx = tid; idx < 32 * 64; idx += 256) {
                int srow = idx >> 5, kk = idx & 31;
                int seq = s0 + srow;
                int l = ki0 + kk;
                float v = 0.f;
                if (seq < 1000 && l < 250) {
                    int b = seq / 250, kq = seq - b * 250;
                    v = g_X1[b * PER_B + h * 62500 + kq * 250 + l];
                }
                usm[srow * 36 + kk] = f2tf32(v);
            }
        }
        __syncthreads();
        int mh_lo = (ch < 4) ? 0 : 1;   // causal: chunks 4..7 only feed kout>=128
        #pragma unroll
        for (int ks = 0; ks < 4; ks++) {
            int kb = ks * 8;
            for (int mh = mh_lo; mh < 2; mh++) {
                int aoff = 128 + mh * 128 + 16 * w - ki0 - kb;
                unsigned int fa0 = ksm[aoff + g - tg];
                unsigned int fa1 = ksm[aoff + 8 + g - tg];
                unsigned int fa2 = ksm[aoff + g - tg - 4];
                unsigned int fa3 = ksm[aoff + 8 + g - tg - 4];
                #pragma unroll
                for (int nt = 0; nt < 8; nt++) {
                    unsigned int fb0 = usm[(nt * 8 + g) * 36 + kb + tg];
                    unsigned int fb1 = usm[(nt * 8 + g) * 36 + kb + tg + 4];
                    mma_tf32(c[mh][nt][0], c[mh][nt][1], c[mh][nt][2], c[mh][nt][3],
                             fa0, fa1, fa2, fa3, fb0, fb1);
                }
            }
        }
    }

    float Dh = Dv[h];
    for (int mh = 0; mh < 2; mh++) {
        for (int qq = 0; qq < 2; qq++) {
            __syncthreads();
            // stage this quarter's fragments: kout rows [mh*128+qq*64, +64)
            if (w >= qq * 4 && w < qq * 4 + 4) {
                int wl = w - qq * 4;
                #pragma unroll
                for (int nt = 0; nt < 8; nt++) {
                    int col = nt * 8 + 2 * tg;
                    int kl = 16 * wl + g;
                    osm[col * 68 + kl]           = c[mh][nt][0];
                    osm[(col + 1) * 68 + kl]     = c[mh][nt][1];
                    osm[col * 68 + kl + 8]       = c[mh][nt][2];
                    osm[(col + 1) * 68 + kl + 8] = c[mh][nt][3];
                }
            }
            int kq0 = mh * 128 + qq * 64;
            // load u quarter into ubuf
            if (path == 0) {
                for (int idx = tid; idx < 64 * 64; idx += 256) {
                    int kk = idx >> 6, srow = idx & 63;
                    int seq = s0 + srow;
                    int l = kq0 + kk;
                    float v = 0.f;
                    if (seq < 1000 && l < 250) {
                        int b = seq / 250, s = seq - b * 250;
                        v = x[((b * 128 + h) * 250 + l) * 250 + s];
                    }
                    ubuf[srow * 68 + kk] = v;
                }
            } else {
                for (int idx = tid; idx < 64 * 64; idx += 256) {
                    int srow = idx >> 6, kk = idx & 63;
                    int seq = s0 + srow;
                    int l = kq0 + kk;
                    float v = 0.f;
                    if (seq < 1000 && l < 250) {
                        int b = seq / 250, kq = seq - b * 250;
                        v = g_X1[b * PER_B + h * 62500 + kq * 250 + l];
                    }
                    ubuf[srow * 68 + kk] = v;
                }
            }
            __syncthreads();
            for (int idx = tid; idx < 64 * 64; idx += 256) {
                int srow = idx >> 6, kl = idx & 63;
                int seq = s0 + srow;
                int kout = kq0 + kl;
                if (seq < 1000 && kout < 250) {
                    float u = ubuf[srow * 68 + kl];
                    float v = osm[srow * 68 + kl] + Dh * u;
                    float t = 0.7978845608028654f * (v + 0.044715f * v * v * v);
                    g_y[seq * SEQ_STRIDE + h * 250 + kout] = 0.5f * v * (1.f + tanhf(t));
                }
            }
        }
    }
}

// --------------- GEMM1 (tf32 mma): z = ow@y + ob, GLU -> g -------------------
__global__ void gemm_ow_mma(const float* __restrict__ ow, const float* __restrict__ ob)
{
    __shared__ char sm_raw[46080];
    unsigned int* owc = (unsigned int*)sm_raw;            // [256][36]
    unsigned int* ysm = (unsigned int*)(sm_raw + 36864);  // [32][72]
    float*        gout = (float*)sm_raw;                  // [128][66] (reused)

    int seq = blockIdx.x;
    int l0  = blockIdx.y * 64;
    int tid = threadIdx.x;
    int w   = tid >> 5;
    int lane = tid & 31;
    int g = lane >> 2, tg = lane & 3;
    int yb = seq * SEQ_STRIDE;

    float c[2][8][4];
    #pragma unroll
    for (int m = 0; m < 2; m++)
        #pragma unroll
        for (int nt = 0; nt < 8; nt++)
            #pragma unroll
            for (int i = 0; i < 4; i++)
                c[m][nt][i] = 0.f;

    for (int kc = 0; kc < 128; kc += 32) {
        for (int idx = tid; idx < 256 * 32; idx += 256) {
            int row = idx >> 5, kk = idx & 31;
            owc[row * 36 + kk] = f2tf32(ow[row * 128 + kc + kk]);
        }
        for (int idx = tid; idx < 32 * 64; idx += 256) {
            int kk = idx >> 6, l = idx & 63;
            float v = (l0 + l < 250) ? g_y[yb + (kc + kk) * 250 + l0 + l] : 0.f;
            ysm[kk * 72 + l] = f2tf32(v);
        }
        __syncthreads();
        #pragma unroll
        for (int ks = 0; ks < 4; ks++) {
            int kb = ks * 8;
            unsigned int fa0[2], fa1[2], fa2[2], fa3[2];
            #pragma unroll
            for (int m = 0; m < 2; m++) {
                int row = m * 128 + 16 * w + g;
                fa0[m] = owc[row * 36 + kb + tg];
                fa1[m] = owc[(row + 8) * 36 + kb + tg];
                fa2[m] = owc[row * 36 + kb + tg + 4];
                fa3[m] = owc[(row + 8) * 36 + kb + tg + 4];
            }
            #pragma unroll
            for (int nt = 0; nt < 8; nt++) {
                unsigned int fb0 = ysm[(kb + tg) * 72 + nt * 8 + g];
                unsigned int fb1 = ysm[(kb + tg + 4) * 72 + nt * 8 + g];
                #pragma unroll
                for (int m = 0; m < 2; m++)
                    mma_tf32(c[m][nt][0], c[m][nt][1], c[m][nt][2], c[m][nt][3],
                             fa0[m], fa1[m], fa2[m], fa3[m], fb0, fb1);
            }
        }
        __syncthreads();
    }

    float ba0 = ob[16 * w + g],        ba8 = ob[16 * w + g + 8];
    float bb0 = ob[128 + 16 * w + g],  bb8 = ob[128 + 16 * w + g + 8];
    #pragma unroll
    for (int nt = 0; nt < 8; nt++) {
        float z10 = c[0][nt][0] + ba0, z11 = c[0][nt][1] + ba0;
        float z12 = c[0][nt][2] + ba8, z13 = c[0][nt][3] + ba8;
        float z20 = c[1][nt][0] + bb0, z21 = c[1][nt][1] + bb0;
        float z22 = c[1][nt][2] + bb8, z23 = c[1][nt][3] + bb8;
        int col = nt * 8 + 2 * tg;
        gout[(16 * w + g) * 66 + col]     = z10 / (1.f + expf(-z20));
        gout[(16 * w + g) * 66 + col + 1] = z11 / (1.f + expf(-z21));
        gout[(16 * w + g + 8) * 66 + col]     = z12 / (1.f + expf(-z22));
        gout[(16 * w + g + 8) * 66 + col + 1] = z13 / (1.f + expf(-z23));
    }
    __syncthreads();
    for (int idx = tid; idx < 128 * 64; idx += 256) {
        int row = idx >> 6, l = idx & 63;
        if (l0 + l < 250)
            g_g[yb + row * 250 + l0 + l] = gout[row * 66 + l];
    }
}

// ------------ GEMM2 (tf32 mma): b2_flat = lw @ g_flat + lb + fused GN stats --
__global__ void gemm_lw_mma(const float* __restrict__ lw, const float* __restrict__ lb)
{
    __shared__ char sm_raw[33792];
    __shared__ float rs[256], rs2[256];
    unsigned int* lsm = (unsigned int*)sm_raw;            // [128][36]
    unsigned int* gsm = (unsigned int*)(sm_raw + 18432);  // [64][40]
    float*        outsm = (float*)sm_raw;                 // [64][132] (reused)

    int seq = blockIdx.x;
    int r0  = blockIdx.y * 64;
    int tid = threadIdx.x;
    int w   = tid >> 5;
    int lane = tid & 31;
    int g = lane >> 2, tg = lane & 3;
    long long gbase = (long long)seq * SEQ_STRIDE;

    float c[8][4];
    #pragma unroll
    for (int nt = 0; nt < 8; nt++)
        #pragma unroll
        for (int i = 0; i < 4; i++)
            c[nt][i] = 0.f;

    for (int kc = 0; kc < 128; kc += 32) {
        for (int idx = tid; idx < 128 * 32; idx += 256) {
            int row = idx >> 5, kk = idx & 31;
            lsm[row * 36 + kk] = f2tf32(lw[row * 128 + kc + kk]);
        }
        for (int idx = tid; idx < 64 * 32; idx += 256) {
            int row = idx >> 5, kk = idx & 31;
            float v = (r0 + row < 250) ? g_g[gbase + (r0 + row) * 128 + kc + kk] : 0.f;
            gsm[row * 40 + kk] = f2tf32(v);
        }
        __syncthreads();
        #pragma unroll
        for (int ks = 0; ks < 4; ks++) {
            int kb = ks * 8;
            int row = 16 * w + g;
            unsigned int fa0 = lsm[row * 36 + kb + tg];
            unsigned int fa1 = lsm[(row + 8) * 36 + kb + tg];
            unsigned int fa2 = lsm[row * 36 + kb + tg + 4];
            unsigned int fa3 = lsm[(row + 8) * 36 + kb + tg + 4];
            #pragma unroll
            for (int nt = 0; nt < 8; nt++) {
                unsigned int fb0 = gsm[(nt * 8 + g) * 40 + kb + tg];
                unsigned int fb1 = gsm[(nt * 8 + g) * 40 + kb + tg + 4];
                mma_tf32(c[nt][0], c[nt][1], c[nt][2], c[nt][3],
                         fa0, fa1, fa2, fa3, fb0, fb1);
            }
        }
        __syncthreads();
    }

    float bv0 = lb[16 * w + g], bv8 = lb[16 * w + g + 8];
    #pragma unroll
    for (int nt = 0; nt < 8; nt++) {
        int trow = nt * 8 + 2 * tg;
        int ocol = 16 * w + g;
        outsm[trow * 132 + ocol]           = c[nt][0] + bv0;
        outsm[(trow + 1) * 132 + ocol]     = c[nt][1] + bv0;
        outsm[trow * 132 + ocol + 8]       = c[nt][2] + bv8;
        outsm[(trow + 1) * 132 + ocol + 8] = c[nt][3] + bv8;
    }
    __syncthreads();
    float s_ = 0.f, ss_ = 0.f;
    for (int idx = tid; idx < 64 * 128; idx += 256) {
        int row = idx >> 7, o = idx & 127;
        if (r0 + row < 250) {
            float v = outsm[row * 132 + o];
            g_b2[gbase + (r0 + row) * 128 + o] = v;
            s_ += v;
            ss_ = fmaf(v, v, ss_);
        }
    }
    rs[tid] = s_; rs2[tid] = ss_;
    __syncthreads();
    for (int st = 128; st > 0; st >>= 1) {
        if (tid < st) { rs[tid] += rs[tid + st]; rs2[tid] += rs2[tid + st]; }
        __syncthreads();
    }
    if (tid == 0) {
        int bid = seq * 4 + blockIdx.y;
        g_redl[bid * 2 + 0] = rs[0];
        g_redl[bid * 2 + 1] = rs2[0];
    }
}

// ------------- GroupNorm stats combine (deterministic) -----------------------
__global__ void red_combine()
{
    int b = blockIdx.x;
    int tid = threadIdx.x;
    float s = 0.f, ss = 0.f;
    for (int i = tid; i < 1000; i += 256) {
        s  += g_redl[(b * 1000 + i) * 2 + 0];
        ss += g_redl[(b * 1000 + i) * 2 + 1];
    }
    __shared__ float sm[256], sm2[256];
    sm[tid] = s; sm2[tid] = ss;
    __syncthreads();
    for (int st = 128; st > 0; st >>= 1) {
        if (tid < st) { sm[tid] += sm[tid + st]; sm2[tid] += sm2[tid + st]; }
        __syncthreads();
    }
    if (tid == 0) {
        float inv = 1.f / (float)PER_B;
        float mu = sm[0] * inv;
        float var = sm2[0] * inv - mu * mu;
        g_stats[b * 2 + 0] = mu;
        g_stats[b * 2 + 1] = rsqrtf(var + 1e-8f);
    }
}

// -------- intra finalize: transpose b2 -> [B,N,K,S], GN, + x  -> g_X1 --------
__global__ void finalize_intra(const float* __restrict__ x,
                               const float* __restrict__ gg,
                               const float* __restrict__ gb)
{
    __shared__ float tile[32][33];
    int bh = blockIdx.x;
    int b = bh >> 7, n = bh & 127;
    int k0 = blockIdx.y * 32, s0 = blockIdx.z * 32;
    int tx = threadIdx.x, ty = threadIdx.y;
    float mu = g_stats[b * 2], istd = g_stats[b * 2 + 1];
    float ga = gg[n] * istd;
    float gbb = gb[n] - mu * ga;
    #pragma unroll
    for (int yy = 0; yy < 32; yy += 8) {
        int s = s0 + ty + yy, k = k0 + tx;
        if (s < 250 && k < 250)
            tile[ty + yy][tx] = g_b2[(b * 250 + s) * SEQ_STRIDE + n * 250 + k];
    }
    __syncthreads();
    #pragma unroll
    for (int yy = 0; yy < 32; yy += 8) {
        int k = k0 + ty + yy, s = s0 + tx;
        if (s < 250 && k < 250) {
            int xi = ((b * 128 + n) * 250 + k) * 250 + s;
            g_X1[xi] = tile[tx][ty + yy] * ga + gbb + x[xi];
        }
    }
}

// ------------- inter finalize: GN + residual ---------------------------------
__global__ void finalize_inter(const float* __restrict__ gg,
                               const float* __restrict__ gb,
                               float* __restrict__ out)
{
    int idx = blockIdx.x * 256 + threadIdx.x;
    if (idx < TOT) {
        int b = idx / PER_B;
        int rem = idx - b * PER_B;
        int n = rem / 62500;
        int rem2 = rem - n * 62500;
        int k = rem2 / 250;
        int s = rem2 - k * 250;
        float v = g_b2[(b * 250 + k) * SEQ_STRIDE + n * 250 + s];
        float mu = g_stats[b * 2], istd = g_stats[b * 2 + 1];
        out[idx] = (v - mu) * istd * gg[n] + gb[n] + g_X1[idx];
    }
}

extern "C" void kernel_launch(void* const* d_in, const int* in_sizes, int n_in,
                              void* d_out, int out_size)
{
    const float* x = (const float*)d_in[0];
    const float* P[2][12];
    for (int p = 0; p < 2; p++)
        for (int i = 0; i < 12; i++)
            P[p][i] = (const float*)d_in[1 + p * 12 + i];
    float* out = (float*)d_out;

    prep_params<<<128, 32>>>(P[0][0], P[0][1], P[0][2], P[0][3], P[0][4], 0);
    prep_params<<<128, 32>>>(P[1][0], P[1][1], P[1][2], P[1][3], P[1][4], 1);
    kern_gen<<<128, 256>>>(0);
    kern_gen<<<128, 256>>>(1);

    // ---- intra path ----
    conv_gemm<<<dim3(128, 16), 256>>>(0, x, P[0][5]);
    gemm_ow_mma<<<dim3(NSEQ, 4), 256>>>(P[0][6], P[0][7]);
    gemm_lw_mma<<<dim3(NSEQ, 4), 256>>>(P[0][8], P[0][9]);
    red_combine<<<4, 256>>>();
    finalize_intra<<<dim3(512, 8, 8), dim3(32, 8)>>>(x, P[0][10], P[0][11]);

    // ---- inter path ----
    conv_gemm<<<dim3(128, 16), 256>>>(1, x, P[1][5]);
    gemm_ow_mma<<<dim3(NSEQ, 4), 256>>>(P[1][6], P[1][7]);
    gemm_lw_mma<<<dim3(NSEQ, 4), 256>>>(P[1][8], P[1][9]);
    red_combine<<<4, 256>>>();
    finalize_inter<<<125000, 256>>>(P[1][10], P[1][11], out);
}

// round 8
// speedup vs baseline: 1.3590x; 1.3590x over previous
#include <cuda_runtime.h>
#include <stdint.h>
#include <math.h>

// Problem constants
#define Bb 4
#define Nn 128
#define Kk 250
#define Ss 250
#define Mm 32
#define NSEQ 1000
#define LSEQ 250
#define SEQ_STRIDE 32000
#define TOT 32000000
#define PER_B 8000000
#define NM 4096

__device__ float g_y[TOT];
__device__ float g_g[TOT];
__device__ float g_b2[TOT];
__device__ float g_X1[TOT];
__device__ float g_P[2 * 6 * NM];           // planes: a_re,a_im,c2r,c2i,dre,dim
__device__ float g_kern[2 * 128 * 384];     // [path][h][128 pad + 250 taps + 6 pad]
__device__ float g_redl[4000 * 2];
__device__ float g_stats[Bb * 2];

__device__ __forceinline__ unsigned int f2tf32(float f)
{
    unsigned int u;
    asm("cvt.rna.tf32.f32 %0, %1;" : "=r"(u) : "f"(f));
    return u;
}

__device__ __forceinline__ void mma_tf32(float& c0, float& c1, float& c2, float& c3,
                                         unsigned int fa0, unsigned int fa1,
                                         unsigned int fa2, unsigned int fa3,
                                         unsigned int fb0, unsigned int fb1)
{
    asm volatile("mma.sync.aligned.m16n8k8.row.col.f32.tf32.tf32.f32 "
                 "{%0,%1,%2,%3}, {%4,%5,%6,%7}, {%8,%9}, {%0,%1,%2,%3};"
                 : "+f"(c0), "+f"(c1), "+f"(c2), "+f"(c3)
                 : "r"(fa0), "r"(fa1), "r"(fa2), "r"(fa3), "r"(fb0), "r"(fb1));
}

// ---------------- parameter prep ---------------------------------------------
__global__ void prep_params(const float* __restrict__ log_dt,
                            const float* __restrict__ logA_re,
                            const float* __restrict__ A_im,
                            const float* __restrict__ C_re,
                            const float* __restrict__ C_im,
                            int path)
{
    int h = blockIdx.x;
    int m = threadIdx.x;
    float dt  = expf(log_dt[h]);
    float Are = -expf(logA_re[h * Mm + m]);
    float Aim = A_im[h * Mm + m];
    float dre = dt * Are, dim = dt * Aim;
    float e   = expf(dre);
    float vre = e * cosf(dim);
    float vim = e * sinf(dim);
    float nre = vre - 1.0f, nim = vim;
    float d2  = Are * Are + Aim * Aim;
    float qre = (nre * Are + nim * Aim) / d2;
    float qim = (nim * Are - nre * Aim) / d2;
    float cr  = C_re[h * Mm + m], ci = C_im[h * Mm + m];
    float c2r = 2.0f * (cr * qre - ci * qim);
    float c2i = 2.0f * (cr * qim + ci * qre);
    int base = path * 6 * NM + h * Mm + m;
    g_P[base + 0 * NM] = vre;
    g_P[base + 1 * NM] = vim;
    g_P[base + 2 * NM] = c2r;
    g_P[base + 3 * NM] = c2i;
    g_P[base + 4 * NM] = dre;
    g_P[base + 5 * NM] = dim;
}

// --------- kernel taps: kern[d] = Re(sum_m C'_m a_m^d) -----------------------
__global__ void kern_gen(int path)
{
    int h = blockIdx.x;
    int tid = threadIdx.x;
    int w = tid >> 5, m = tid & 31;
    int base = path * 6 * NM + h * Mm + m;
    float ar  = g_P[base + 0 * NM];
    float ai  = g_P[base + 1 * NM];
    float c2r = g_P[base + 2 * NM];
    float c2i = g_P[base + 3 * NM];
    float dre = g_P[base + 4 * NM];
    float dim = g_P[base + 5 * NM];
    float l0 = (float)(w * 32);
    float e = expf(l0 * dre);
    float pr = e * cosf(l0 * dim);
    float pi = e * sinf(l0 * dim);
    float* kout = &g_kern[(path * 128 + h) * 384];
    if (tid < 128) kout[tid] = 0.f;
    if (tid < 6)   kout[378 + tid] = 0.f;
    for (int i = 0; i < 32; i++) {
        int l = w * 32 + i;
        float v = fmaf(c2r, pr, -c2i * pi);
        v += __shfl_xor_sync(0xffffffffu, v, 1);
        v += __shfl_xor_sync(0xffffffffu, v, 2);
        v += __shfl_xor_sync(0xffffffffu, v, 4);
        v += __shfl_xor_sync(0xffffffffu, v, 8);
        v += __shfl_xor_sync(0xffffffffu, v, 16);
        if (m == 0 && l < 250) kout[128 + l] = v;
        float t = pr;
        pr = fmaf(ar, t, -ai * pi);
        pi = fmaf(ai, t,  ar * pi);
    }
}

// ------- conv as causal Toeplitz GEMM (R6 structure) + direct-x path0 --------
// grid (h, 2 kout-tiles, 16 seq-tiles), 256 thr. Tile 128 kout x 64 seq.
__global__ void conv_gemm(int path, const float* __restrict__ x,
                          const float* __restrict__ Dv)
{
    __shared__ char smr[33792];
    unsigned int* ksm = (unsigned int*)smr;           // 384 words
    unsigned int* usm = (unsigned int*)(smr + 1536);  // [64 seq][36]
    float*        osm = (float*)smr;                  // [64 seq][129] (reused)

    int h   = blockIdx.x;
    int ko0 = blockIdx.y * 128;
    int s0  = blockIdx.z * 64;
    int tid = threadIdx.x;
    int w = tid >> 5, lane = tid & 31;
    int g = lane >> 2, tg = lane & 3;

    const float* kern = &g_kern[(path * 128 + h) * 384];
    for (int i = tid; i < 384; i += 256) ksm[i] = f2tf32(kern[i]);

    float c[8][4];
    #pragma unroll
    for (int nt = 0; nt < 8; nt++)
        #pragma unroll
        for (int i = 0; i < 4; i++)
            c[nt][i] = 0.f;

    int nch = (blockIdx.y == 0) ? 4 : 8;
    for (int ch = 0; ch < nch; ch++) {
        int ki0 = ch * 32;
        __syncthreads();
        if (path == 0) {
            // x[b][h][l][s]: coalesced along s, transposed store
            for (int idx = tid; idx < 32 * 64; idx += 256) {
                int kk = idx >> 6, srow = idx & 63;
                int seq = s0 + srow, l = ki0 + kk;
                float v = 0.f;
                if (seq < 1000 && l < 250) {
                    int b = seq / 250, s = seq - b * 250;
                    v = x[((b * 128 + h) * 250 + l) * 250 + s];
                }
                usm[srow * 36 + kk] = f2tf32(v);
            }
        } else {
            // g_X1[b][h][kq][l]: coalesced along l
            for (int idx = tid; idx < 64 * 32; idx += 256) {
                int srow = idx >> 5, kk = idx & 31;
                int seq = s0 + srow, l = ki0 + kk;
                float v = 0.f;
                if (seq < 1000 && l < 250) {
                    int b = seq / 250, kq = seq - b * 250;
                    v = g_X1[b * PER_B + h * 62500 + kq * 250 + l];
                }
                usm[srow * 36 + kk] = f2tf32(v);
            }
        }
        __syncthreads();
        #pragma unroll
        for (int ks = 0; ks < 4; ks++) {
            int kb = ks * 8;
            int aoff = 128 + ko0 + 16 * w - ki0 - kb;
            unsigned int fa0 = ksm[aoff + g - tg];
            unsigned int fa1 = ksm[aoff + 8 + g - tg];
            unsigned int fa2 = ksm[aoff + g - tg - 4];
            unsigned int fa3 = ksm[aoff + 8 + g - tg - 4];
            #pragma unroll
            for (int nt = 0; nt < 8; nt++) {
                unsigned int fb0 = usm[(nt * 8 + g) * 36 + kb + tg];
                unsigned int fb1 = usm[(nt * 8 + g) * 36 + kb + tg + 4];
                mma_tf32(c[nt][0], c[nt][1], c[nt][2], c[nt][3],
                         fa0, fa1, fa2, fa3, fb0, fb1);
            }
        }
    }
    __syncthreads();

    // stage C -> osm[seq][kout_local], pad 129
    #pragma unroll
    for (int nt = 0; nt < 8; nt++) {
        int col = nt * 8 + 2 * tg;
        int row = 16 * w + g;
        osm[col * 129 + row]           = c[nt][0];
        osm[(col + 1) * 129 + row]     = c[nt][1];
        osm[col * 129 + row + 8]       = c[nt][2];
        osm[(col + 1) * 129 + row + 8] = c[nt][3];
    }
    __syncthreads();

    float Dh = Dv[h];
    if (path == 0) {
        // pass A: D*u + GELU in-place (x read coalesced along s; osm srow-fastest
        // is bank-stride-1 with pad 129)
        for (int idx = tid; idx < 64 * 128; idx += 256) {
            int kk = idx >> 6, srow = idx & 63;
            int seq = s0 + srow, kout = ko0 + kk;
            if (seq < 1000 && kout < 250) {
                int b = seq / 250, s = seq - b * 250;
                float u = x[((b * 128 + h) * 250 + kout) * 250 + s];
                float v = osm[srow * 129 + kk] + Dh * u;
                float t = 0.7978845608028654f * (v + 0.044715f * v * v * v);
                osm[srow * 129 + kk] = 0.5f * v * (1.f + tanhf(t));
            }
        }
        __syncthreads();
        // pass B: coalesced write along kout
        for (int idx = tid; idx < 64 * 128; idx += 256) {
            int srow = idx >> 7, k = idx & 127;
            int seq = s0 + srow, kout = ko0 + k;
            if (seq < 1000 && kout < 250)
                g_y[seq * SEQ_STRIDE + h * 250 + kout] = osm[srow * 129 + k];
        }
    } else {
        for (int idx = tid; idx < 64 * 128; idx += 256) {
            int srow = idx >> 7, k = idx & 127;
            int seq = s0 + srow, kout = ko0 + k;
            if (seq < 1000 && kout < 250) {
                int b = seq / 250, kq = seq - b * 250;
                float u = g_X1[b * PER_B + h * 62500 + kq * 250 + kout];
                float v = osm[srow * 129 + k] + Dh * u;
                float t = 0.7978845608028654f * (v + 0.044715f * v * v * v);
                g_y[seq * SEQ_STRIDE + h * 250 + kout] = 0.5f * v * (1.f + tanhf(t));
            }
        }
    }
}

// --------------- GEMM1 (tf32 mma): z = ow@y + ob, GLU -> g -------------------
__global__ void gemm_ow_mma(const float* __restrict__ ow, const float* __restrict__ ob)
{
    __shared__ char sm_raw[46080];
    unsigned int* owc = (unsigned int*)sm_raw;            // [256][36]
    unsigned int* ysm = (unsigned int*)(sm_raw + 36864);  // [32][72]
    float*        gout = (float*)sm_raw;                  // [128][66] (reused)

    int seq = blockIdx.x;
    int l0  = blockIdx.y * 64;
    int tid = threadIdx.x;
    int w   = tid >> 5;
    int lane = tid & 31;
    int g = lane >> 2, tg = lane & 3;
    int yb = seq * SEQ_STRIDE;

    float c[2][8][4];
    #pragma unroll
    for (int m = 0; m < 2; m++)
        #pragma unroll
        for (int nt = 0; nt < 8; nt++)
            #pragma unroll
            for (int i = 0; i < 4; i++)
                c[m][nt][i] = 0.f;

    for (int kc = 0; kc < 128; kc += 32) {
        for (int idx = tid; idx < 256 * 32; idx += 256) {
            int row = idx >> 5, kk = idx & 31;
            owc[row * 36 + kk] = f2tf32(ow[row * 128 + kc + kk]);
        }
        for (int idx = tid; idx < 32 * 64; idx += 256) {
            int kk = idx >> 6, l = idx & 63;
            float v = (l0 + l < 250) ? g_y[yb + (kc + kk) * 250 + l0 + l] : 0.f;
            ysm[kk * 72 + l] = f2tf32(v);
        }
        __syncthreads();
        #pragma unroll
        for (int ks = 0; ks < 4; ks++) {
            int kb = ks * 8;
            unsigned int fa0[2], fa1[2], fa2[2], fa3[2];
            #pragma unroll
            for (int m = 0; m < 2; m++) {
                int row = m * 128 + 16 * w + g;
                fa0[m] = owc[row * 36 + kb + tg];
                fa1[m] = owc[(row + 8) * 36 + kb + tg];
                fa2[m] = owc[row * 36 + kb + tg + 4];
                fa3[m] = owc[(row + 8) * 36 + kb + tg + 4];
            }
            #pragma unroll
            for (int nt = 0; nt < 8; nt++) {
                unsigned int fb0 = ysm[(kb + tg) * 72 + nt * 8 + g];
                unsigned int fb1 = ysm[(kb + tg + 4) * 72 + nt * 8 + g];
                #pragma unroll
                for (int m = 0; m < 2; m++)
                    mma_tf32(c[m][nt][0], c[m][nt][1], c[m][nt][2], c[m][nt][3],
                             fa0[m], fa1[m], fa2[m], fa3[m], fb0, fb1);
            }
        }
        __syncthreads();
    }

    float ba0 = ob[16 * w + g],        ba8 = ob[16 * w + g + 8];
    float bb0 = ob[128 + 16 * w + g],  bb8 = ob[128 + 16 * w + g + 8];
    #pragma unroll
    for (int nt = 0; nt < 8; nt++) {
        float z10 = c[0][nt][0] + ba0, z11 = c[0][nt][1] + ba0;
        float z12 = c[0][nt][2] + ba8, z13 = c[0][nt][3] + ba8;
        float z20 = c[1][nt][0] + bb0, z21 = c[1][nt][1] + bb0;
        float z22 = c[1][nt][2] + bb8, z23 = c[1][nt][3] + bb8;
        int col = nt * 8 + 2 * tg;
        gout[(16 * w + g) * 66 + col]     = z10 / (1.f + expf(-z20));
        gout[(16 * w + g) * 66 + col + 1] = z11 / (1.f + expf(-z21));
        gout[(16 * w + g + 8) * 66 + col]     = z12 / (1.f + expf(-z22));
        gout[(16 * w + g + 8) * 66 + col + 1] = z13 / (1.f + expf(-z23));
    }
    __syncthreads();
    for (int idx = tid; idx < 128 * 64; idx += 256) {
        int row = idx >> 6, l = idx & 63;
        if (l0 + l < 250)
            g_g[yb + row * 250 + l0 + l] = gout[row * 66 + l];
    }
}

// ------------ GEMM2 (tf32 mma): b2_flat = lw @ g_flat + lb + fused GN stats --
__global__ void gemm_lw_mma(const float* __restrict__ lw, const float* __restrict__ lb)
{
    __shared__ char sm_raw[33792];
    __shared__ float rs[256], rs2[256];
    unsigned int* lsm = (unsigned int*)sm_raw;            // [128][36]
    unsigned int* gsm = (unsigned int*)(sm_raw + 18432);  // [64][40]
    float*        outsm = (float*)sm_raw;                 // [64][132] (reused)

    int seq = blockIdx.x;
    int r0  = blockIdx.y * 64;
    int tid = threadIdx.x;
    int w   = tid >> 5;
    int lane = tid & 31;
    int g = lane >> 2, tg = lane & 3;
    long long gbase = (long long)seq * SEQ_STRIDE;

    float c[8][4];
    #pragma unroll
    for (int nt = 0; nt < 8; nt++)
        #pragma unroll
        for (int i = 0; i < 4; i++)
            c[nt][i] = 0.f;

    for (int kc = 0; kc < 128; kc += 32) {
        for (int idx = tid; idx < 128 * 32; idx += 256) {
            int row = idx >> 5, kk = idx & 31;
            lsm[row * 36 + kk] = f2tf32(lw[row * 128 + kc + kk]);
        }
        for (int idx = tid; idx < 64 * 32; idx += 256) {
            int row = idx >> 5, kk = idx & 31;
            float v = (r0 + row < 250) ? g_g[gbase + (r0 + row) * 128 + kc + kk] : 0.f;
            gsm[row * 40 + kk] = f2tf32(v);
        }
        __syncthreads();
        #pragma unroll
        for (int ks = 0; ks < 4; ks++) {
            int kb = ks * 8;
            int row = 16 * w + g;
            unsigned int fa0 = lsm[row * 36 + kb + tg];
            unsigned int fa1 = lsm[(row + 8) * 36 + kb + tg];
            unsigned int fa2 = lsm[row * 36 + kb + tg + 4];
            unsigned int fa3 = lsm[(row + 8) * 36 + kb + tg + 4];
            #pragma unroll
            for (int nt = 0; nt < 8; nt++) {
                unsigned int fb0 = gsm[(nt * 8 + g) * 40 + kb + tg];
                unsigned int fb1 = gsm[(nt * 8 + g) * 40 + kb + tg + 4];
                mma_tf32(c[nt][0], c[nt][1], c[nt][2], c[nt][3],
                         fa0, fa1, fa2, fa3, fb0, fb1);
            }
        }
        __syncthreads();
    }

    float bv0 = lb[16 * w + g], bv8 = lb[16 * w + g + 8];
    #pragma unroll
    for (int nt = 0; nt < 8; nt++) {
        int trow = nt * 8 + 2 * tg;
        int ocol = 16 * w + g;
        outsm[trow * 132 + ocol]           = c[nt][0] + bv0;
        outsm[(trow + 1) * 132 + ocol]     = c[nt][1] + bv0;
        outsm[trow * 132 + ocol + 8]       = c[nt][2] + bv8;
        outsm[(trow + 1) * 132 + ocol + 8] = c[nt][3] + bv8;
    }
    __syncthreads();
    float s_ = 0.f, ss_ = 0.f;
    for (int idx = tid; idx < 64 * 128; idx += 256) {
        int row = idx >> 7, o = idx & 127;
        if (r0 + row < 250) {
            float v = outsm[row * 132 + o];
            g_b2[gbase + (r0 + row) * 128 + o] = v;
            s_ += v;
            ss_ = fmaf(v, v, ss_);
        }
    }
    rs[tid] = s_; rs2[tid] = ss_;
    __syncthreads();
    for (int st = 128; st > 0; st >>= 1) {
        if (tid < st) { rs[tid] += rs[tid + st]; rs2[tid] += rs2[tid + st]; }
        __syncthreads();
    }
    if (tid == 0) {
        int bid = seq * 4 + blockIdx.y;
        g_redl[bid * 2 + 0] = rs[0];
        g_redl[bid * 2 + 1] = rs2[0];
    }
}

// ------------- GroupNorm stats combine (deterministic) -----------------------
__global__ void red_combine()
{
    int b = blockIdx.x;
    int tid = threadIdx.x;
    float s = 0.f, ss = 0.f;
    for (int i = tid; i < 1000; i += 256) {
        s  += g_redl[(b * 1000 + i) * 2 + 0];
        ss += g_redl[(b * 1000 + i) * 2 + 1];
    }
    __shared__ float sm[256], sm2[256];
    sm[tid] = s; sm2[tid] = ss;
    __syncthreads();
    for (int st = 128; st > 0; st >>= 1) {
        if (tid < st) { sm[tid] += sm[tid + st]; sm2[tid] += sm2[tid + st]; }
        __syncthreads();
    }
    if (tid == 0) {
        float inv = 1.f / (float)PER_B;
        float mu = sm[0] * inv;
        float var = sm2[0] * inv - mu * mu;
        g_stats[b * 2 + 0] = mu;
        g_stats[b * 2 + 1] = rsqrtf(var + 1e-8f);
    }
}

// -------- intra finalize: transpose b2 -> [B,N,K,S], GN, + x  -> g_X1 --------
__global__ void finalize_intra(const float* __restrict__ x,
                               const float* __restrict__ gg,
                               const float* __restrict__ gb)
{
    __shared__ float tile[32][33];
    int bh = blockIdx.x;
    int b = bh >> 7, n = bh & 127;
    int k0 = blockIdx.y * 32, s0 = blockIdx.z * 32;
    int tx = threadIdx.x, ty = threadIdx.y;
    float mu = g_stats[b * 2], istd = g_stats[b * 2 + 1];
    float ga = gg[n] * istd;
    float gbb = gb[n] - mu * ga;
    #pragma unroll
    for (int yy = 0; yy < 32; yy += 8) {
        int s = s0 + ty + yy, k = k0 + tx;
        if (s < 250 && k < 250)
            tile[ty + yy][tx] = g_b2[(b * 250 + s) * SEQ_STRIDE + n * 250 + k];
    }
    __syncthreads();
    #pragma unroll
    for (int yy = 0; yy < 32; yy += 8) {
        int k = k0 + ty + yy, s = s0 + tx;
        if (s < 250 && k < 250) {
            int xi = ((b * 128 + n) * 250 + k) * 250 + s;
            g_X1[xi] = tile[tx][ty + yy] * ga + gbb + x[xi];
        }
    }
}

// ------------- inter finalize: GN + residual ---------------------------------
__global__ void finalize_inter(const float* __restrict__ gg,
                               const float* __restrict__ gb,
                               float* __restrict__ out)
{
    int idx = blockIdx.x * 256 + threadIdx.x;
    if (idx < TOT) {
        int b = idx / PER_B;
        int rem = idx - b * PER_B;
        int n = rem / 62500;
        int rem2 = rem - n * 62500;
        int k = rem2 / 250;
        int s = rem2 - k * 250;
        float v = g_b2[(b * 250 + k) * SEQ_STRIDE + n * 250 + s];
        float mu = g_stats[b * 2], istd = g_stats[b * 2 + 1];
        out[idx] = (v - mu) * istd * gg[n] + gb[n] + g_X1[idx];
    }
}

extern "C" void kernel_launch(void* const* d_in, const int* in_sizes, int n_in,
                              void* d_out, int out_size)
{
    const float* x = (const float*)d_in[0];
    const float* P[2][12];
    for (int p = 0; p < 2; p++)
        for (int i = 0; i < 12; i++)
            P[p][i] = (const float*)d_in[1 + p * 12 + i];
    float* out = (float*)d_out;

    prep_params<<<128, 32>>>(P[0][0], P[0][1], P[0][2], P[0][3], P[0][4], 0);
    prep_params<<<128, 32>>>(P[1][0], P[1][1], P[1][2], P[1][3], P[1][4], 1);
    kern_gen<<<128, 256>>>(0);
    kern_gen<<<128, 256>>>(1);

    // ---- intra path ----
    conv_gemm<<<dim3(128, 2, 16), 256>>>(0, x, P[0][5]);
    gemm_ow_mma<<<dim3(NSEQ, 4), 256>>>(P[0][6], P[0][7]);
    gemm_lw_mma<<<dim3(NSEQ, 4), 256>>>(P[0][8], P[0][9]);
    red_combine<<<4, 256>>>();
    finalize_intra<<<dim3(512, 8, 8), dim3(32, 8)>>>(x, P[0][10], P[0][11]);

    // ---- inter path ----
    conv_gemm<<<dim3(128, 2, 16), 256>>>(1, x, P[1][5]);
    gemm_ow_mma<<<dim3(NSEQ, 4), 256>>>(P[1][6], P[1][7]);
    gemm_lw_mma<<<dim3(NSEQ, 4), 256>>>(P[1][8], P[1][9]);
    red_combine<<<4, 256>>>();
    finalize_inter<<<125000, 256>>>(P[1][10], P[1][11], out);
}

// round 9
// speedup vs baseline: 1.4880x; 1.0949x over previous
#include <cuda_runtime.h>
#include <stdint.h>
#include <math.h>

// Problem constants
#define Bb 4
#define Nn 128
#define Kk 250
#define Ss 250
#define Mm 32
#define NSEQ 1000
#define LSEQ 250
#define SEQ_STRIDE 32000
#define TOT 32000000
#define PER_B 8000000
#define NM 4096

#define FUSED_SMEM 186368

__device__ float g_y[TOT];
__device__ float g_b2[TOT];
__device__ float g_X1[TOT];
__device__ float g_P[2 * 6 * NM];           // planes: a_re,a_im,c2r,c2i,dre,dim
__device__ float g_kern[2 * 128 * 384];     // [path][h][128 pad + 250 taps + 6 pad]
__device__ float g_redl[1000 * 2];
__device__ float g_stats[Bb * 2];

__device__ __forceinline__ unsigned int f2tf32(float f)
{
    unsigned int u;
    asm("cvt.rna.tf32.f32 %0, %1;" : "=r"(u) : "f"(f));
    return u;
}

__device__ __forceinline__ void mma_tf32(float& c0, float& c1, float& c2, float& c3,
                                         unsigned int fa0, unsigned int fa1,
                                         unsigned int fa2, unsigned int fa3,
                                         unsigned int fb0, unsigned int fb1)
{
    asm volatile("mma.sync.aligned.m16n8k8.row.col.f32.tf32.tf32.f32 "
                 "{%0,%1,%2,%3}, {%4,%5,%6,%7}, {%8,%9}, {%0,%1,%2,%3};"
                 : "+f"(c0), "+f"(c1), "+f"(c2), "+f"(c3)
                 : "r"(fa0), "r"(fa1), "r"(fa2), "r"(fa3), "r"(fb0), "r"(fb1));
}

// ---------------- parameter prep ---------------------------------------------
__global__ void prep_params(const float* __restrict__ log_dt,
                            const float* __restrict__ logA_re,
                            const float* __restrict__ A_im,
                            const float* __restrict__ C_re,
                            const float* __restrict__ C_im,
                            int path)
{
    int h = blockIdx.x;
    int m = threadIdx.x;
    float dt  = expf(log_dt[h]);
    float Are = -expf(logA_re[h * Mm + m]);
    float Aim = A_im[h * Mm + m];
    float dre = dt * Are, dim = dt * Aim;
    float e   = expf(dre);
    float vre = e * cosf(dim);
    float vim = e * sinf(dim);
    float nre = vre - 1.0f, nim = vim;
    float d2  = Are * Are + Aim * Aim;
    float qre = (nre * Are + nim * Aim) / d2;
    float qim = (nim * Are - nre * Aim) / d2;
    float cr  = C_re[h * Mm + m], ci = C_im[h * Mm + m];
    float c2r = 2.0f * (cr * qre - ci * qim);
    float c2i = 2.0f * (cr * qim + ci * qre);
    int base = path * 6 * NM + h * Mm + m;
    g_P[base + 0 * NM] = vre;
    g_P[base + 1 * NM] = vim;
    g_P[base + 2 * NM] = c2r;
    g_P[base + 3 * NM] = c2i;
    g_P[base + 4 * NM] = dre;
    g_P[base + 5 * NM] = dim;
}

// --------- kernel taps: kern[d] = Re(sum_m C'_m a_m^d) -----------------------
__global__ void kern_gen(int path)
{
    int h = blockIdx.x;
    int tid = threadIdx.x;
    int w = tid >> 5, m = tid & 31;
    int base = path * 6 * NM + h * Mm + m;
    float ar  = g_P[base + 0 * NM];
    float ai  = g_P[base + 1 * NM];
    float c2r = g_P[base + 2 * NM];
    float c2i = g_P[base + 3 * NM];
    float dre = g_P[base + 4 * NM];
    float dim = g_P[base + 5 * NM];
    float l0 = (float)(w * 32);
    float e = expf(l0 * dre);
    float pr = e * cosf(l0 * dim);
    float pi = e * sinf(l0 * dim);
    float* kout = &g_kern[(path * 128 + h) * 384];
    if (tid < 128) kout[tid] = 0.f;
    if (tid < 6)   kout[378 + tid] = 0.f;
    for (int i = 0; i < 32; i++) {
        int l = w * 32 + i;
        float v = fmaf(c2r, pr, -c2i * pi);
        v += __shfl_xor_sync(0xffffffffu, v, 1);
        v += __shfl_xor_sync(0xffffffffu, v, 2);
        v += __shfl_xor_sync(0xffffffffu, v, 4);
        v += __shfl_xor_sync(0xffffffffu, v, 8);
        v += __shfl_xor_sync(0xffffffffu, v, 16);
        if (m == 0 && l < 250) kout[128 + l] = v;
        float t = pr;
        pr = fmaf(ar, t, -ai * pi);
        pi = fmaf(ai, t,  ar * pi);
    }
}

// ------- conv as causal Toeplitz GEMM + direct-x path0 (R8 proven) -----------
__global__ void conv_gemm(int path, const float* __restrict__ x,
                          const float* __restrict__ Dv)
{
    __shared__ char smr[33792];
    unsigned int* ksm = (unsigned int*)smr;           // 384 words
    unsigned int* usm = (unsigned int*)(smr + 1536);  // [64 seq][36]
    float*        osm = (float*)smr;                  // [64 seq][129] (reused)

    int h   = blockIdx.x;
    int ko0 = blockIdx.y * 128;
    int s0  = blockIdx.z * 64;
    int tid = threadIdx.x;
    int w = tid >> 5, lane = tid & 31;
    int g = lane >> 2, tg = lane & 3;

    const float* kern = &g_kern[(path * 128 + h) * 384];
    for (int i = tid; i < 384; i += 256) ksm[i] = f2tf32(kern[i]);

    float c[8][4];
    #pragma unroll
    for (int nt = 0; nt < 8; nt++)
        #pragma unroll
        for (int i = 0; i < 4; i++)
            c[nt][i] = 0.f;

    int nch = (blockIdx.y == 0) ? 4 : 8;
    for (int ch = 0; ch < nch; ch++) {
        int ki0 = ch * 32;
        __syncthreads();
        if (path == 0) {
            for (int idx = tid; idx < 32 * 64; idx += 256) {
                int kk = idx >> 6, srow = idx & 63;
                int seq = s0 + srow, l = ki0 + kk;
                float v = 0.f;
                if (seq < 1000 && l < 250) {
                    int b = seq / 250, s = seq - b * 250;
                    v = x[((b * 128 + h) * 250 + l) * 250 + s];
                }
                usm[srow * 36 + kk] = f2tf32(v);
            }
        } else {
            for (int idx = tid; idx < 64 * 32; idx += 256) {
                int srow = idx >> 5, kk = idx & 31;
                int seq = s0 + srow, l = ki0 + kk;
                float v = 0.f;
                if (seq < 1000 && l < 250) {
                    int b = seq / 250, kq = seq - b * 250;
                    v = g_X1[b * PER_B + h * 62500 + kq * 250 + l];
                }
                usm[srow * 36 + kk] = f2tf32(v);
            }
        }
        __syncthreads();
        #pragma unroll
        for (int ks = 0; ks < 4; ks++) {
            int kb = ks * 8;
            int aoff = 128 + ko0 + 16 * w - ki0 - kb;
            unsigned int fa0 = ksm[aoff + g - tg];
            unsigned int fa1 = ksm[aoff + 8 + g - tg];
            unsigned int fa2 = ksm[aoff + g - tg - 4];
            unsigned int fa3 = ksm[aoff + 8 + g - tg - 4];
            #pragma unroll
            for (int nt = 0; nt < 8; nt++) {
                unsigned int fb0 = usm[(nt * 8 + g) * 36 + kb + tg];
                unsigned int fb1 = usm[(nt * 8 + g) * 36 + kb + tg + 4];
                mma_tf32(c[nt][0], c[nt][1], c[nt][2], c[nt][3],
                         fa0, fa1, fa2, fa3, fb0, fb1);
            }
        }
    }
    __syncthreads();

    #pragma unroll
    for (int nt = 0; nt < 8; nt++) {
        int col = nt * 8 + 2 * tg;
        int row = 16 * w + g;
        osm[col * 129 + row]           = c[nt][0];
        osm[(col + 1) * 129 + row]     = c[nt][1];
        osm[col * 129 + row + 8]       = c[nt][2];
        osm[(col + 1) * 129 + row + 8] = c[nt][3];
    }
    __syncthreads();

    float Dh = Dv[h];
    if (path == 0) {
        for (int idx = tid; idx < 64 * 128; idx += 256) {
            int kk = idx >> 6, srow = idx & 63;
            int seq = s0 + srow, kout = ko0 + kk;
            if (seq < 1000 && kout < 250) {
                int b = seq / 250, s = seq - b * 250;
                float u = x[((b * 128 + h) * 250 + kout) * 250 + s];
                float v = osm[srow * 129 + kk] + Dh * u;
                float t = 0.7978845608028654f * (v + 0.044715f * v * v * v);
                osm[srow * 129 + kk] = 0.5f * v * (1.f + tanhf(t));
            }
        }
        __syncthreads();
        for (int idx = tid; idx < 64 * 128; idx += 256) {
            int srow = idx >> 7, k = idx & 127;
            int seq = s0 + srow, kout = ko0 + k;
            if (seq < 1000 && kout < 250)
                g_y[seq * SEQ_STRIDE + h * 250 + kout] = osm[srow * 129 + k];
        }
    } else {
        for (int idx = tid; idx < 64 * 128; idx += 256) {
            int srow = idx >> 7, k = idx & 127;
            int seq = s0 + srow, kout = ko0 + k;
            if (seq < 1000 && kout < 250) {
                int b = seq / 250, kq = seq - b * 250;
                float u = g_X1[b * PER_B + h * 62500 + kq * 250 + kout];
                float v = osm[srow * 129 + k] + Dh * u;
                float t = 0.7978845608028654f * (v + 0.044715f * v * v * v);
                g_y[seq * SEQ_STRIDE + h * 250 + kout] = 0.5f * v * (1.f + tanhf(t));
            }
        }
    }
}

// ------ FUSED: ow GEMM + GLU (smem) + lw GEMM + bias + GN stats, per seq -----
// 512 thr / 16 warps; two warp-halves process two 64-wide tiles concurrently.
// dyn smem: gsm [l<250][129] tf32 GLU plane | wbuf (weights) | per-half stage bufs
__global__ void fused_ow_lw(const float* __restrict__ ow, const float* __restrict__ ob,
                            const float* __restrict__ lw, const float* __restrict__ lb)
{
    extern __shared__ unsigned int dynsm[];
    unsigned int* gsm  = dynsm;            // 32256 u32: [l][129] (ch inner)
    unsigned int* wbuf = dynsm + 32256;    // 9216 u32: owc [256][36] / lwsm [128][36]
    unsigned int* cbuf = dynsm + 41472;    // per-half: ysm [32][72] / gsm2 [64][40]
    __shared__ float rs[512], rs2[512];

    int seq  = blockIdx.x;
    int tid  = threadIdx.x;
    int w    = tid >> 5, lane = tid & 31;
    int half = tid >> 8;
    int lt   = tid & 255;
    int w8   = w & 7;
    int g = lane >> 2, tg = lane & 3;
    int yb = seq * SEQ_STRIDE;

    // ---------------- phase 1: z = ow@y+ob, GLU -> gsm ----------------
    for (int li = 0; li < 2; li++) {
        int l0 = li * 128 + half * 64;
        float c[2][8][4];
        #pragma unroll
        for (int m = 0; m < 2; m++)
            #pragma unroll
            for (int nt = 0; nt < 8; nt++)
                #pragma unroll
                for (int i = 0; i < 4; i++)
                    c[m][nt][i] = 0.f;

        for (int kc = 0; kc < 128; kc += 32) {
            __syncthreads();
            for (int idx = tid; idx < 256 * 32; idx += 512) {
                int row = idx >> 5, kk = idx & 31;
                wbuf[row * 36 + kk] = f2tf32(ow[row * 128 + kc + kk]);
            }
            unsigned int* ysm = cbuf + half * 2304;
            for (int idx = lt; idx < 32 * 64; idx += 256) {
                int kk = idx >> 6, l = idx & 63;
                float v = (l0 + l < 250) ? g_y[yb + (kc + kk) * 250 + l0 + l] : 0.f;
                ysm[kk * 72 + l] = f2tf32(v);
            }
            __syncthreads();
            unsigned int* ysm2 = cbuf + half * 2304;
            #pragma unroll
            for (int ks = 0; ks < 4; ks++) {
                int kb = ks * 8;
                unsigned int fa0[2], fa1[2], fa2[2], fa3[2];
                #pragma unroll
                for (int m = 0; m < 2; m++) {
                    int row = m * 128 + 16 * w8 + g;
                    fa0[m] = wbuf[row * 36 + kb + tg];
                    fa1[m] = wbuf[(row + 8) * 36 + kb + tg];
                    fa2[m] = wbuf[row * 36 + kb + tg + 4];
                    fa3[m] = wbuf[(row + 8) * 36 + kb + tg + 4];
                }
                #pragma unroll
                for (int nt = 0; nt < 8; nt++) {
                    unsigned int fb0 = ysm2[(kb + tg) * 72 + nt * 8 + g];
                    unsigned int fb1 = ysm2[(kb + tg + 4) * 72 + nt * 8 + g];
                    #pragma unroll
                    for (int m = 0; m < 2; m++)
                        mma_tf32(c[m][nt][0], c[m][nt][1], c[m][nt][2], c[m][nt][3],
                                 fa0[m], fa1[m], fa2[m], fa3[m], fb0, fb1);
                }
            }
        }
        float ba0 = ob[16 * w8 + g],        ba8 = ob[16 * w8 + g + 8];
        float bb0 = ob[128 + 16 * w8 + g],  bb8 = ob[128 + 16 * w8 + g + 8];
        int rowA = 16 * w8 + g;
        #pragma unroll
        for (int nt = 0; nt < 8; nt++) {
            int col = nt * 8 + 2 * tg;
            if (l0 + col < 250) {
                float z1 = c[0][nt][0] + ba0, z2 = c[1][nt][0] + bb0;
                float z3 = c[0][nt][2] + ba8, z4 = c[1][nt][2] + bb8;
                gsm[(l0 + col) * 129 + rowA]     = f2tf32(z1 / (1.f + expf(-z2)));
                gsm[(l0 + col) * 129 + rowA + 8] = f2tf32(z3 / (1.f + expf(-z4)));
            }
            if (l0 + col + 1 < 250) {
                float z1 = c[0][nt][1] + ba0, z2 = c[1][nt][1] + bb0;
                float z3 = c[0][nt][3] + ba8, z4 = c[1][nt][3] + bb8;
                gsm[(l0 + col + 1) * 129 + rowA]     = f2tf32(z1 / (1.f + expf(-z2)));
                gsm[(l0 + col + 1) * 129 + rowA + 8] = f2tf32(z3 / (1.f + expf(-z4)));
            }
        }
    }
    __syncthreads();

    // ------------ phase 2: b2_flat = lw @ g_flat + lb, fused stats -----------
    float s_ = 0.f, ss_ = 0.f;
    for (int ri = 0; ri < 2; ri++) {
        int r0 = ri * 128 + half * 64;
        float c2[8][4];
        #pragma unroll
        for (int nt = 0; nt < 8; nt++)
            #pragma unroll
            for (int i = 0; i < 4; i++)
                c2[nt][i] = 0.f;

        for (int kc2 = 0; kc2 < 128; kc2 += 32) {
            __syncthreads();
            for (int idx = tid; idx < 128 * 32; idx += 512) {
                int row = idx >> 5, kk = idx & 31;
                wbuf[row * 36 + kk] = f2tf32(lw[row * 128 + kc2 + kk]);
            }
            unsigned int* gsm2 = cbuf + half * 2560;
            for (int idx = lt; idx < 64 * 32; idx += 256) {
                int r = idx >> 5, kk = idx & 31;
                int rg = r0 + r;
                unsigned int val = 0u;
                if (rg < 250) {
                    int o = rg * 128 + kc2 + kk;
                    int n = o / 250, l = o - n * 250;
                    val = gsm[l * 129 + n];
                }
                gsm2[r * 40 + kk] = val;
            }
            __syncthreads();
            unsigned int* gsm2b = cbuf + half * 2560;
            #pragma unroll
            for (int ks = 0; ks < 4; ks++) {
                int kb = ks * 8;
                int row = 16 * w8 + g;
                unsigned int fa0 = wbuf[row * 36 + kb + tg];
                unsigned int fa1 = wbuf[(row + 8) * 36 + kb + tg];
                unsigned int fa2 = wbuf[row * 36 + kb + tg + 4];
                unsigned int fa3 = wbuf[(row + 8) * 36 + kb + tg + 4];
                #pragma unroll
                for (int nt = 0; nt < 8; nt++) {
                    unsigned int fb0 = gsm2b[(nt * 8 + g) * 40 + kb + tg];
                    unsigned int fb1 = gsm2b[(nt * 8 + g) * 40 + kb + tg + 4];
                    mma_tf32(c2[nt][0], c2[nt][1], c2[nt][2], c2[nt][3],
                             fa0, fa1, fa2, fa3, fb0, fb1);
                }
            }
        }
        float bv0 = lb[16 * w8 + g], bv8 = lb[16 * w8 + g + 8];
        int ocol = 16 * w8 + g;
        #pragma unroll
        for (int nt = 0; nt < 8; nt++) {
            int trow = nt * 8 + 2 * tg;
            int rg = r0 + trow;
            if (rg < 250) {
                float v0 = c2[nt][0] + bv0;
                float v8 = c2[nt][2] + bv8;
                g_b2[yb + rg * 128 + ocol]     = v0;
                g_b2[yb + rg * 128 + ocol + 8] = v8;
                s_ += v0 + v8;
                ss_ = fmaf(v0, v0, ss_);
                ss_ = fmaf(v8, v8, ss_);
            }
            if (rg + 1 < 250) {
                float v0 = c2[nt][1] + bv0;
                float v8 = c2[nt][3] + bv8;
                g_b2[yb + (rg + 1) * 128 + ocol]     = v0;
                g_b2[yb + (rg + 1) * 128 + ocol + 8] = v8;
                s_ += v0 + v8;
                ss_ = fmaf(v0, v0, ss_);
                ss_ = fmaf(v8, v8, ss_);
            }
        }
    }
    rs[tid] = s_; rs2[tid] = ss_;
    __syncthreads();
    for (int st = 256; st > 0; st >>= 1) {
        if (tid < st) { rs[tid] += rs[tid + st]; rs2[tid] += rs2[tid + st]; }
        __syncthreads();
    }
    if (tid == 0) {
        g_redl[seq * 2 + 0] = rs[0];
        g_redl[seq * 2 + 1] = rs2[0];
    }
}

// ------------- GroupNorm stats combine (deterministic) -----------------------
__global__ void red_combine()
{
    int b = blockIdx.x;
    int tid = threadIdx.x;
    float s = 0.f, ss = 0.f;
    for (int i = tid; i < 250; i += 256) {
        s  += g_redl[(b * 250 + i) * 2 + 0];
        ss += g_redl[(b * 250 + i) * 2 + 1];
    }
    __shared__ float sm[256], sm2[256];
    sm[tid] = s; sm2[tid] = ss;
    __syncthreads();
    for (int st = 128; st > 0; st >>= 1) {
        if (tid < st) { sm[tid] += sm[tid + st]; sm2[tid] += sm2[tid + st]; }
        __syncthreads();
    }
    if (tid == 0) {
        float inv = 1.f / (float)PER_B;
        float mu = sm[0] * inv;
        float var = sm2[0] * inv - mu * mu;
        g_stats[b * 2 + 0] = mu;
        g_stats[b * 2 + 1] = rsqrtf(var + 1e-8f);
    }
}

// -------- intra finalize: transpose b2 -> [B,N,K,S], GN, + x  -> g_X1 --------
__global__ void finalize_intra(const float* __restrict__ x,
                               const float* __restrict__ gg,
                               const float* __restrict__ gb)
{
    __shared__ float tile[32][33];
    int bh = blockIdx.x;
    int b = bh >> 7, n = bh & 127;
    int k0 = blockIdx.y * 32, s0 = blockIdx.z * 32;
    int tx = threadIdx.x, ty = threadIdx.y;
    float mu = g_stats[b * 2], istd = g_stats[b * 2 + 1];
    float ga = gg[n] * istd;
    float gbb = gb[n] - mu * ga;
    #pragma unroll
    for (int yy = 0; yy < 32; yy += 8) {
        int s = s0 + ty + yy, k = k0 + tx;
        if (s < 250 && k < 250)
            tile[ty + yy][tx] = g_b2[(b * 250 + s) * SEQ_STRIDE + n * 250 + k];
    }
    __syncthreads();
    #pragma unroll
    for (int yy = 0; yy < 32; yy += 8) {
        int k = k0 + ty + yy, s = s0 + tx;
        if (s < 250 && k < 250) {
            int xi = ((b * 128 + n) * 250 + k) * 250 + s;
            g_X1[xi] = tile[tx][ty + yy] * ga + gbb + x[xi];
        }
    }
}

// ------------- inter finalize: GN + residual ---------------------------------
__global__ void finalize_inter(const float* __restrict__ gg,
                               const float* __restrict__ gb,
                               float* __restrict__ out)
{
    int idx = blockIdx.x * 256 + threadIdx.x;
    if (idx < TOT) {
        int b = idx / PER_B;
        int rem = idx - b * PER_B;
        int n = rem / 62500;
        int rem2 = rem - n * 62500;
        int k = rem2 / 250;
        int s = rem2 - k * 250;
        float v = g_b2[(b * 250 + k) * SEQ_STRIDE + n * 250 + s];
        float mu = g_stats[b * 2], istd = g_stats[b * 2 + 1];
        out[idx] = (v - mu) * istd * gg[n] + gb[n] + g_X1[idx];
    }
}

extern "C" void kernel_launch(void* const* d_in, const int* in_sizes, int n_in,
                              void* d_out, int out_size)
{
    const float* x = (const float*)d_in[0];
    const float* P[2][12];
    for (int p = 0; p < 2; p++)
        for (int i = 0; i < 12; i++)
            P[p][i] = (const float*)d_in[1 + p * 12 + i];
    float* out = (float*)d_out;

    cudaFuncSetAttribute(fused_ow_lw,
                         cudaFuncAttributeMaxDynamicSharedMemorySize, FUSED_SMEM);

    prep_params<<<128, 32>>>(P[0][0], P[0][1], P[0][2], P[0][3], P[0][4], 0);
    prep_params<<<128, 32>>>(P[1][0], P[1][1], P[1][2], P[1][3], P[1][4], 1);
    kern_gen<<<128, 256>>>(0);
    kern_gen<<<128, 256>>>(1);

    // ---- intra path ----
    conv_gemm<<<dim3(128, 2, 16), 256>>>(0, x, P[0][5]);
    fused_ow_lw<<<NSEQ, 512, FUSED_SMEM>>>(P[0][6], P[0][7], P[0][8], P[0][9]);
    red_combine<<<4, 256>>>();
    finalize_intra<<<dim3(512, 8, 8), dim3(32, 8)>>>(x, P[0][10], P[0][11]);

    // ---- inter path ----
    conv_gemm<<<dim3(128, 2, 16), 256>>>(1, x, P[1][5]);
    fused_ow_lw<<<NSEQ, 512, FUSED_SMEM>>>(P[1][6], P[1][7], P[1][8], P[1][9]);
    red_combine<<<4, 256>>>();
    finalize_inter<<<125000, 256>>>(P[1][10], P[1][11], out);
}

// round 10
// speedup vs baseline: 1.7030x; 1.1445x over previous
#include <cuda_runtime.h>
#include <stdint.h>
#include <math.h>

// Problem constants
#define Bb 4
#define Nn 128
#define Kk 250
#define Ss 250
#define Mm 32
#define NSEQ 1000
#define LSEQ 250
#define SEQ_STRIDE 32000
#define TOT 32000000
#define PER_B 8000000
#define NM 4096

#define FUSED_SMEM 196608

__device__ float g_y[TOT];
__device__ float g_b2[TOT];
__device__ float g_X1[TOT];
__device__ float g_P[2 * 6 * NM];           // planes: a_re,a_im,c2r,c2i,dre,dim
__device__ float g_kern[2 * 128 * 384];     // [path][h][128 pad + 250 taps + 6 pad]
__device__ unsigned int g_owf[2 * 32768];   // packed tf32 ow fragments
__device__ unsigned int g_lwf[2 * 16384];   // packed tf32 lw fragments
__device__ float g_redl[1000 * 2];
__device__ float g_stats[Bb * 2];

__device__ __forceinline__ unsigned int f2tf32(float f)
{
    unsigned int u;
    asm("cvt.rna.tf32.f32 %0, %1;" : "=r"(u) : "f"(f));
    return u;
}

__device__ __forceinline__ void mma_tf32(float& c0, float& c1, float& c2, float& c3,
                                         unsigned int fa0, unsigned int fa1,
                                         unsigned int fa2, unsigned int fa3,
                                         unsigned int fb0, unsigned int fb1)
{
    asm volatile("mma.sync.aligned.m16n8k8.row.col.f32.tf32.tf32.f32 "
                 "{%0,%1,%2,%3}, {%4,%5,%6,%7}, {%8,%9}, {%0,%1,%2,%3};"
                 : "+f"(c0), "+f"(c1), "+f"(c2), "+f"(c3)
                 : "r"(fa0), "r"(fa1), "r"(fa2), "r"(fa3), "r"(fb0), "r"(fb1));
}

// ---------------- parameter prep ---------------------------------------------
__global__ void prep_params(const float* __restrict__ log_dt,
                            const float* __restrict__ logA_re,
                            const float* __restrict__ A_im,
                            const float* __restrict__ C_re,
                            const float* __restrict__ C_im,
                            int path)
{
    int h = blockIdx.x;
    int m = threadIdx.x;
    float dt  = expf(log_dt[h]);
    float Are = -expf(logA_re[h * Mm + m]);
    float Aim = A_im[h * Mm + m];
    float dre = dt * Are, dim = dt * Aim;
    float e   = expf(dre);
    float vre = e * cosf(dim);
    float vim = e * sinf(dim);
    float nre = vre - 1.0f, nim = vim;
    float d2  = Are * Are + Aim * Aim;
    float qre = (nre * Are + nim * Aim) / d2;
    float qim = (nim * Are - nre * Aim) / d2;
    float cr  = C_re[h * Mm + m], ci = C_im[h * Mm + m];
    float c2r = 2.0f * (cr * qre - ci * qim);
    float c2i = 2.0f * (cr * qim + ci * qre);
    int base = path * 6 * NM + h * Mm + m;
    g_P[base + 0 * NM] = vre;
    g_P[base + 1 * NM] = vim;
    g_P[base + 2 * NM] = c2r;
    g_P[base + 3 * NM] = c2i;
    g_P[base + 4 * NM] = dre;
    g_P[base + 5 * NM] = dim;
}

// --------- kernel taps -------------------------------------------------------
__global__ void kern_gen(int path)
{
    int h = blockIdx.x;
    int tid = threadIdx.x;
    int w = tid >> 5, m = tid & 31;
    int base = path * 6 * NM + h * Mm + m;
    float ar  = g_P[base + 0 * NM];
    float ai  = g_P[base + 1 * NM];
    float c2r = g_P[base + 2 * NM];
    float c2i = g_P[base + 3 * NM];
    float dre = g_P[base + 4 * NM];
    float dim = g_P[base + 5 * NM];
    float l0 = (float)(w * 32);
    float e = expf(l0 * dre);
    float pr = e * cosf(l0 * dim);
    float pi = e * sinf(l0 * dim);
    float* kout = &g_kern[(path * 128 + h) * 384];
    if (tid < 128) kout[tid] = 0.f;
    if (tid < 6)   kout[378 + tid] = 0.f;
    for (int i = 0; i < 32; i++) {
        int l = w * 32 + i;
        float v = fmaf(c2r, pr, -c2i * pi);
        v += __shfl_xor_sync(0xffffffffu, v, 1);
        v += __shfl_xor_sync(0xffffffffu, v, 2);
        v += __shfl_xor_sync(0xffffffffu, v, 4);
        v += __shfl_xor_sync(0xffffffffu, v, 8);
        v += __shfl_xor_sync(0xffffffffu, v, 16);
        if (m == 0 && l < 250) kout[128 + l] = v;
        float t = pr;
        pr = fmaf(ar, t, -ai * pi);
        pi = fmaf(ai, t,  ar * pi);
    }
}

// --------- pack weights into per-fragment tf32 layout ------------------------
// owf idx bits: [kc32:13-14][w8:10-12][ks:8-9][m:7][lane:2-6][j:0-1]
// lwf idx bits: [kc32:12-13][w8:9-11][ks:7-8][lane:2-6][j:0-1]
__global__ void pack_w(const float* __restrict__ ow, const float* __restrict__ lw,
                       int path)
{
    int idx = blockIdx.x * 256 + threadIdx.x;
    if (idx < 32768) {
        int j = idx & 3;
        int lane = (idx >> 2) & 31;
        int m = (idx >> 7) & 1;
        int ks = (idx >> 8) & 3;
        int w8 = (idx >> 10) & 7;
        int kc32 = (idx >> 13) & 3;
        int g = lane >> 2, tg = lane & 3;
        int row = m * 128 + 16 * w8 + g + ((j & 1) ? 8 : 0);
        int col = kc32 * 32 + ks * 8 + tg + ((j >> 1) ? 4 : 0);
        g_owf[path * 32768 + idx] = f2tf32(ow[row * 128 + col]);
    } else {
        int id2 = idx - 32768;
        int j = id2 & 3;
        int lane = (id2 >> 2) & 31;
        int ks = (id2 >> 7) & 3;
        int w8 = (id2 >> 9) & 7;
        int kc32 = (id2 >> 12) & 3;
        int g = lane >> 2, tg = lane & 3;
        int row = 16 * w8 + g + ((j & 1) ? 8 : 0);
        int col = kc32 * 32 + ks * 8 + tg + ((j >> 1) ? 4 : 0);
        g_lwf[path * 16384 + id2] = f2tf32(lw[row * 128 + col]);
    }
}

// ------- conv as causal Toeplitz GEMM + direct-x path0 (R8 proven) -----------
__global__ void conv_gemm(int path, const float* __restrict__ x,
                          const float* __restrict__ Dv)
{
    __shared__ char smr[33792];
    unsigned int* ksm = (unsigned int*)smr;           // 384 words
    unsigned int* usm = (unsigned int*)(smr + 1536);  // [64 seq][36]
    float*        osm = (float*)smr;                  // [64 seq][129] (reused)

    int h   = blockIdx.x;
    int ko0 = blockIdx.y * 128;
    int s0  = blockIdx.z * 64;
    int tid = threadIdx.x;
    int w = tid >> 5, lane = tid & 31;
    int g = lane >> 2, tg = lane & 3;

    const float* kern = &g_kern[(path * 128 + h) * 384];
    for (int i = tid; i < 384; i += 256) ksm[i] = f2tf32(kern[i]);

    float c[8][4];
    #pragma unroll
    for (int nt = 0; nt < 8; nt++)
        #pragma unroll
        for (int i = 0; i < 4; i++)
            c[nt][i] = 0.f;

    int nch = (blockIdx.y == 0) ? 4 : 8;
    for (int ch = 0; ch < nch; ch++) {
        int ki0 = ch * 32;
        __syncthreads();
        if (path == 0) {
            for (int idx = tid; idx < 32 * 64; idx += 256) {
                int kk = idx >> 6, srow = idx & 63;
                int seq = s0 + srow, l = ki0 + kk;
                float v = 0.f;
                if (seq < 1000 && l < 250) {
                    int b = seq / 250, s = seq - b * 250;
                    v = x[((b * 128 + h) * 250 + l) * 250 + s];
                }
                usm[srow * 36 + kk] = f2tf32(v);
            }
        } else {
            for (int idx = tid; idx < 64 * 32; idx += 256) {
                int srow = idx >> 5, kk = idx & 31;
                int seq = s0 + srow, l = ki0 + kk;
                float v = 0.f;
                if (seq < 1000 && l < 250) {
                    int b = seq / 250, kq = seq - b * 250;
                    v = g_X1[b * PER_B + h * 62500 + kq * 250 + l];
                }
                usm[srow * 36 + kk] = f2tf32(v);
            }
        }
        __syncthreads();
        #pragma unroll
        for (int ks = 0; ks < 4; ks++) {
            int kb = ks * 8;
            int aoff = 128 + ko0 + 16 * w - ki0 - kb;
            unsigned int fa0 = ksm[aoff + g - tg];
            unsigned int fa1 = ksm[aoff + 8 + g - tg];
            unsigned int fa2 = ksm[aoff + g - tg - 4];
            unsigned int fa3 = ksm[aoff + 8 + g - tg - 4];
            #pragma unroll
            for (int nt = 0; nt < 8; nt++) {
                unsigned int fb0 = usm[(nt * 8 + g) * 36 + kb + tg];
                unsigned int fb1 = usm[(nt * 8 + g) * 36 + kb + tg + 4];
                mma_tf32(c[nt][0], c[nt][1], c[nt][2], c[nt][3],
                         fa0, fa1, fa2, fa3, fb0, fb1);
            }
        }
    }
    __syncthreads();

    #pragma unroll
    for (int nt = 0; nt < 8; nt++) {
        int col = nt * 8 + 2 * tg;
        int row = 16 * w + g;
        osm[col * 129 + row]           = c[nt][0];
        osm[(col + 1) * 129 + row]     = c[nt][1];
        osm[col * 129 + row + 8]       = c[nt][2];
        osm[(col + 1) * 129 + row + 8] = c[nt][3];
    }
    __syncthreads();

    float Dh = Dv[h];
    if (path == 0) {
        for (int idx = tid; idx < 64 * 128; idx += 256) {
            int kk = idx >> 6, srow = idx & 63;
            int seq = s0 + srow, kout = ko0 + kk;
            if (seq < 1000 && kout < 250) {
                int b = seq / 250, s = seq - b * 250;
                float u = x[((b * 128 + h) * 250 + kout) * 250 + s];
                float v = osm[srow * 129 + kk] + Dh * u;
                float t = 0.7978845608028654f * (v + 0.044715f * v * v * v);
                osm[srow * 129 + kk] = 0.5f * v * (1.f + tanhf(t));
            }
        }
        __syncthreads();
        for (int idx = tid; idx < 64 * 128; idx += 256) {
            int srow = idx >> 7, k = idx & 127;
            int seq = s0 + srow, kout = ko0 + k;
            if (seq < 1000 && kout < 250)
                g_y[seq * SEQ_STRIDE + h * 250 + kout] = osm[srow * 129 + k];
        }
    } else {
        for (int idx = tid; idx < 64 * 128; idx += 256) {
            int srow = idx >> 7, k = idx & 127;
            int seq = s0 + srow, kout = ko0 + k;
            if (seq < 1000 && kout < 250) {
                int b = seq / 250, kq = seq - b * 250;
                float u = g_X1[b * PER_B + h * 62500 + kq * 250 + kout];
                float v = osm[srow * 129 + k] + Dh * u;
                float t = 0.7978845608028654f * (v + 0.044715f * v * v * v);
                g_y[seq * SEQ_STRIDE + h * 250 + kout] = 0.5f * v * (1.f + tanhf(t));
            }
        }
    }
}

// ------ FUSED: ow GEMM + GLU (smem) + lw GEMM + bias + GN stats, per seq -----
// 512 thr / 16 warps; weights pre-packed in gmem (L2-resident).
// dyn smem: gsm [250][129] tf32 plane | cbuf per-half (ysm / gsm2 / obuf)
__global__ void fused_ow_lw(int path, const float* __restrict__ ob,
                            const float* __restrict__ lb)
{
    extern __shared__ unsigned int dynsm[];
    unsigned int* gsm  = dynsm;            // 32256 u32: [l][129]
    unsigned int* cbuf = dynsm + 32256;    // 2 x 8448 u32 per half
    __shared__ float rs[512], rs2[512];

    int seq  = blockIdx.x;
    int tid  = threadIdx.x;
    int w    = tid >> 5, lane = tid & 31;
    int half = tid >> 8;
    int lt   = tid & 255;
    int w8   = w & 7;
    int g = lane >> 2, tg = lane & 3;
    int yb = seq * SEQ_STRIDE;

    unsigned int* hbuf = cbuf + half * 8448;

    // ---------------- phase 1: z = ow@y+ob, GLU -> gsm ----------------
    for (int li = 0; li < 2; li++) {
        int l0 = li * 128 + half * 64;
        float c[2][8][4];
        #pragma unroll
        for (int m = 0; m < 2; m++)
            #pragma unroll
            for (int nt = 0; nt < 8; nt++)
                #pragma unroll
                for (int i = 0; i < 4; i++)
                    c[m][nt][i] = 0.f;

        for (int kc = 0; kc < 128; kc += 32) {
            __syncthreads();
            for (int idx = lt; idx < 32 * 64; idx += 256) {
                int kk = idx >> 6, l = idx & 63;
                float v = (l0 + l < 250) ? g_y[yb + (kc + kk) * 250 + l0 + l] : 0.f;
                hbuf[kk * 72 + l] = f2tf32(v);
            }
            __syncthreads();
            int kc32 = kc >> 5;
            #pragma unroll
            for (int ks = 0; ks < 4; ks++) {
                int kb = ks * 8;
                unsigned int fa0[2], fa1[2], fa2[2], fa3[2];
                #pragma unroll
                for (int m = 0; m < 2; m++) {
                    const uint4 Av = *(const uint4*)&g_owf[path * 32768 +
                        ((((kc32 * 8 + w8) * 4 + ks) * 2 + m) * 32 + lane) * 4];
                    fa0[m] = Av.x; fa1[m] = Av.y; fa2[m] = Av.z; fa3[m] = Av.w;
                }
                #pragma unroll
                for (int nt = 0; nt < 8; nt++) {
                    unsigned int fb0 = hbuf[(kb + tg) * 72 + nt * 8 + g];
                    unsigned int fb1 = hbuf[(kb + tg + 4) * 72 + nt * 8 + g];
                    #pragma unroll
                    for (int m = 0; m < 2; m++)
                        mma_tf32(c[m][nt][0], c[m][nt][1], c[m][nt][2], c[m][nt][3],
                                 fa0[m], fa1[m], fa2[m], fa3[m], fb0, fb1);
                }
            }
        }
        float ba0 = ob[16 * w8 + g],        ba8 = ob[16 * w8 + g + 8];
        float bb0 = ob[128 + 16 * w8 + g],  bb8 = ob[128 + 16 * w8 + g + 8];
        int rowA = 16 * w8 + g;
        #pragma unroll
        for (int nt = 0; nt < 8; nt++) {
            int col = nt * 8 + 2 * tg;
            if (l0 + col < 250) {
                float z1 = c[0][nt][0] + ba0, z2 = c[1][nt][0] + bb0;
                float z3 = c[0][nt][2] + ba8, z4 = c[1][nt][2] + bb8;
                gsm[(l0 + col) * 129 + rowA]     = f2tf32(z1 / (1.f + expf(-z2)));
                gsm[(l0 + col) * 129 + rowA + 8] = f2tf32(z3 / (1.f + expf(-z4)));
            }
            if (l0 + col + 1 < 250) {
                float z1 = c[0][nt][1] + ba0, z2 = c[1][nt][1] + bb0;
                float z3 = c[0][nt][3] + ba8, z4 = c[1][nt][3] + bb8;
                gsm[(l0 + col + 1) * 129 + rowA]     = f2tf32(z1 / (1.f + expf(-z2)));
                gsm[(l0 + col + 1) * 129 + rowA + 8] = f2tf32(z3 / (1.f + expf(-z4)));
            }
        }
    }
    __syncthreads();

    // ------------ phase 2: b2_flat = lw @ g_flat + lb, fused stats -----------
    float s_ = 0.f, ss_ = 0.f;
    for (int ri = 0; ri < 2; ri++) {
        int r0 = ri * 128 + half * 64;
        float c2[8][4];
        #pragma unroll
        for (int nt = 0; nt < 8; nt++)
            #pragma unroll
            for (int i = 0; i < 4; i++)
                c2[nt][i] = 0.f;

        for (int kc2 = 0; kc2 < 128; kc2 += 32) {
            __syncthreads();
            for (int idx = lt; idx < 64 * 32; idx += 256) {
                int r = idx >> 5, kk = idx & 31;
                int rg = r0 + r;
                unsigned int val = 0u;
                if (rg < 250) {
                    int o = rg * 128 + kc2 + kk;
                    int n = o / 250, l = o - n * 250;
                    val = gsm[l * 129 + n];
                }
                hbuf[r * 40 + kk] = val;
            }
            __syncthreads();
            int kc32 = kc2 >> 5;
            #pragma unroll
            for (int ks = 0; ks < 4; ks++) {
                int kb = ks * 8;
                const uint4 Av = *(const uint4*)&g_lwf[path * 16384 +
                    (((kc32 * 8 + w8) * 4 + ks) * 32 + lane) * 4];
                #pragma unroll
                for (int nt = 0; nt < 8; nt++) {
                    unsigned int fb0 = hbuf[(nt * 8 + g) * 40 + kb + tg];
                    unsigned int fb1 = hbuf[(nt * 8 + g) * 40 + kb + tg + 4];
                    mma_tf32(c2[nt][0], c2[nt][1], c2[nt][2], c2[nt][3],
                             Av.x, Av.y, Av.z, Av.w, fb0, fb1);
                }
            }
        }
        // stage to obuf (pad 132), then coalesced float4 store + stats
        float* obuf = (float*)hbuf;
        float bv0 = lb[16 * w8 + g], bv8 = lb[16 * w8 + g + 8];
        int ocol = 16 * w8 + g;
        __syncthreads();
        #pragma unroll
        for (int nt = 0; nt < 8; nt++) {
            int trow = nt * 8 + 2 * tg;
            obuf[trow * 132 + ocol]           = c2[nt][0] + bv0;
            obuf[(trow + 1) * 132 + ocol]     = c2[nt][1] + bv0;
            obuf[trow * 132 + ocol + 8]       = c2[nt][2] + bv8;
            obuf[(trow + 1) * 132 + ocol + 8] = c2[nt][3] + bv8;
        }
        __syncthreads();
        for (int i4 = lt; i4 < 64 * 32; i4 += 256) {
            int r = i4 >> 5, c4 = i4 & 31;
            int rg = r0 + r;
            if (rg < 250) {
                float4 v = *(float4*)&obuf[r * 132 + c4 * 4];
                *(float4*)&g_b2[yb + rg * 128 + c4 * 4] = v;
                s_ += (v.x + v.y) + (v.z + v.w);
                ss_ = fmaf(v.x, v.x, ss_);
                ss_ = fmaf(v.y, v.y, ss_);
                ss_ = fmaf(v.z, v.z, ss_);
                ss_ = fmaf(v.w, v.w, ss_);
            }
        }
    }
    rs[tid] = s_; rs2[tid] = ss_;
    __syncthreads();
    for (int st = 256; st > 0; st >>= 1) {
        if (tid < st) { rs[tid] += rs[tid + st]; rs2[tid] += rs2[tid + st]; }
        __syncthreads();
    }
    if (tid == 0) {
        g_redl[seq * 2 + 0] = rs[0];
        g_redl[seq * 2 + 1] = rs2[0];
    }
}

// ------------- GroupNorm stats combine (deterministic) -----------------------
__global__ void red_combine()
{
    int b = blockIdx.x;
    int tid = threadIdx.x;
    float s = 0.f, ss = 0.f;
    for (int i = tid; i < 250; i += 256) {
        s  += g_redl[(b * 250 + i) * 2 + 0];
        ss += g_redl[(b * 250 + i) * 2 + 1];
    }
    __shared__ float sm[256], sm2[256];
    sm[tid] = s; sm2[tid] = ss;
    __syncthreads();
    for (int st = 128; st > 0; st >>= 1) {
        if (tid < st) { sm[tid] += sm[tid + st]; sm2[tid] += sm2[tid + st]; }
        __syncthreads();
    }
    if (tid == 0) {
        float inv = 1.f / (float)PER_B;
        float mu = sm[0] * inv;
        float var = sm2[0] * inv - mu * mu;
        g_stats[b * 2 + 0] = mu;
        g_stats[b * 2 + 1] = rsqrtf(var + 1e-8f);
    }
}

// -------- intra finalize: transpose b2 -> [B,N,K,S], GN, + x  -> g_X1 --------
__global__ void finalize_intra(const float* __restrict__ x,
                               const float* __restrict__ gg,
                               const float* __restrict__ gb)
{
    __shared__ float tile[32][33];
    int bh = blockIdx.x;
    int b = bh >> 7, n = bh & 127;
    int k0 = blockIdx.y * 32, s0 = blockIdx.z * 32;
    int tx = threadIdx.x, ty = threadIdx.y;
    float mu = g_stats[b * 2], istd = g_stats[b * 2 + 1];
    float ga = gg[n] * istd;
    float gbb = gb[n] - mu * ga;
    #pragma unroll
    for (int yy = 0; yy < 32; yy += 8) {
        int s = s0 + ty + yy, k = k0 + tx;
        if (s < 250 && k < 250)
            tile[ty + yy][tx] = g_b2[(b * 250 + s) * SEQ_STRIDE + n * 250 + k];
    }
    __syncthreads();
    #pragma unroll
    for (int yy = 0; yy < 32; yy += 8) {
        int k = k0 + ty + yy, s = s0 + tx;
        if (s < 250 && k < 250) {
            int xi = ((b * 128 + n) * 250 + k) * 250 + s;
            g_X1[xi] = tile[tx][ty + yy] * ga + gbb + x[xi];
        }
    }
}

// ------------- inter finalize: GN + residual (float2) ------------------------
__global__ void finalize_inter(const float* __restrict__ gg,
                               const float* __restrict__ gb,
                               float* __restrict__ out)
{
    int idx2 = blockIdx.x * 256 + threadIdx.x;
    if (idx2 < TOT / 2) {
        int idx = idx2 * 2;
        int b = idx / PER_B;
        int rem = idx - b * PER_B;
        int n = rem / 62500;
        int rem2 = rem - n * 62500;
        int k = rem2 / 250;
        int s = rem2 - k * 250;
        float2 v2 = *(const float2*)&g_b2[(b * 250 + k) * SEQ_STRIDE + n * 250 + s];
        float2 x1 = *(const float2*)&g_X1[idx];
        float mu = g_stats[b * 2], istd = g_stats[b * 2 + 1];
        float ga = gg[n] * istd;
        float gbb = gb[n] - mu * ga;
        float2 r;
        r.x = v2.x * ga + gbb + x1.x;
        r.y = v2.y * ga + gbb + x1.y;
        *(float2*)&out[idx] = r;
    }
}

extern "C" void kernel_launch(void* const* d_in, const int* in_sizes, int n_in,
                              void* d_out, int out_size)
{
    const float* x = (const float*)d_in[0];
    const float* P[2][12];
    for (int p = 0; p < 2; p++)
        for (int i = 0; i < 12; i++)
            P[p][i] = (const float*)d_in[1 + p * 12 + i];
    float* out = (float*)d_out;

    cudaFuncSetAttribute(fused_ow_lw,
                         cudaFuncAttributeMaxDynamicSharedMemorySize, FUSED_SMEM);

    prep_params<<<128, 32>>>(P[0][0], P[0][1], P[0][2], P[0][3], P[0][4], 0);
    prep_params<<<128, 32>>>(P[1][0], P[1][1], P[1][2], P[1][3], P[1][4], 1);
    kern_gen<<<128, 256>>>(0);
    kern_gen<<<128, 256>>>(1);
    pack_w<<<192, 256>>>(P[0][6], P[0][8], 0);
    pack_w<<<192, 256>>>(P[1][6], P[1][8], 1);

    // ---- intra path ----
    conv_gemm<<<dim3(128, 2, 16), 256>>>(0, x, P[0][5]);
    fused_ow_lw<<<NSEQ, 512, FUSED_SMEM>>>(0, P[0][7], P[0][9]);
    red_combine<<<4, 256>>>();
    finalize_intra<<<dim3(512, 8, 8), dim3(32, 8)>>>(x, P[0][10], P[0][11]);

    // ---- inter path ----
    conv_gemm<<<dim3(128, 2, 16), 256>>>(1, x, P[1][5]);
    fused_ow_lw<<<NSEQ, 512, FUSED_SMEM>>>(1, P[1][7], P[1][9]);
    red_combine<<<4, 256>>>();
    finalize_inter<<<62500, 256>>>(P[1][10], P[1][11], out);
}

// round 11
// speedup vs baseline: 1.7679x; 1.0382x over previous
#include <cuda_runtime.h>
#include <stdint.h>
#include <math.h>

// Problem constants
#define Bb 4
#define Nn 128
#define Kk 250
#define Ss 250
#define Mm 32
#define NSEQ 1000
#define LSEQ 250
#define SEQ_STRIDE 32000
#define TOT 32000000
#define PER_B 8000000
#define NM 4096

#define FUSED_SMEM 196608

__device__ float g_y[TOT];                  // holds tf32-truncated bit patterns
__device__ float g_b2[TOT];
__device__ float g_X1[TOT];
__device__ float g_P[2 * 6 * NM];
__device__ float g_kern[2 * 128 * 384];
__device__ unsigned int g_owf[2 * 32768];
__device__ unsigned int g_lwf[2 * 16384];
__device__ float g_redl[1000 * 2];
__device__ float g_stats[Bb * 2];

__device__ __forceinline__ unsigned int f2tf32(float f)
{
    unsigned int u;
    asm("cvt.rna.tf32.f32 %0, %1;" : "=r"(u) : "f"(f));
    return u;
}

__device__ __forceinline__ void mma_tf32(float& c0, float& c1, float& c2, float& c3,
                                         unsigned int fa0, unsigned int fa1,
                                         unsigned int fa2, unsigned int fa3,
                                         unsigned int fb0, unsigned int fb1)
{
    asm volatile("mma.sync.aligned.m16n8k8.row.col.f32.tf32.tf32.f32 "
                 "{%0,%1,%2,%3}, {%4,%5,%6,%7}, {%8,%9}, {%0,%1,%2,%3};"
                 : "+f"(c0), "+f"(c1), "+f"(c2), "+f"(c3)
                 : "r"(fa0), "r"(fa1), "r"(fa2), "r"(fa3), "r"(fb0), "r"(fb1));
}

__device__ __forceinline__ void cp_async8(unsigned int dst_smem, const void* src,
                                          int src_bytes)
{
    asm volatile("cp.async.ca.shared.global [%0], [%1], 8, %2;"
                 :: "r"(dst_smem), "l"(src), "r"(src_bytes));
}
__device__ __forceinline__ void cp_commit()
{
    asm volatile("cp.async.commit_group;");
}
__device__ __forceinline__ void cp_wait0()
{
    asm volatile("cp.async.wait_group 0;");
}

// ---------------- parameter prep ---------------------------------------------
__global__ void prep_params(const float* __restrict__ log_dt,
                            const float* __restrict__ logA_re,
                            const float* __restrict__ A_im,
                            const float* __restrict__ C_re,
                            const float* __restrict__ C_im,
                            int path)
{
    int h = blockIdx.x;
    int m = threadIdx.x;
    float dt  = expf(log_dt[h]);
    float Are = -expf(logA_re[h * Mm + m]);
    float Aim = A_im[h * Mm + m];
    float dre = dt * Are, dim = dt * Aim;
    float e   = expf(dre);
    float vre = e * cosf(dim);
    float vim = e * sinf(dim);
    float nre = vre - 1.0f, nim = vim;
    float d2  = Are * Are + Aim * Aim;
    float qre = (nre * Are + nim * Aim) / d2;
    float qim = (nim * Are - nre * Aim) / d2;
    float cr  = C_re[h * Mm + m], ci = C_im[h * Mm + m];
    float c2r = 2.0f * (cr * qre - ci * qim);
    float c2i = 2.0f * (cr * qim + ci * qre);
    int base = path * 6 * NM + h * Mm + m;
    g_P[base + 0 * NM] = vre;
    g_P[base + 1 * NM] = vim;
    g_P[base + 2 * NM] = c2r;
    g_P[base + 3 * NM] = c2i;
    g_P[base + 4 * NM] = dre;
    g_P[base + 5 * NM] = dim;
}

// --------- kernel taps -------------------------------------------------------
__global__ void kern_gen(int path)
{
    int h = blockIdx.x;
    int tid = threadIdx.x;
    int w = tid >> 5, m = tid & 31;
    int base = path * 6 * NM + h * Mm + m;
    float ar  = g_P[base + 0 * NM];
    float ai  = g_P[base + 1 * NM];
    float c2r = g_P[base + 2 * NM];
    float c2i = g_P[base + 3 * NM];
    float dre = g_P[base + 4 * NM];
    float dim = g_P[base + 5 * NM];
    float l0 = (float)(w * 32);
    float e = expf(l0 * dre);
    float pr = e * cosf(l0 * dim);
    float pi = e * sinf(l0 * dim);
    float* kout = &g_kern[(path * 128 + h) * 384];
    if (tid < 128) kout[tid] = 0.f;
    if (tid < 6)   kout[378 + tid] = 0.f;
    for (int i = 0; i < 32; i++) {
        int l = w * 32 + i;
        float v = fmaf(c2r, pr, -c2i * pi);
        v += __shfl_xor_sync(0xffffffffu, v, 1);
        v += __shfl_xor_sync(0xffffffffu, v, 2);
        v += __shfl_xor_sync(0xffffffffu, v, 4);
        v += __shfl_xor_sync(0xffffffffu, v, 8);
        v += __shfl_xor_sync(0xffffffffu, v, 16);
        if (m == 0 && l < 250) kout[128 + l] = v;
        float t = pr;
        pr = fmaf(ar, t, -ai * pi);
        pi = fmaf(ai, t,  ar * pi);
    }
}

// --------- pack weights into per-fragment tf32 layout ------------------------
__global__ void pack_w(const float* __restrict__ ow, const float* __restrict__ lw,
                       int path)
{
    int idx = blockIdx.x * 256 + threadIdx.x;
    if (idx < 32768) {
        int j = idx & 3;
        int lane = (idx >> 2) & 31;
        int m = (idx >> 7) & 1;
        int ks = (idx >> 8) & 3;
        int w8 = (idx >> 10) & 7;
        int kc32 = (idx >> 13) & 3;
        int g = lane >> 2, tg = lane & 3;
        int row = m * 128 + 16 * w8 + g + ((j & 1) ? 8 : 0);
        int col = kc32 * 32 + ks * 8 + tg + ((j >> 1) ? 4 : 0);
        g_owf[path * 32768 + idx] = f2tf32(ow[row * 128 + col]);
    } else {
        int id2 = idx - 32768;
        int j = id2 & 3;
        int lane = (id2 >> 2) & 31;
        int ks = (id2 >> 7) & 3;
        int w8 = (id2 >> 9) & 7;
        int kc32 = (id2 >> 12) & 3;
        int g = lane >> 2, tg = lane & 3;
        int row = 16 * w8 + g + ((j & 1) ? 8 : 0);
        int col = kc32 * 32 + ks * 8 + tg + ((j >> 1) ? 4 : 0);
        g_lwf[path * 16384 + id2] = f2tf32(lw[row * 128 + col]);
    }
}

// ------- conv as causal Toeplitz GEMM + direct-x path0 (R8 proven) -----------
__global__ void conv_gemm(int path, const float* __restrict__ x,
                          const float* __restrict__ Dv)
{
    __shared__ char smr[33792];
    unsigned int* ksm = (unsigned int*)smr;           // 384 words
    unsigned int* usm = (unsigned int*)(smr + 1536);  // [64 seq][36]
    float*        osm = (float*)smr;                  // [64 seq][129] (reused)

    int h   = blockIdx.x;
    int ko0 = blockIdx.y * 128;
    int s0  = blockIdx.z * 64;
    int tid = threadIdx.x;
    int w = tid >> 5, lane = tid & 31;
    int g = lane >> 2, tg = lane & 3;

    const float* kern = &g_kern[(path * 128 + h) * 384];
    for (int i = tid; i < 384; i += 256) ksm[i] = f2tf32(kern[i]);

    float c[8][4];
    #pragma unroll
    for (int nt = 0; nt < 8; nt++)
        #pragma unroll
        for (int i = 0; i < 4; i++)
            c[nt][i] = 0.f;

    int nch = (blockIdx.y == 0) ? 4 : 8;
    for (int ch = 0; ch < nch; ch++) {
        int ki0 = ch * 32;
        __syncthreads();
        if (path == 0) {
            for (int idx = tid; idx < 32 * 64; idx += 256) {
                int kk = idx >> 6, srow = idx & 63;
                int seq = s0 + srow, l = ki0 + kk;
                float v = 0.f;
                if (seq < 1000 && l < 250) {
                    int b = seq / 250, s = seq - b * 250;
                    v = x[((b * 128 + h) * 250 + l) * 250 + s];
                }
                usm[srow * 36 + kk] = f2tf32(v);
            }
        } else {
            for (int idx = tid; idx < 64 * 32; idx += 256) {
                int srow = idx >> 5, kk = idx & 31;
                int seq = s0 + srow, l = ki0 + kk;
                float v = 0.f;
                if (seq < 1000 && l < 250) {
                    int b = seq / 250, kq = seq - b * 250;
                    v = g_X1[b * PER_B + h * 62500 + kq * 250 + l];
                }
                usm[srow * 36 + kk] = f2tf32(v);
            }
        }
        __syncthreads();
        #pragma unroll
        for (int ks = 0; ks < 4; ks++) {
            int kb = ks * 8;
            int aoff = 128 + ko0 + 16 * w - ki0 - kb;
            unsigned int fa0 = ksm[aoff + g - tg];
            unsigned int fa1 = ksm[aoff + 8 + g - tg];
            unsigned int fa2 = ksm[aoff + g - tg - 4];
            unsigned int fa3 = ksm[aoff + 8 + g - tg - 4];
            #pragma unroll
            for (int nt = 0; nt < 8; nt++) {
                unsigned int fb0 = usm[(nt * 8 + g) * 36 + kb + tg];
                unsigned int fb1 = usm[(nt * 8 + g) * 36 + kb + tg + 4];
                mma_tf32(c[nt][0], c[nt][1], c[nt][2], c[nt][3],
                         fa0, fa1, fa2, fa3, fb0, fb1);
            }
        }
    }
    __syncthreads();

    #pragma unroll
    for (int nt = 0; nt < 8; nt++) {
        int col = nt * 8 + 2 * tg;
        int row = 16 * w + g;
        osm[col * 129 + row]           = c[nt][0];
        osm[(col + 1) * 129 + row]     = c[nt][1];
        osm[col * 129 + row + 8]       = c[nt][2];
        osm[(col + 1) * 129 + row + 8] = c[nt][3];
    }
    __syncthreads();

    float Dh = Dv[h];
    if (path == 0) {
        for (int idx = tid; idx < 64 * 128; idx += 256) {
            int kk = idx >> 6, srow = idx & 63;
            int seq = s0 + srow, kout = ko0 + kk;
            if (seq < 1000 && kout < 250) {
                int b = seq / 250, s = seq - b * 250;
                float u = x[((b * 128 + h) * 250 + kout) * 250 + s];
                float v = osm[srow * 129 + kk] + Dh * u;
                float t = 0.7978845608028654f * (v + 0.044715f * v * v * v);
                osm[srow * 129 + kk] = 0.5f * v * (1.f + tanhf(t));
            }
        }
        __syncthreads();
        for (int idx = tid; idx < 64 * 128; idx += 256) {
            int srow = idx >> 7, k = idx & 127;
            int seq = s0 + srow, kout = ko0 + k;
            if (seq < 1000 && kout < 250)
                g_y[seq * SEQ_STRIDE + h * 250 + kout] =
                    __uint_as_float(f2tf32(osm[srow * 129 + k]));
        }
    } else {
        for (int idx = tid; idx < 64 * 128; idx += 256) {
            int srow = idx >> 7, k = idx & 127;
            int seq = s0 + srow, kout = ko0 + k;
            if (seq < 1000 && kout < 250) {
                int b = seq / 250, kq = seq - b * 250;
                float u = g_X1[b * PER_B + h * 62500 + kq * 250 + kout];
                float v = osm[srow * 129 + k] + Dh * u;
                float t = 0.7978845608028654f * (v + 0.044715f * v * v * v);
                g_y[seq * SEQ_STRIDE + h * 250 + kout] =
                    __uint_as_float(f2tf32(0.5f * v * (1.f + tanhf(t))));
            }
        }
    }
}

// ------ FUSED: ow GEMM + GLU (smem) + lw GEMM + bias + GN stats, per seq -----
// 512 thr / 16 warps; weights pre-packed; y staged via double-buffered cp.async
__global__ void fused_ow_lw(int path, const float* __restrict__ ob,
                            const float* __restrict__ lb)
{
    extern __shared__ unsigned int dynsm[];
    unsigned int* gsm  = dynsm;            // 32256 u32: [l][129]
    unsigned int* cbuf = dynsm + 32256;    // 2 x 8448 u32 per half
    __shared__ float rs[512], rs2[512];

    int seq  = blockIdx.x;
    int tid  = threadIdx.x;
    int w    = tid >> 5, lane = tid & 31;
    int half = tid >> 8;
    int lt   = tid & 255;
    int w8   = w & 7;
    int g = lane >> 2, tg = lane & 3;
    int yb = seq * SEQ_STRIDE;

    unsigned int* hbuf = cbuf + half * 8448;
    // phase-1 double buffers (each 32x72 = 2304 u32)
    unsigned int hbase = (unsigned int)__cvta_generic_to_shared(hbuf);

    // ---------------- phase 1: z = ow@y+ob, GLU -> gsm ----------------
    for (int li = 0; li < 2; li++) {
        int l0 = li * 128 + half * 64;
        float c[2][8][4];
        #pragma unroll
        for (int m = 0; m < 2; m++)
            #pragma unroll
            for (int nt = 0; nt < 8; nt++)
                #pragma unroll
                for (int i = 0; i < 4; i++)
                    c[m][nt][i] = 0.f;

        __syncthreads();   // protect buffers from previous iteration's readers
        // prologue: stage chunk 0 into buffer 0
        {
            #pragma unroll
            for (int j = 0; j < 4; j++) {
                int q = lt + 256 * j;
                int kk = q >> 5, pos = (q & 31) * 2;
                int lg = l0 + pos;
                int rem = 250 - lg;
                int bytes = (rem <= 0) ? 0 : (rem >= 2 ? 8 : 4);
                const float* src = (rem <= 0) ? g_y : &g_y[yb + kk * 250 + lg];
                cp_async8(hbase + (kk * 72 + pos) * 4, src, bytes);
            }
            cp_commit();
        }
        for (int kcid = 0; kcid < 4; kcid++) {
            cp_wait0();
            __syncthreads();
            if (kcid < 3) {
                int kcn = (kcid + 1) * 32;
                unsigned int dstb = hbase + (((kcid + 1) & 1) * 2304) * 4;
                #pragma unroll
                for (int j = 0; j < 4; j++) {
                    int q = lt + 256 * j;
                    int kk = q >> 5, pos = (q & 31) * 2;
                    int lg = l0 + pos;
                    int rem = 250 - lg;
                    int bytes = (rem <= 0) ? 0 : (rem >= 2 ? 8 : 4);
                    const float* src = (rem <= 0) ? g_y
                        : &g_y[yb + (kcn + kk) * 250 + lg];
                    cp_async8(dstb + (kk * 72 + pos) * 4, src, bytes);
                }
                cp_commit();
            }
            unsigned int* ybuf = hbuf + (kcid & 1) * 2304;
            int kc32 = kcid;
            #pragma unroll
            for (int ks = 0; ks < 4; ks++) {
                int kb = ks * 8;
                unsigned int fa0[2], fa1[2], fa2[2], fa3[2];
                #pragma unroll
                for (int m = 0; m < 2; m++) {
                    const uint4 Av = *(const uint4*)&g_owf[path * 32768 +
                        ((((kc32 * 8 + w8) * 4 + ks) * 2 + m) * 32 + lane) * 4];
                    fa0[m] = Av.x; fa1[m] = Av.y; fa2[m] = Av.z; fa3[m] = Av.w;
                }
                #pragma unroll
                for (int nt = 0; nt < 8; nt++) {
                    unsigned int fb0 = ybuf[(kb + tg) * 72 + nt * 8 + g];
                    unsigned int fb1 = ybuf[(kb + tg + 4) * 72 + nt * 8 + g];
                    #pragma unroll
                    for (int m = 0; m < 2; m++)
                        mma_tf32(c[m][nt][0], c[m][nt][1], c[m][nt][2], c[m][nt][3],
                                 fa0[m], fa1[m], fa2[m], fa3[m], fb0, fb1);
                }
            }
        }
        float ba0 = ob[16 * w8 + g],        ba8 = ob[16 * w8 + g + 8];
        float bb0 = ob[128 + 16 * w8 + g],  bb8 = ob[128 + 16 * w8 + g + 8];
        int rowA = 16 * w8 + g;
        #pragma unroll
        for (int nt = 0; nt < 8; nt++) {
            int col = nt * 8 + 2 * tg;
            if (l0 + col < 250) {
                float z1 = c[0][nt][0] + ba0, z2 = c[1][nt][0] + bb0;
                float z3 = c[0][nt][2] + ba8, z4 = c[1][nt][2] + bb8;
                gsm[(l0 + col) * 129 + rowA]     = f2tf32(z1 / (1.f + expf(-z2)));
                gsm[(l0 + col) * 129 + rowA + 8] = f2tf32(z3 / (1.f + expf(-z4)));
            }
            if (l0 + col + 1 < 250) {
                float z1 = c[0][nt][1] + ba0, z2 = c[1][nt][1] + bb0;
                float z3 = c[0][nt][3] + ba8, z4 = c[1][nt][3] + bb8;
                gsm[(l0 + col + 1) * 129 + rowA]     = f2tf32(z1 / (1.f + expf(-z2)));
                gsm[(l0 + col + 1) * 129 + rowA + 8] = f2tf32(z3 / (1.f + expf(-z4)));
            }
        }
    }
    __syncthreads();

    // ------------ phase 2: b2_flat = lw @ g_flat + lb, fused stats -----------
    float s_ = 0.f, ss_ = 0.f;
    for (int ri = 0; ri < 2; ri++) {
        int r0 = ri * 128 + half * 64;
        float c2[8][4];
        #pragma unroll
        for (int nt = 0; nt < 8; nt++)
            #pragma unroll
            for (int i = 0; i < 4; i++)
                c2[nt][i] = 0.f;

        for (int kc2 = 0; kc2 < 128; kc2 += 32) {
            __syncthreads();
            for (int idx = lt; idx < 64 * 32; idx += 256) {
                int r = idx >> 5, kk = idx & 31;
                int rg = r0 + r;
                unsigned int val = 0u;
                if (rg < 250) {
                    int o = rg * 128 + kc2 + kk;
                    int n = o / 250, l = o - n * 250;
                    val = gsm[l * 129 + n];
                }
                hbuf[r * 40 + kk] = val;
            }
            __syncthreads();
            int kc32 = kc2 >> 5;
            #pragma unroll
            for (int ks = 0; ks < 4; ks++) {
                int kb = ks * 8;
                const uint4 Av = *(const uint4*)&g_lwf[path * 16384 +
                    (((kc32 * 8 + w8) * 4 + ks) * 32 + lane) * 4];
                #pragma unroll
                for (int nt = 0; nt < 8; nt++) {
                    unsigned int fb0 = hbuf[(nt * 8 + g) * 40 + kb + tg];
                    unsigned int fb1 = hbuf[(nt * 8 + g) * 40 + kb + tg + 4];
                    mma_tf32(c2[nt][0], c2[nt][1], c2[nt][2], c2[nt][3],
                             Av.x, Av.y, Av.z, Av.w, fb0, fb1);
                }
            }
        }
        float* obuf = (float*)hbuf;
        float bv0 = lb[16 * w8 + g], bv8 = lb[16 * w8 + g + 8];
        int ocol = 16 * w8 + g;
        __syncthreads();
        #pragma unroll
        for (int nt = 0; nt < 8; nt++) {
            int trow = nt * 8 + 2 * tg;
            obuf[trow * 132 + ocol]           = c2[nt][0] + bv0;
            obuf[(trow + 1) * 132 + ocol]     = c2[nt][1] + bv0;
            obuf[trow * 132 + ocol + 8]       = c2[nt][2] + bv8;
            obuf[(trow + 1) * 132 + ocol + 8] = c2[nt][3] + bv8;
        }
        __syncthreads();
        for (int i4 = lt; i4 < 64 * 32; i4 += 256) {
            int r = i4 >> 5, c4 = i4 & 31;
            int rg = r0 + r;
            if (rg < 250) {
                float4 v = *(float4*)&obuf[r * 132 + c4 * 4];
                *(float4*)&g_b2[yb + rg * 128 + c4 * 4] = v;
                s_ += (v.x + v.y) + (v.z + v.w);
                ss_ = fmaf(v.x, v.x, ss_);
                ss_ = fmaf(v.y, v.y, ss_);
                ss_ = fmaf(v.z, v.z, ss_);
                ss_ = fmaf(v.w, v.w, ss_);
            }
        }
    }
    rs[tid] = s_; rs2[tid] = ss_;
    __syncthreads();
    for (int st = 256; st > 0; st >>= 1) {
        if (tid < st) { rs[tid] += rs[tid + st]; rs2[tid] += rs2[tid + st]; }
        __syncthreads();
    }
    if (tid == 0) {
        g_redl[seq * 2 + 0] = rs[0];
        g_redl[seq * 2 + 1] = rs2[0];
    }
}

// ------------- GroupNorm stats combine (deterministic) -----------------------
__global__ void red_combine()
{
    int b = blockIdx.x;
    int tid = threadIdx.x;
    float s = 0.f, ss = 0.f;
    for (int i = tid; i < 250; i += 256) {
        s  += g_redl[(b * 250 + i) * 2 + 0];
        ss += g_redl[(b * 250 + i) * 2 + 1];
    }
    __shared__ float sm[256], sm2[256];
    sm[tid] = s; sm2[tid] = ss;
    __syncthreads();
    for (int st = 128; st > 0; st >>= 1) {
        if (tid < st) { sm[tid] += sm[tid + st]; sm2[tid] += sm2[tid + st]; }
        __syncthreads();
    }
    if (tid == 0) {
        float inv = 1.f / (float)PER_B;
        float mu = sm[0] * inv;
        float var = sm2[0] * inv - mu * mu;
        g_stats[b * 2 + 0] = mu;
        g_stats[b * 2 + 1] = rsqrtf(var + 1e-8f);
    }
}

// -------- intra finalize: transpose b2 -> [B,N,K,S], GN, + x  -> g_X1 --------
__global__ void finalize_intra(const float* __restrict__ x,
                               const float* __restrict__ gg,
                               const float* __restrict__ gb)
{
    __shared__ float tile[32][33];
    int bh = blockIdx.x;
    int b = bh >> 7, n = bh & 127;
    int k0 = blockIdx.y * 32, s0 = blockIdx.z * 32;
    int tx = threadIdx.x, ty = threadIdx.y;
    float mu = g_stats[b * 2], istd = g_stats[b * 2 + 1];
    float ga = gg[n] * istd;
    float gbb = gb[n] - mu * ga;
    #pragma unroll
    for (int yy = 0; yy < 32; yy += 8) {
        int s = s0 + ty + yy, k = k0 + tx;
        if (s < 250 && k < 250)
            tile[ty + yy][tx] = g_b2[(b * 250 + s) * SEQ_STRIDE + n * 250 + k];
    }
    __syncthreads();
    #pragma unroll
    for (int yy = 0; yy < 32; yy += 8) {
        int k = k0 + ty + yy, s = s0 + tx;
        if (s < 250 && k < 250) {
            int xi = ((b * 128 + n) * 250 + k) * 250 + s;
            g_X1[xi] = tile[tx][ty + yy] * ga + gbb + x[xi];
        }
    }
}

// ------------- inter finalize: GN + residual (float2) ------------------------
__global__ void finalize_inter(const float* __restrict__ gg,
                               const float* __restrict__ gb,
                               float* __restrict__ out)
{
    int idx2 = blockIdx.x * 256 + threadIdx.x;
    if (idx2 < TOT / 2) {
        int idx = idx2 * 2;
        int b = idx / PER_B;
        int rem = idx - b * PER_B;
        int n = rem / 62500;
        int rem2 = rem - n * 62500;
        int k = rem2 / 250;
        int s = rem2 - k * 250;
        float2 v2 = *(const float2*)&g_b2[(b * 250 + k) * SEQ_STRIDE + n * 250 + s];
        float2 x1 = *(const float2*)&g_X1[idx];
        float mu = g_stats[b * 2], istd = g_stats[b * 2 + 1];
        float ga = gg[n] * istd;
        float gbb = gb[n] - mu * ga;
        float2 r;
        r.x = v2.x * ga + gbb + x1.x;
        r.y = v2.y * ga + gbb + x1.y;
        *(float2*)&out[idx] = r;
    }
}

extern "C" void kernel_launch(void* const* d_in, const int* in_sizes, int n_in,
                              void* d_out, int out_size)
{
    const float* x = (const float*)d_in[0];
    const float* P[2][12];
    for (int p = 0; p < 2; p++)
        for (int i = 0; i < 12; i++)
            P[p][i] = (const float*)d_in[1 + p * 12 + i];
    float* out = (float*)d_out;

    cudaFuncSetAttribute(fused_ow_lw,
                         cudaFuncAttributeMaxDynamicSharedMemorySize, FUSED_SMEM);

    prep_params<<<128, 32>>>(P[0][0], P[0][1], P[0][2], P[0][3], P[0][4], 0);
    prep_params<<<128, 32>>>(P[1][0], P[1][1], P[1][2], P[1][3], P[1][4], 1);
    kern_gen<<<128, 256>>>(0);
    kern_gen<<<128, 256>>>(1);
    pack_w<<<192, 256>>>(P[0][6], P[0][8], 0);
    pack_w<<<192, 256>>>(P[1][6], P[1][8], 1);

    // ---- intra path ----
    conv_gemm<<<dim3(128, 2, 16), 256>>>(0, x, P[0][5]);
    fused_ow_lw<<<NSEQ, 512, FUSED_SMEM>>>(0, P[0][7], P[0][9]);
    red_combine<<<4, 256>>>();
    finalize_intra<<<dim3(512, 8, 8), dim3(32, 8)>>>(x, P[0][10], P[0][11]);

    // ---- inter path ----
    conv_gemm<<<dim3(128, 2, 16), 256>>>(1, x, P[1][5]);
    fused_ow_lw<<<NSEQ, 512, FUSED_SMEM>>>(1, P[1][7], P[1][9]);
    red_combine<<<4, 256>>>();
    finalize_inter<<<62500, 256>>>(P[1][10], P[1][11], out);
}

// round 12
// speedup vs baseline: 1.8219x; 1.0305x over previous
#include <cuda_runtime.h>
#include <stdint.h>
#include <math.h>

// Problem constants
#define Bb 4
#define Nn 128
#define Kk 250
#define Ss 250
#define Mm 32
#define NSEQ 1000
#define LSEQ 250
#define SEQ_STRIDE 32000
#define TOT 32000000
#define PER_B 8000000
#define NM 4096

#define FUSED_SMEM 196608

__device__ float g_y[TOT];                  // holds tf32-truncated bit patterns
__device__ float g_b2[TOT];
__device__ float g_X1[TOT];
__device__ float g_P[2 * 6 * NM];
__device__ float g_kern[2 * 128 * 384];
__device__ unsigned int g_owf[2 * 32768];
__device__ unsigned int g_lwf[2 * 16384];
__device__ float g_redl[1000 * 2];
__device__ float g_stats[Bb * 2];

__device__ __forceinline__ unsigned int f2tf32(float f)
{
    unsigned int u;
    asm("cvt.rna.tf32.f32 %0, %1;" : "=r"(u) : "f"(f));
    return u;
}

__device__ __forceinline__ float gelu_f(float v)
{
    float t = 0.7978845608028654f * fmaf(0.044715f * v, v * v, v);
    float tc = fminf(fmaxf(t, -15.f), 15.f);
    float et = __expf(2.f * tc);
    float th = __fdividef(et - 1.f, et + 1.f);
    return 0.5f * v * (1.f + th);
}

__device__ __forceinline__ void mma_tf32(float& c0, float& c1, float& c2, float& c3,
                                         unsigned int fa0, unsigned int fa1,
                                         unsigned int fa2, unsigned int fa3,
                                         unsigned int fb0, unsigned int fb1)
{
    asm volatile("mma.sync.aligned.m16n8k8.row.col.f32.tf32.tf32.f32 "
                 "{%0,%1,%2,%3}, {%4,%5,%6,%7}, {%8,%9}, {%0,%1,%2,%3};"
                 : "+f"(c0), "+f"(c1), "+f"(c2), "+f"(c3)
                 : "r"(fa0), "r"(fa1), "r"(fa2), "r"(fa3), "r"(fb0), "r"(fb1));
}

__device__ __forceinline__ void cp_async8(unsigned int dst_smem, const void* src,
                                          int src_bytes)
{
    asm volatile("cp.async.ca.shared.global [%0], [%1], 8, %2;"
                 :: "r"(dst_smem), "l"(src), "r"(src_bytes));
}
__device__ __forceinline__ void cp_commit()
{
    asm volatile("cp.async.commit_group;");
}
__device__ __forceinline__ void cp_wait0()
{
    asm volatile("cp.async.wait_group 0;");
}

// ---------------- parameter prep ---------------------------------------------
__global__ void prep_params(const float* __restrict__ log_dt,
                            const float* __restrict__ logA_re,
                            const float* __restrict__ A_im,
                            const float* __restrict__ C_re,
                            const float* __restrict__ C_im,
                            int path)
{
    int h = blockIdx.x;
    int m = threadIdx.x;
    float dt  = expf(log_dt[h]);
    float Are = -expf(logA_re[h * Mm + m]);
    float Aim = A_im[h * Mm + m];
    float dre = dt * Are, dim = dt * Aim;
    float e   = expf(dre);
    float vre = e * cosf(dim);
    float vim = e * sinf(dim);
    float nre = vre - 1.0f, nim = vim;
    float d2  = Are * Are + Aim * Aim;
    float qre = (nre * Are + nim * Aim) / d2;
    float qim = (nim * Are - nre * Aim) / d2;
    float cr  = C_re[h * Mm + m], ci = C_im[h * Mm + m];
    float c2r = 2.0f * (cr * qre - ci * qim);
    float c2i = 2.0f * (cr * qim + ci * qre);
    int base = path * 6 * NM + h * Mm + m;
    g_P[base + 0 * NM] = vre;
    g_P[base + 1 * NM] = vim;
    g_P[base + 2 * NM] = c2r;
    g_P[base + 3 * NM] = c2i;
    g_P[base + 4 * NM] = dre;
    g_P[base + 5 * NM] = dim;
}

// --------- kernel taps -------------------------------------------------------
__global__ void kern_gen(int path)
{
    int h = blockIdx.x;
    int tid = threadIdx.x;
    int w = tid >> 5, m = tid & 31;
    int base = path * 6 * NM + h * Mm + m;
    float ar  = g_P[base + 0 * NM];
    float ai  = g_P[base + 1 * NM];
    float c2r = g_P[base + 2 * NM];
    float c2i = g_P[base + 3 * NM];
    float dre = g_P[base + 4 * NM];
    float dim = g_P[base + 5 * NM];
    float l0 = (float)(w * 32);
    float e = expf(l0 * dre);
    float pr = e * cosf(l0 * dim);
    float pi = e * sinf(l0 * dim);
    float* kout = &g_kern[(path * 128 + h) * 384];
    if (tid < 128) kout[tid] = 0.f;
    if (tid < 6)   kout[378 + tid] = 0.f;
    for (int i = 0; i < 32; i++) {
        int l = w * 32 + i;
        float v = fmaf(c2r, pr, -c2i * pi);
        v += __shfl_xor_sync(0xffffffffu, v, 1);
        v += __shfl_xor_sync(0xffffffffu, v, 2);
        v += __shfl_xor_sync(0xffffffffu, v, 4);
        v += __shfl_xor_sync(0xffffffffu, v, 8);
        v += __shfl_xor_sync(0xffffffffu, v, 16);
        if (m == 0 && l < 250) kout[128 + l] = v;
        float t = pr;
        pr = fmaf(ar, t, -ai * pi);
        pi = fmaf(ai, t,  ar * pi);
    }
}

// --------- pack weights into per-fragment tf32 layout ------------------------
__global__ void pack_w(const float* __restrict__ ow, const float* __restrict__ lw,
                       int path)
{
    int idx = blockIdx.x * 256 + threadIdx.x;
    if (idx < 32768) {
        int j = idx & 3;
        int lane = (idx >> 2) & 31;
        int m = (idx >> 7) & 1;
        int ks = (idx >> 8) & 3;
        int w8 = (idx >> 10) & 7;
        int kc32 = (idx >> 13) & 3;
        int g = lane >> 2, tg = lane & 3;
        int row = m * 128 + 16 * w8 + g + ((j & 1) ? 8 : 0);
        int col = kc32 * 32 + ks * 8 + tg + ((j >> 1) ? 4 : 0);
        g_owf[path * 32768 + idx] = f2tf32(ow[row * 128 + col]);
    } else {
        int id2 = idx - 32768;
        int j = id2 & 3;
        int lane = (id2 >> 2) & 31;
        int ks = (id2 >> 7) & 3;
        int w8 = (id2 >> 9) & 7;
        int kc32 = (id2 >> 12) & 3;
        int g = lane >> 2, tg = lane & 3;
        int row = 16 * w8 + g + ((j & 1) ? 8 : 0);
        int col = kc32 * 32 + ks * 8 + tg + ((j >> 1) ? 4 : 0);
        g_lwf[path * 16384 + id2] = f2tf32(lw[row * 128 + col]);
    }
}

// ------- conv as causal Toeplitz GEMM + direct-x path0 -----------------------
__global__ void conv_gemm(int path, const float* __restrict__ x,
                          const float* __restrict__ Dv)
{
    __shared__ char smr[33792];
    unsigned int* ksm = (unsigned int*)smr;           // 384 words
    unsigned int* usm = (unsigned int*)(smr + 1536);  // [64 seq][36]
    float*        osm = (float*)smr;                  // [64 seq][129] (reused)

    int h   = blockIdx.x;
    int ko0 = blockIdx.y * 128;
    int s0  = blockIdx.z * 64;
    int tid = threadIdx.x;
    int w = tid >> 5, lane = tid & 31;
    int g = lane >> 2, tg = lane & 3;

    const float* kern = &g_kern[(path * 128 + h) * 384];
    for (int i = tid; i < 384; i += 256) ksm[i] = f2tf32(kern[i]);

    float c[8][4];
    #pragma unroll
    for (int nt = 0; nt < 8; nt++)
        #pragma unroll
        for (int i = 0; i < 4; i++)
            c[nt][i] = 0.f;

    int nch = (blockIdx.y == 0) ? 4 : 8;
    for (int ch = 0; ch < nch; ch++) {
        int ki0 = ch * 32;
        __syncthreads();
        if (path == 0) {
            for (int idx = tid; idx < 32 * 64; idx += 256) {
                int kk = idx >> 6, srow = idx & 63;
                int seq = s0 + srow, l = ki0 + kk;
                float v = 0.f;
                if (seq < 1000 && l < 250) {
                    int b = seq / 250, s = seq - b * 250;
                    v = x[((b * 128 + h) * 250 + l) * 250 + s];
                }
                usm[srow * 36 + kk] = f2tf32(v);
            }
        } else {
            for (int idx = tid; idx < 64 * 32; idx += 256) {
                int srow = idx >> 5, kk = idx & 31;
                int seq = s0 + srow, l = ki0 + kk;
                float v = 0.f;
                if (seq < 1000 && l < 250) {
                    int b = seq / 250, kq = seq - b * 250;
                    v = g_X1[b * PER_B + h * 62500 + kq * 250 + l];
                }
                usm[srow * 36 + kk] = f2tf32(v);
            }
        }
        __syncthreads();
        #pragma unroll
        for (int ks = 0; ks < 4; ks++) {
            int kb = ks * 8;
            int aoff = 128 + ko0 + 16 * w - ki0 - kb;
            unsigned int fa0 = ksm[aoff + g - tg];
            unsigned int fa1 = ksm[aoff + 8 + g - tg];
            unsigned int fa2 = ksm[aoff + g - tg - 4];
            unsigned int fa3 = ksm[aoff + 8 + g - tg - 4];
            #pragma unroll
            for (int nt = 0; nt < 8; nt++) {
                unsigned int fb0 = usm[(nt * 8 + g) * 36 + kb + tg];
                unsigned int fb1 = usm[(nt * 8 + g) * 36 + kb + tg + 4];
                mma_tf32(c[nt][0], c[nt][1], c[nt][2], c[nt][3],
                         fa0, fa1, fa2, fa3, fb0, fb1);
            }
        }
    }
    __syncthreads();

    #pragma unroll
    for (int nt = 0; nt < 8; nt++) {
        int col = nt * 8 + 2 * tg;
        int row = 16 * w + g;
        osm[col * 129 + row]           = c[nt][0];
        osm[(col + 1) * 129 + row]     = c[nt][1];
        osm[col * 129 + row + 8]       = c[nt][2];
        osm[(col + 1) * 129 + row + 8] = c[nt][3];
    }
    __syncthreads();

    float Dh = Dv[h];
    if (path == 0) {
        for (int idx = tid; idx < 64 * 128; idx += 256) {
            int kk = idx >> 6, srow = idx & 63;
            int seq = s0 + srow, kout = ko0 + kk;
            if (seq < 1000 && kout < 250) {
                int b = seq / 250, s = seq - b * 250;
                float u = x[((b * 128 + h) * 250 + kout) * 250 + s];
                float v = osm[srow * 129 + kk] + Dh * u;
                osm[srow * 129 + kk] = gelu_f(v);
            }
        }
        __syncthreads();
        for (int idx = tid; idx < 64 * 128; idx += 256) {
            int srow = idx >> 7, k = idx & 127;
            int seq = s0 + srow, kout = ko0 + k;
            if (seq < 1000 && kout < 250)
                g_y[seq * SEQ_STRIDE + h * 250 + kout] =
                    __uint_as_float(f2tf32(osm[srow * 129 + k]));
        }
    } else {
        for (int idx = tid; idx < 64 * 128; idx += 256) {
            int srow = idx >> 7, k = idx & 127;
            int seq = s0 + srow, kout = ko0 + k;
            if (seq < 1000 && kout < 250) {
                int b = seq / 250, kq = seq - b * 250;
                float u = g_X1[b * PER_B + h * 62500 + kq * 250 + kout];
                float v = osm[srow * 129 + k] + Dh * u;
                g_y[seq * SEQ_STRIDE + h * 250 + kout] =
                    __uint_as_float(f2tf32(gelu_f(v)));
            }
        }
    }
}

// ------ FUSED: ow GEMM + GLU (smem) + lw GEMM + bias + GN stats, per seq -----
__global__ void fused_ow_lw(int path, const float* __restrict__ ob,
                            const float* __restrict__ lb)
{
    extern __shared__ unsigned int dynsm[];
    unsigned int* gsm  = dynsm;            // 32256 u32: [l][129]
    unsigned int* cbuf = dynsm + 32256;    // 2 x 8448 u32 per half
    __shared__ float rs[512], rs2[512];

    int seq  = blockIdx.x;
    int tid  = threadIdx.x;
    int w    = tid >> 5, lane = tid & 31;
    int half = tid >> 8;
    int lt   = tid & 255;
    int w8   = w & 7;
    int g = lane >> 2, tg = lane & 3;
    int yb = seq * SEQ_STRIDE;

    unsigned int* hbuf = cbuf + half * 8448;
    unsigned int hbase = (unsigned int)__cvta_generic_to_shared(hbuf);

    // ---------------- phase 1: z = ow@y+ob, GLU -> gsm ----------------
    for (int li = 0; li < 2; li++) {
        int l0 = li * 128 + half * 64;
        float c[2][8][4];
        #pragma unroll
        for (int m = 0; m < 2; m++)
            #pragma unroll
            for (int nt = 0; nt < 8; nt++)
                #pragma unroll
                for (int i = 0; i < 4; i++)
                    c[m][nt][i] = 0.f;

        __syncthreads();
        {
            #pragma unroll
            for (int j = 0; j < 4; j++) {
                int q = lt + 256 * j;
                int kk = q >> 5, pos = (q & 31) * 2;
                int lg = l0 + pos;
                int rem = 250 - lg;
                int bytes = (rem <= 0) ? 0 : (rem >= 2 ? 8 : 4);
                const float* src = (rem <= 0) ? g_y : &g_y[yb + kk * 250 + lg];
                cp_async8(hbase + (kk * 72 + pos) * 4, src, bytes);
            }
            cp_commit();
        }
        for (int kcid = 0; kcid < 4; kcid++) {
            cp_wait0();
            __syncthreads();
            if (kcid < 3) {
                int kcn = (kcid + 1) * 32;
                unsigned int dstb = hbase + (((kcid + 1) & 1) * 2304) * 4;
                #pragma unroll
                for (int j = 0; j < 4; j++) {
                    int q = lt + 256 * j;
                    int kk = q >> 5, pos = (q & 31) * 2;
                    int lg = l0 + pos;
                    int rem = 250 - lg;
                    int bytes = (rem <= 0) ? 0 : (rem >= 2 ? 8 : 4);
                    const float* src = (rem <= 0) ? g_y
                        : &g_y[yb + (kcn + kk) * 250 + lg];
                    cp_async8(dstb + (kk * 72 + pos) * 4, src, bytes);
                }
                cp_commit();
            }
            unsigned int* ybuf = hbuf + (kcid & 1) * 2304;
            int kc32 = kcid;
            #pragma unroll
            for (int ks = 0; ks < 4; ks++) {
                int kb = ks * 8;
                unsigned int fa0[2], fa1[2], fa2[2], fa3[2];
                #pragma unroll
                for (int m = 0; m < 2; m++) {
                    const uint4 Av = *(const uint4*)&g_owf[path * 32768 +
                        ((((kc32 * 8 + w8) * 4 + ks) * 2 + m) * 32 + lane) * 4];
                    fa0[m] = Av.x; fa1[m] = Av.y; fa2[m] = Av.z; fa3[m] = Av.w;
                }
                #pragma unroll
                for (int nt = 0; nt < 8; nt++) {
                    unsigned int fb0 = ybuf[(kb + tg) * 72 + nt * 8 + g];
                    unsigned int fb1 = ybuf[(kb + tg + 4) * 72 + nt * 8 + g];
                    #pragma unroll
                    for (int m = 0; m < 2; m++)
                        mma_tf32(c[m][nt][0], c[m][nt][1], c[m][nt][2], c[m][nt][3],
                                 fa0[m], fa1[m], fa2[m], fa3[m], fb0, fb1);
                }
            }
        }
        float ba0 = ob[16 * w8 + g],        ba8 = ob[16 * w8 + g + 8];
        float bb0 = ob[128 + 16 * w8 + g],  bb8 = ob[128 + 16 * w8 + g + 8];
        int rowA = 16 * w8 + g;
        #pragma unroll
        for (int nt = 0; nt < 8; nt++) {
            int col = nt * 8 + 2 * tg;
            if (l0 + col < 250) {
                float z1 = c[0][nt][0] + ba0, z2 = c[1][nt][0] + bb0;
                float z3 = c[0][nt][2] + ba8, z4 = c[1][nt][2] + bb8;
                gsm[(l0 + col) * 129 + rowA] =
                    f2tf32(__fdividef(z1, 1.f + __expf(-z2)));
                gsm[(l0 + col) * 129 + rowA + 8] =
                    f2tf32(__fdividef(z3, 1.f + __expf(-z4)));
            }
            if (l0 + col + 1 < 250) {
                float z1 = c[0][nt][1] + ba0, z2 = c[1][nt][1] + bb0;
                float z3 = c[0][nt][3] + ba8, z4 = c[1][nt][3] + bb8;
                gsm[(l0 + col + 1) * 129 + rowA] =
                    f2tf32(__fdividef(z1, 1.f + __expf(-z2)));
                gsm[(l0 + col + 1) * 129 + rowA + 8] =
                    f2tf32(__fdividef(z3, 1.f + __expf(-z4)));
            }
        }
    }
    __syncthreads();

    // ------------ phase 2: b2_flat = lw @ g_flat + lb, fused stats -----------
    float s_ = 0.f, ss_ = 0.f;
    for (int ri = 0; ri < 2; ri++) {
        int r0 = ri * 128 + half * 64;
        float c2[8][4];
        #pragma unroll
        for (int nt = 0; nt < 8; nt++)
            #pragma unroll
            for (int i = 0; i < 4; i++)
                c2[nt][i] = 0.f;

        for (int kc2 = 0; kc2 < 128; kc2 += 32) {
            __syncthreads();
            for (int idx = lt; idx < 64 * 32; idx += 256) {
                int r = idx >> 5, kk = idx & 31;
                int rg = r0 + r;
                unsigned int val = 0u;
                if (rg < 250) {
                    int o = rg * 128 + kc2 + kk;
                    int n = o / 250, l = o - n * 250;
                    val = gsm[l * 129 + n];
                }
                hbuf[r * 40 + kk] = val;
            }
            __syncthreads();
            int kc32 = kc2 >> 5;
            #pragma unroll
            for (int ks = 0; ks < 4; ks++) {
                int kb = ks * 8;
                const uint4 Av = *(const uint4*)&g_lwf[path * 16384 +
                    (((kc32 * 8 + w8) * 4 + ks) * 32 + lane) * 4];
                #pragma unroll
                for (int nt = 0; nt < 8; nt++) {
                    unsigned int fb0 = hbuf[(nt * 8 + g) * 40 + kb + tg];
                    unsigned int fb1 = hbuf[(nt * 8 + g) * 40 + kb + tg + 4];
                    mma_tf32(c2[nt][0], c2[nt][1], c2[nt][2], c2[nt][3],
                             Av.x, Av.y, Av.z, Av.w, fb0, fb1);
                }
            }
        }
        float* obuf = (float*)hbuf;
        float bv0 = lb[16 * w8 + g], bv8 = lb[16 * w8 + g + 8];
        int ocol = 16 * w8 + g;
        __syncthreads();
        #pragma unroll
        for (int nt = 0; nt < 8; nt++) {
            int trow = nt * 8 + 2 * tg;
            obuf[trow * 132 + ocol]           = c2[nt][0] + bv0;
            obuf[(trow + 1) * 132 + ocol]     = c2[nt][1] + bv0;
            obuf[trow * 132 + ocol + 8]       = c2[nt][2] + bv8;
            obuf[(trow + 1) * 132 + ocol + 8] = c2[nt][3] + bv8;
        }
        __syncthreads();
        for (int i4 = lt; i4 < 64 * 32; i4 += 256) {
            int r = i4 >> 5, c4 = i4 & 31;
            int rg = r0 + r;
            if (rg < 250) {
                float4 v = *(float4*)&obuf[r * 132 + c4 * 4];
                *(float4*)&g_b2[yb + rg * 128 + c4 * 4] = v;
                s_ += (v.x + v.y) + (v.z + v.w);
                ss_ = fmaf(v.x, v.x, ss_);
                ss_ = fmaf(v.y, v.y, ss_);
                ss_ = fmaf(v.z, v.z, ss_);
                ss_ = fmaf(v.w, v.w, ss_);
            }
        }
    }
    rs[tid] = s_; rs2[tid] = ss_;
    __syncthreads();
    for (int st = 256; st > 0; st >>= 1) {
        if (tid < st) { rs[tid] += rs[tid + st]; rs2[tid] += rs2[tid + st]; }
        __syncthreads();
    }
    if (tid == 0) {
        g_redl[seq * 2 + 0] = rs[0];
        g_redl[seq * 2 + 1] = rs2[0];
    }
}

// ------------- GroupNorm stats combine (deterministic) -----------------------
__global__ void red_combine()
{
    int b = blockIdx.x;
    int tid = threadIdx.x;
    float s = 0.f, ss = 0.f;
    for (int i = tid; i < 250; i += 256) {
        s  += g_redl[(b * 250 + i) * 2 + 0];
        ss += g_redl[(b * 250 + i) * 2 + 1];
    }
    __shared__ float sm[256], sm2[256];
    sm[tid] = s; sm2[tid] = ss;
    __syncthreads();
    for (int st = 128; st > 0; st >>= 1) {
        if (tid < st) { sm[tid] += sm[tid + st]; sm2[tid] += sm2[tid + st]; }
        __syncthreads();
    }
    if (tid == 0) {
        float inv = 1.f / (float)PER_B;
        float mu = sm[0] * inv;
        float var = sm2[0] * inv - mu * mu;
        g_stats[b * 2 + 0] = mu;
        g_stats[b * 2 + 1] = rsqrtf(var + 1e-8f);
    }
}

// -------- intra finalize: transpose b2 -> [B,N,K,S], GN, + x  -> g_X1 --------
__global__ void finalize_intra(const float* __restrict__ x,
                               const float* __restrict__ gg,
                               const float* __restrict__ gb)
{
    __shared__ float tile[32][33];
    int bh = blockIdx.x;
    int b = bh >> 7, n = bh & 127;
    int k0 = blockIdx.y * 32, s0 = blockIdx.z * 32;
    int tx = threadIdx.x, ty = threadIdx.y;
    float mu = g_stats[b * 2], istd = g_stats[b * 2 + 1];
    float ga = gg[n] * istd;
    float gbb = gb[n] - mu * ga;
    #pragma unroll
    for (int yy = 0; yy < 32; yy += 8) {
        int s = s0 + ty + yy, k = k0 + tx;
        if (s < 250 && k < 250)
            tile[ty + yy][tx] = g_b2[(b * 250 + s) * SEQ_STRIDE + n * 250 + k];
    }
    __syncthreads();
    #pragma unroll
    for (int yy = 0; yy < 32; yy += 8) {
        int k = k0 + ty + yy, s = s0 + tx;
        if (s < 250 && k < 250) {
            int xi = ((b * 128 + n) * 250 + k) * 250 + s;
            g_X1[xi] = tile[tx][ty + yy] * ga + gbb + x[xi];
        }
    }
}

// ------------- inter finalize: GN + residual (float2) ------------------------
__global__ void finalize_inter(const float* __restrict__ gg,
                               const float* __restrict__ gb,
                               float* __restrict__ out)
{
    int idx2 = blockIdx.x * 256 + threadIdx.x;
    if (idx2 < TOT / 2) {
        int idx = idx2 * 2;
        int b = idx / PER_B;
        int rem = idx - b * PER_B;
        int n = rem / 62500;
        int rem2 = rem - n * 62500;
        int k = rem2 / 250;
        int s = rem2 - k * 250;
        float2 v2 = *(const float2*)&g_b2[(b * 250 + k) * SEQ_STRIDE + n * 250 + s];
        float2 x1 = *(const float2*)&g_X1[idx];
        float mu = g_stats[b * 2], istd = g_stats[b * 2 + 1];
        float ga = gg[n] * istd;
        float gbb = gb[n] - mu * ga;
        float2 r;
        r.x = v2.x * ga + gbb + x1.x;
        r.y = v2.y * ga + gbb + x1.y;
        *(float2*)&out[idx] = r;
    }
}

extern "C" void kernel_launch(void* const* d_in, const int* in_sizes, int n_in,
                              void* d_out, int out_size)
{
    const float* x = (const float*)d_in[0];
    const float* P[2][12];
    for (int p = 0; p < 2; p++)
        for (int i = 0; i < 12; i++)
            P[p][i] = (const float*)d_in[1 + p * 12 + i];
    float* out = (float*)d_out;

    cudaFuncSetAttribute(fused_ow_lw,
                         cudaFuncAttributeMaxDynamicSharedMemorySize, FUSED_SMEM);

    prep_params<<<128, 32>>>(P[0][0], P[0][1], P[0][2], P[0][3], P[0][4], 0);
    prep_params<<<128, 32>>>(P[1][0], P[1][1], P[1][2], P[1][3], P[1][4], 1);
    kern_gen<<<128, 256>>>(0);
    kern_gen<<<128, 256>>>(1);
    pack_w<<<192, 256>>>(P[0][6], P[0][8], 0);
    pack_w<<<192, 256>>>(P[1][6], P[1][8], 1);

    // ---- intra path ----
    conv_gemm<<<dim3(128, 2, 16), 256>>>(0, x, P[0][5]);
    fused_ow_lw<<<NSEQ, 512, FUSED_SMEM>>>(0, P[0][7], P[0][9]);
    red_combine<<<4, 256>>>();
    finalize_intra<<<dim3(512, 8, 8), dim3(32, 8)>>>(x, P[0][10], P[0][11]);

    // ---- inter path ----
    conv_gemm<<<dim3(128, 2, 16), 256>>>(1, x, P[1][5]);
    fused_ow_lw<<<NSEQ, 512, FUSED_SMEM>>>(1, P[1][7], P[1][9]);
    red_combine<<<4, 256>>>();
    finalize_inter<<<62500, 256>>>(P[1][10], P[1][11], out);
}

// round 13
// speedup vs baseline: 1.8398x; 1.0098x over previous
#include <cuda_runtime.h>
#include <stdint.h>
#include <math.h>

// Problem constants
#define Bb 4
#define Nn 128
#define Kk 250
#define Ss 250
#define Mm 32
#define NSEQ 1000
#define LSEQ 250
#define SEQ_STRIDE 32000
#define TOT 32000000
#define PER_B 8000000
#define NM 4096

#define FUSED_SMEM 196608
#define CONV_SMEM 76800   // ksm 1536 | usm 9216 | ubuf 33024 | osm 33024

__device__ float g_y[TOT];                  // holds tf32-truncated bit patterns
__device__ float g_b2[TOT];
__device__ float g_X1[TOT];
__device__ float g_P[2 * 6 * NM];
__device__ float g_kern[2 * 128 * 384];
__device__ unsigned int g_owf[2 * 32768];
__device__ unsigned int g_lwf[2 * 16384];
__device__ float g_redl[1000 * 2];
__device__ float g_stats[Bb * 2];

__device__ __forceinline__ unsigned int f2tf32(float f)
{
    unsigned int u;
    asm("cvt.rna.tf32.f32 %0, %1;" : "=r"(u) : "f"(f));
    return u;
}

__device__ __forceinline__ float gelu_f(float v)
{
    float t = 0.7978845608028654f * fmaf(0.044715f * v, v * v, v);
    float tc = fminf(fmaxf(t, -15.f), 15.f);
    float et = __expf(2.f * tc);
    float th = __fdividef(et - 1.f, et + 1.f);
    return 0.5f * v * (1.f + th);
}

__device__ __forceinline__ void mma_tf32(float& c0, float& c1, float& c2, float& c3,
                                         unsigned int fa0, unsigned int fa1,
                                         unsigned int fa2, unsigned int fa3,
                                         unsigned int fb0, unsigned int fb1)
{
    asm volatile("mma.sync.aligned.m16n8k8.row.col.f32.tf32.tf32.f32 "
                 "{%0,%1,%2,%3}, {%4,%5,%6,%7}, {%8,%9}, {%0,%1,%2,%3};"
                 : "+f"(c0), "+f"(c1), "+f"(c2), "+f"(c3)
                 : "r"(fa0), "r"(fa1), "r"(fa2), "r"(fa3), "r"(fb0), "r"(fb1));
}

__device__ __forceinline__ void cp_async8(unsigned int dst_smem, const void* src,
                                          int src_bytes)
{
    asm volatile("cp.async.ca.shared.global [%0], [%1], 8, %2;"
                 :: "r"(dst_smem), "l"(src), "r"(src_bytes));
}
__device__ __forceinline__ void cp_commit()
{
    asm volatile("cp.async.commit_group;");
}
__device__ __forceinline__ void cp_wait0()
{
    asm volatile("cp.async.wait_group 0;");
}

// ---------------- parameter prep ---------------------------------------------
__global__ void prep_params(const float* __restrict__ log_dt,
                            const float* __restrict__ logA_re,
                            const float* __restrict__ A_im,
                            const float* __restrict__ C_re,
                            const float* __restrict__ C_im,
                            int path)
{
    int h = blockIdx.x;
    int m = threadIdx.x;
    float dt  = expf(log_dt[h]);
    float Are = -expf(logA_re[h * Mm + m]);
    float Aim = A_im[h * Mm + m];
    float dre = dt * Are, dim = dt * Aim;
    float e   = expf(dre);
    float vre = e * cosf(dim);
    float vim = e * sinf(dim);
    float nre = vre - 1.0f, nim = vim;
    float d2  = Are * Are + Aim * Aim;
    float qre = (nre * Are + nim * Aim) / d2;
    float qim = (nim * Are - nre * Aim) / d2;
    float cr  = C_re[h * Mm + m], ci = C_im[h * Mm + m];
    float c2r = 2.0f * (cr * qre - ci * qim);
    float c2i = 2.0f * (cr * qim + ci * qre);
    int base = path * 6 * NM + h * Mm + m;
    g_P[base + 0 * NM] = vre;
    g_P[base + 1 * NM] = vim;
    g_P[base + 2 * NM] = c2r;
    g_P[base + 3 * NM] = c2i;
    g_P[base + 4 * NM] = dre;
    g_P[base + 5 * NM] = dim;
}

// --------- kernel taps -------------------------------------------------------
__global__ void kern_gen(int path)
{
    int h = blockIdx.x;
    int tid = threadIdx.x;
    int w = tid >> 5, m = tid & 31;
    int base = path * 6 * NM + h * Mm + m;
    float ar  = g_P[base + 0 * NM];
    float ai  = g_P[base + 1 * NM];
    float c2r = g_P[base + 2 * NM];
    float c2i = g_P[base + 3 * NM];
    float dre = g_P[base + 4 * NM];
    float dim = g_P[base + 5 * NM];
    float l0 = (float)(w * 32);
    float e = expf(l0 * dre);
    float pr = e * cosf(l0 * dim);
    float pi = e * sinf(l0 * dim);
    float* kout = &g_kern[(path * 128 + h) * 384];
    if (tid < 128) kout[tid] = 0.f;
    if (tid < 6)   kout[378 + tid] = 0.f;
    for (int i = 0; i < 32; i++) {
        int l = w * 32 + i;
        float v = fmaf(c2r, pr, -c2i * pi);
        v += __shfl_xor_sync(0xffffffffu, v, 1);
        v += __shfl_xor_sync(0xffffffffu, v, 2);
        v += __shfl_xor_sync(0xffffffffu, v, 4);
        v += __shfl_xor_sync(0xffffffffu, v, 8);
        v += __shfl_xor_sync(0xffffffffu, v, 16);
        if (m == 0 && l < 250) kout[128 + l] = v;
        float t = pr;
        pr = fmaf(ar, t, -ai * pi);
        pi = fmaf(ai, t,  ar * pi);
    }
}

// --------- pack weights into per-fragment tf32 layout ------------------------
__global__ void pack_w(const float* __restrict__ ow, const float* __restrict__ lw,
                       int path)
{
    int idx = blockIdx.x * 256 + threadIdx.x;
    if (idx < 32768) {
        int j = idx & 3;
        int lane = (idx >> 2) & 31;
        int m = (idx >> 7) & 1;
        int ks = (idx >> 8) & 3;
        int w8 = (idx >> 10) & 7;
        int kc32 = (idx >> 13) & 3;
        int g = lane >> 2, tg = lane & 3;
        int row = m * 128 + 16 * w8 + g + ((j & 1) ? 8 : 0);
        int col = kc32 * 32 + ks * 8 + tg + ((j >> 1) ? 4 : 0);
        g_owf[path * 32768 + idx] = f2tf32(ow[row * 128 + col]);
    } else {
        int id2 = idx - 32768;
        int j = id2 & 3;
        int lane = (id2 >> 2) & 31;
        int ks = (id2 >> 7) & 3;
        int w8 = (id2 >> 9) & 7;
        int kc32 = (id2 >> 12) & 3;
        int g = lane >> 2, tg = lane & 3;
        int row = 16 * w8 + g + ((j & 1) ? 8 : 0);
        int col = kc32 * 32 + ks * 8 + tg + ((j >> 1) ? 4 : 0);
        g_lwf[path * 16384 + id2] = f2tf32(lw[row * 128 + col]);
    }
}

// ------- conv as causal Toeplitz GEMM; u retained in smem for epilogue -------
__global__ void conv_gemm(int path, const float* __restrict__ x,
                          const float* __restrict__ Dv)
{
    extern __shared__ char smr[];
    unsigned int* ksm = (unsigned int*)smr;             // 384 words
    unsigned int* usm = (unsigned int*)(smr + 1536);    // [64 seq][36]
    float*        ubuf = (float*)(smr + 10752);         // [64 seq][129] fp32 u
    float*        osm = (float*)(smr + 43776);          // [64 seq][129]

    int h   = blockIdx.x;
    int ko0 = blockIdx.y * 128;
    int s0  = blockIdx.z * 64;
    int tid = threadIdx.x;
    int w = tid >> 5, lane = tid & 31;
    int g = lane >> 2, tg = lane & 3;

    const float* kern = &g_kern[(path * 128 + h) * 384];
    for (int i = tid; i < 384; i += 256) ksm[i] = f2tf32(kern[i]);

    float c[8][4];
    #pragma unroll
    for (int nt = 0; nt < 8; nt++)
        #pragma unroll
        for (int i = 0; i < 4; i++)
            c[nt][i] = 0.f;

    int nch = (blockIdx.y == 0) ? 4 : 8;
    for (int ch = 0; ch < nch; ch++) {
        int ki0 = ch * 32;
        __syncthreads();
        if (path == 0) {
            for (int idx = tid; idx < 32 * 64; idx += 256) {
                int kk = idx >> 6, srow = idx & 63;
                int seq = s0 + srow, l = ki0 + kk;
                float v = 0.f;
                if (seq < 1000 && l < 250) {
                    int b = seq / 250, s = seq - b * 250;
                    v = x[((b * 128 + h) * 250 + l) * 250 + s];
                }
                usm[srow * 36 + kk] = f2tf32(v);
                int rel = l - ko0;
                if (rel >= 0 && rel < 128)
                    ubuf[srow * 129 + rel] = v;
            }
        } else {
            for (int idx = tid; idx < 64 * 32; idx += 256) {
                int srow = idx >> 5, kk = idx & 31;
                int seq = s0 + srow, l = ki0 + kk;
                float v = 0.f;
                if (seq < 1000 && l < 250) {
                    int b = seq / 250, kq = seq - b * 250;
                    v = g_X1[b * PER_B + h * 62500 + kq * 250 + l];
                }
                usm[srow * 36 + kk] = f2tf32(v);
                int rel = l - ko0;
                if (rel >= 0 && rel < 128)
                    ubuf[srow * 129 + rel] = v;
            }
        }
        __syncthreads();
        #pragma unroll
        for (int ks = 0; ks < 4; ks++) {
            int kb = ks * 8;
            int aoff = 128 + ko0 + 16 * w - ki0 - kb;
            unsigned int fa0 = ksm[aoff + g - tg];
            unsigned int fa1 = ksm[aoff + 8 + g - tg];
            unsigned int fa2 = ksm[aoff + g - tg - 4];
            unsigned int fa3 = ksm[aoff + 8 + g - tg - 4];
            #pragma unroll
            for (int nt = 0; nt < 8; nt++) {
                unsigned int fb0 = usm[(nt * 8 + g) * 36 + kb + tg];
                unsigned int fb1 = usm[(nt * 8 + g) * 36 + kb + tg + 4];
                mma_tf32(c[nt][0], c[nt][1], c[nt][2], c[nt][3],
                         fa0, fa1, fa2, fa3, fb0, fb1);
            }
        }
    }

    // epilogue: per-fragment D*u + GELU in-register (u from ubuf), stage to osm
    float Dh = Dv[h];
    #pragma unroll
    for (int nt = 0; nt < 8; nt++) {
        int col = nt * 8 + 2 * tg;         // seq local
        int row = 16 * w + g;              // kout local
        float u00 = ubuf[col * 129 + row];
        float u10 = ubuf[(col + 1) * 129 + row];
        float u08 = ubuf[col * 129 + row + 8];
        float u18 = ubuf[(col + 1) * 129 + row + 8];
        osm[col * 129 + row]           = gelu_f(fmaf(Dh, u00, c[nt][0]));
        osm[(col + 1) * 129 + row]     = gelu_f(fmaf(Dh, u10, c[nt][1]));
        osm[col * 129 + row + 8]       = gelu_f(fmaf(Dh, u08, c[nt][2]));
        osm[(col + 1) * 129 + row + 8] = gelu_f(fmaf(Dh, u18, c[nt][3]));
    }
    __syncthreads();

    // coalesced write along kout, tf32-truncated
    for (int idx = tid; idx < 64 * 128; idx += 256) {
        int srow = idx >> 7, k = idx & 127;
        int seq = s0 + srow, kout = ko0 + k;
        if (seq < 1000 && kout < 250)
            g_y[seq * SEQ_STRIDE + h * 250 + kout] =
                __uint_as_float(f2tf32(osm[srow * 129 + k]));
    }
}

// ------ FUSED: ow GEMM + GLU (smem) + lw GEMM + bias + GN stats, per seq -----
__global__ void fused_ow_lw(int path, const float* __restrict__ ob,
                            const float* __restrict__ lb)
{
    extern __shared__ unsigned int dynsm[];
    unsigned int* gsm  = dynsm;            // 32256 u32: [l][129]
    unsigned int* cbuf = dynsm + 32256;    // 2 x 8448 u32 per half
    __shared__ float rs[512], rs2[512];

    int seq  = blockIdx.x;
    int tid  = threadIdx.x;
    int w    = tid >> 5, lane = tid & 31;
    int half = tid >> 8;
    int lt   = tid & 255;
    int w8   = w & 7;
    int g = lane >> 2, tg = lane & 3;
    int yb = seq * SEQ_STRIDE;

    unsigned int* hbuf = cbuf + half * 8448;
    unsigned int hbase = (unsigned int)__cvta_generic_to_shared(hbuf);

    // ---------------- phase 1: z = ow@y+ob, GLU -> gsm ----------------
    for (int li = 0; li < 2; li++) {
        int l0 = li * 128 + half * 64;
        float c[2][8][4];
        #pragma unroll
        for (int m = 0; m < 2; m++)
            #pragma unroll
            for (int nt = 0; nt < 8; nt++)
                #pragma unroll
                for (int i = 0; i < 4; i++)
                    c[m][nt][i] = 0.f;

        __syncthreads();
        {
            #pragma unroll
            for (int j = 0; j < 4; j++) {
                int q = lt + 256 * j;
                int kk = q >> 5, pos = (q & 31) * 2;
                int lg = l0 + pos;
                int rem = 250 - lg;
                int bytes = (rem <= 0) ? 0 : (rem >= 2 ? 8 : 4);
                const float* src = (rem <= 0) ? g_y : &g_y[yb + kk * 250 + lg];
                cp_async8(hbase + (kk * 72 + pos) * 4, src, bytes);
            }
            cp_commit();
        }
        for (int kcid = 0; kcid < 4; kcid++) {
            cp_wait0();
            __syncthreads();
            if (kcid < 3) {
                int kcn = (kcid + 1) * 32;
                unsigned int dstb = hbase + (((kcid + 1) & 1) * 2304) * 4;
                #pragma unroll
                for (int j = 0; j < 4; j++) {
                    int q = lt + 256 * j;
                    int kk = q >> 5, pos = (q & 31) * 2;
                    int lg = l0 + pos;
                    int rem = 250 - lg;
                    int bytes = (rem <= 0) ? 0 : (rem >= 2 ? 8 : 4);
                    const float* src = (rem <= 0) ? g_y
                        : &g_y[yb + (kcn + kk) * 250 + lg];
                    cp_async8(dstb + (kk * 72 + pos) * 4, src, bytes);
                }
                cp_commit();
            }
            unsigned int* ybuf = hbuf + (kcid & 1) * 2304;
            int kc32 = kcid;
            #pragma unroll
            for (int ks = 0; ks < 4; ks++) {
                int kb = ks * 8;
                unsigned int fa0[2], fa1[2], fa2[2], fa3[2];
                #pragma unroll
                for (int m = 0; m < 2; m++) {
                    const uint4 Av = *(const uint4*)&g_owf[path * 32768 +
                        ((((kc32 * 8 + w8) * 4 + ks) * 2 + m) * 32 + lane) * 4];
                    fa0[m] = Av.x; fa1[m] = Av.y; fa2[m] = Av.z; fa3[m] = Av.w;
                }
                #pragma unroll
                for (int nt = 0; nt < 8; nt++) {
                    unsigned int fb0 = ybuf[(kb + tg) * 72 + nt * 8 + g];
                    unsigned int fb1 = ybuf[(kb + tg + 4) * 72 + nt * 8 + g];
                    #pragma unroll
                    for (int m = 0; m < 2; m++)
                        mma_tf32(c[m][nt][0], c[m][nt][1], c[m][nt][2], c[m][nt][3],
                                 fa0[m], fa1[m], fa2[m], fa3[m], fb0, fb1);
                }
            }
        }
        float ba0 = ob[16 * w8 + g],        ba8 = ob[16 * w8 + g + 8];
        float bb0 = ob[128 + 16 * w8 + g],  bb8 = ob[128 + 16 * w8 + g + 8];
        int rowA = 16 * w8 + g;
        #pragma unroll
        for (int nt = 0; nt < 8; nt++) {
            int col = nt * 8 + 2 * tg;
            if (l0 + col < 250) {
                float z1 = c[0][nt][0] + ba0, z2 = c[1][nt][0] + bb0;
                float z3 = c[0][nt][2] + ba8, z4 = c[1][nt][2] + bb8;
                gsm[(l0 + col) * 129 + rowA] =
                    f2tf32(__fdividef(z1, 1.f + __expf(-z2)));
                gsm[(l0 + col) * 129 + rowA + 8] =
                    f2tf32(__fdividef(z3, 1.f + __expf(-z4)));
            }
            if (l0 + col + 1 < 250) {
                float z1 = c[0][nt][1] + ba0, z2 = c[1][nt][1] + bb0;
                float z3 = c[0][nt][3] + ba8, z4 = c[1][nt][3] + bb8;
                gsm[(l0 + col + 1) * 129 + rowA] =
                    f2tf32(__fdividef(z1, 1.f + __expf(-z2)));
                gsm[(l0 + col + 1) * 129 + rowA + 8] =
                    f2tf32(__fdividef(z3, 1.f + __expf(-z4)));
            }
        }
    }
    __syncthreads();

    // ------------ phase 2: b2_flat = lw @ g_flat + lb, fused stats -----------
    float s_ = 0.f, ss_ = 0.f;
    for (int ri = 0; ri < 2; ri++) {
        int r0 = ri * 128 + half * 64;
        float c2[8][4];
        #pragma unroll
        for (int nt = 0; nt < 8; nt++)
            #pragma unroll
            for (int i = 0; i < 4; i++)
                c2[nt][i] = 0.f;

        for (int kc2 = 0; kc2 < 128; kc2 += 32) {
            __syncthreads();
            for (int idx = lt; idx < 64 * 32; idx += 256) {
                int r = idx >> 5, kk = idx & 31;
                int rg = r0 + r;
                unsigned int val = 0u;
                if (rg < 250) {
                    int o = rg * 128 + kc2 + kk;
                    int n = o / 250, l = o - n * 250;
                    val = gsm[l * 129 + n];
                }
                hbuf[r * 40 + kk] = val;
            }
            __syncthreads();
            int kc32 = kc2 >> 5;
            #pragma unroll
            for (int ks = 0; ks < 4; ks++) {
                int kb = ks * 8;
                const uint4 Av = *(const uint4*)&g_lwf[path * 16384 +
                    (((kc32 * 8 + w8) * 4 + ks) * 32 + lane) * 4];
                #pragma unroll
                for (int nt = 0; nt < 8; nt++) {
                    unsigned int fb0 = hbuf[(nt * 8 + g) * 40 + kb + tg];
                    unsigned int fb1 = hbuf[(nt * 8 + g) * 40 + kb + tg + 4];
                    mma_tf32(c2[nt][0], c2[nt][1], c2[nt][2], c2[nt][3],
                             Av.x, Av.y, Av.z, Av.w, fb0, fb1);
                }
            }
        }
        float* obuf = (float*)hbuf;
        float bv0 = lb[16 * w8 + g], bv8 = lb[16 * w8 + g + 8];
        int ocol = 16 * w8 + g;
        __syncthreads();
        #pragma unroll
        for (int nt = 0; nt < 8; nt++) {
            int trow = nt * 8 + 2 * tg;
            obuf[trow * 132 + ocol]           = c2[nt][0] + bv0;
            obuf[(trow + 1) * 132 + ocol]     = c2[nt][1] + bv0;
            obuf[trow * 132 + ocol + 8]       = c2[nt][2] + bv8;
            obuf[(trow + 1) * 132 + ocol + 8] = c2[nt][3] + bv8;
        }
        __syncthreads();
        for (int i4 = lt; i4 < 64 * 32; i4 += 256) {
            int r = i4 >> 5, c4 = i4 & 31;
            int rg = r0 + r;
            if (rg < 250) {
                float4 v = *(float4*)&obuf[r * 132 + c4 * 4];
                *(float4*)&g_b2[yb + rg * 128 + c4 * 4] = v;
                s_ += (v.x + v.y) + (v.z + v.w);
                ss_ = fmaf(v.x, v.x, ss_);
                ss_ = fmaf(v.y, v.y, ss_);
                ss_ = fmaf(v.z, v.z, ss_);
                ss_ = fmaf(v.w, v.w, ss_);
            }
        }
    }
    rs[tid] = s_; rs2[tid] = ss_;
    __syncthreads();
    for (int st = 256; st > 0; st >>= 1) {
        if (tid < st) { rs[tid] += rs[tid + st]; rs2[tid] += rs2[tid + st]; }
        __syncthreads();
    }
    if (tid == 0) {
        g_redl[seq * 2 + 0] = rs[0];
        g_redl[seq * 2 + 1] = rs2[0];
    }
}

// ------------- GroupNorm stats combine (deterministic) -----------------------
__global__ void red_combine()
{
    int b = blockIdx.x;
    int tid = threadIdx.x;
    float s = 0.f, ss = 0.f;
    for (int i = tid; i < 250; i += 256) {
        s  += g_redl[(b * 250 + i) * 2 + 0];
        ss += g_redl[(b * 250 + i) * 2 + 1];
    }
    __shared__ float sm[256], sm2[256];
    sm[tid] = s; sm2[tid] = ss;
    __syncthreads();
    for (int st = 128; st > 0; st >>= 1) {
        if (tid < st) { sm[tid] += sm[tid + st]; sm2[tid] += sm2[tid + st]; }
        __syncthreads();
    }
    if (tid == 0) {
        float inv = 1.f / (float)PER_B;
        float mu = sm[0] * inv;
        float var = sm2[0] * inv - mu * mu;
        g_stats[b * 2 + 0] = mu;
        g_stats[b * 2 + 1] = rsqrtf(var + 1e-8f);
    }
}

// -------- intra finalize: transpose b2 -> [B,N,K,S], GN, + x  -> g_X1 --------
__global__ void finalize_intra(const float* __restrict__ x,
                               const float* __restrict__ gg,
                               const float* __restrict__ gb)
{
    __shared__ float tile[32][33];
    int bh = blockIdx.x;
    int b = bh >> 7, n = bh & 127;
    int k0 = blockIdx.y * 32, s0 = blockIdx.z * 32;
    int tx = threadIdx.x, ty = threadIdx.y;
    float mu = g_stats[b * 2], istd = g_stats[b * 2 + 1];
    float ga = gg[n] * istd;
    float gbb = gb[n] - mu * ga;
    #pragma unroll
    for (int yy = 0; yy < 32; yy += 8) {
        int s = s0 + ty + yy, k = k0 + tx;
        if (s < 250 && k < 250)
            tile[ty + yy][tx] = g_b2[(b * 250 + s) * SEQ_STRIDE + n * 250 + k];
    }
    __syncthreads();
    #pragma unroll
    for (int yy = 0; yy < 32; yy += 8) {
        int k = k0 + ty + yy, s = s0 + tx;
        if (s < 250 && k < 250) {
            int xi = ((b * 128 + n) * 250 + k) * 250 + s;
            g_X1[xi] = tile[tx][ty + yy] * ga + gbb + x[xi];
        }
    }
}

// ------------- inter finalize: GN + residual (float2) ------------------------
__global__ void finalize_inter(const float* __restrict__ gg,
                               const float* __restrict__ gb,
                               float* __restrict__ out)
{
    int idx2 = blockIdx.x * 256 + threadIdx.x;
    if (idx2 < TOT / 2) {
        int idx = idx2 * 2;
        int b = idx / PER_B;
        int rem = idx - b * PER_B;
        int n = rem / 62500;
        int rem2 = rem - n * 62500;
        int k = rem2 / 250;
        int s = rem2 - k * 250;
        float2 v2 = *(const float2*)&g_b2[(b * 250 + k) * SEQ_STRIDE + n * 250 + s];
        float2 x1 = *(const float2*)&g_X1[idx];
        float mu = g_stats[b * 2], istd = g_stats[b * 2 + 1];
        float ga = gg[n] * istd;
        float gbb = gb[n] - mu * ga;
        float2 r;
        r.x = v2.x * ga + gbb + x1.x;
        r.y = v2.y * ga + gbb + x1.y;
        *(float2*)&out[idx] = r;
    }
}

extern "C" void kernel_launch(void* const* d_in, const int* in_sizes, int n_in,
                              void* d_out, int out_size)
{
    const float* x = (const float*)d_in[0];
    const float* P[2][12];
    for (int p = 0; p < 2; p++)
        for (int i = 0; i < 12; i++)
            P[p][i] = (const float*)d_in[1 + p * 12 + i];
    float* out = (float*)d_out;

    cudaFuncSetAttribute(fused_ow_lw,
                         cudaFuncAttributeMaxDynamicSharedMemorySize, FUSED_SMEM);
    cudaFuncSetAttribute(conv_gemm,
                         cudaFuncAttributeMaxDynamicSharedMemorySize, CONV_SMEM);

    prep_params<<<128, 32>>>(P[0][0], P[0][1], P[0][2], P[0][3], P[0][4], 0);
    prep_params<<<128, 32>>>(P[1][0], P[1][1], P[1][2], P[1][3], P[1][4], 1);
    kern_gen<<<128, 256>>>(0);
    kern_gen<<<128, 256>>>(1);
    pack_w<<<192, 256>>>(P[0][6], P[0][8], 0);
    pack_w<<<192, 256>>>(P[1][6], P[1][8], 1);

    // ---- intra path ----
    conv_gemm<<<dim3(128, 2, 16), 256, CONV_SMEM>>>(0, x, P[0][5]);
    fused_ow_lw<<<NSEQ, 512, FUSED_SMEM>>>(0, P[0][7], P[0][9]);
    red_combine<<<4, 256>>>();
    finalize_intra<<<dim3(512, 8, 8), dim3(32, 8)>>>(x, P[0][10], P[0][11]);

    // ---- inter path ----
    conv_gemm<<<dim3(128, 2, 16), 256, CONV_SMEM>>>(1, x, P[1][5]);
    fused_ow_lw<<<NSEQ, 512, FUSED_SMEM>>>(1, P[1][7], P[1][9]);
    red_combine<<<4, 256>>>();
    finalize_inter<<<62500, 256>>>(P[1][10], P[1][11], out);
}

// round 14
// speedup vs baseline: 1.8536x; 1.0075x over previous
#include <cuda_runtime.h>
#include <stdint.h>
#include <math.h>

// Problem constants
#define Bb 4
#define Nn 128
#define Kk 250
#define Ss 250
#define Mm 32
#define NSEQ 1000
#define LSEQ 250
#define SEQ_STRIDE 32000
#define TOT 32000000
#define PER_B 8000000
#define NM 4096

#define FUSED_SMEM 196608
#define CONV_SMEM 43776   // ksm 1536 | usm 9216 | ubuf(=osm, aliased) 33024

__device__ float g_y[TOT];                  // holds tf32-truncated bit patterns
__device__ float g_b2[TOT];
__device__ float g_X1[TOT];
__device__ float g_P[2 * 6 * NM];
__device__ float g_kern[2 * 128 * 384];
__device__ unsigned int g_owf[2 * 32768];
__device__ unsigned int g_lwf[2 * 16384];
__device__ float g_redl[1000 * 2];
__device__ float g_stats[Bb * 2];

__device__ __forceinline__ unsigned int f2tf32(float f)
{
    unsigned int u;
    asm("cvt.rna.tf32.f32 %0, %1;" : "=r"(u) : "f"(f));
    return u;
}

__device__ __forceinline__ float gelu_f(float v)
{
    float t = 0.7978845608028654f * fmaf(0.044715f * v, v * v, v);
    float tc = fminf(fmaxf(t, -15.f), 15.f);
    float et = __expf(2.f * tc);
    float th = __fdividef(et - 1.f, et + 1.f);
    return 0.5f * v * (1.f + th);
}

__device__ __forceinline__ void mma_tf32(float& c0, float& c1, float& c2, float& c3,
                                         unsigned int fa0, unsigned int fa1,
                                         unsigned int fa2, unsigned int fa3,
                                         unsigned int fb0, unsigned int fb1)
{
    asm volatile("mma.sync.aligned.m16n8k8.row.col.f32.tf32.tf32.f32 "
                 "{%0,%1,%2,%3}, {%4,%5,%6,%7}, {%8,%9}, {%0,%1,%2,%3};"
                 : "+f"(c0), "+f"(c1), "+f"(c2), "+f"(c3)
                 : "r"(fa0), "r"(fa1), "r"(fa2), "r"(fa3), "r"(fb0), "r"(fb1));
}

__device__ __forceinline__ void cp_async8(unsigned int dst_smem, const void* src,
                                          int src_bytes)
{
    asm volatile("cp.async.ca.shared.global [%0], [%1], 8, %2;"
                 :: "r"(dst_smem), "l"(src), "r"(src_bytes));
}
__device__ __forceinline__ void cp_commit()
{
    asm volatile("cp.async.commit_group;");
}
__device__ __forceinline__ void cp_wait0()
{
    asm volatile("cp.async.wait_group 0;");
}

// ---------------- parameter prep ---------------------------------------------
__global__ void prep_params(const float* __restrict__ log_dt,
                            const float* __restrict__ logA_re,
                            const float* __restrict__ A_im,
                            const float* __restrict__ C_re,
                            const float* __restrict__ C_im,
                            int path)
{
    int h = blockIdx.x;
    int m = threadIdx.x;
    float dt  = expf(log_dt[h]);
    float Are = -expf(logA_re[h * Mm + m]);
    float Aim = A_im[h * Mm + m];
    float dre = dt * Are, dim = dt * Aim;
    float e   = expf(dre);
    float vre = e * cosf(dim);
    float vim = e * sinf(dim);
    float nre = vre - 1.0f, nim = vim;
    float d2  = Are * Are + Aim * Aim;
    float qre = (nre * Are + nim * Aim) / d2;
    float qim = (nim * Are - nre * Aim) / d2;
    float cr  = C_re[h * Mm + m], ci = C_im[h * Mm + m];
    float c2r = 2.0f * (cr * qre - ci * qim);
    float c2i = 2.0f * (cr * qim + ci * qre);
    int base = path * 6 * NM + h * Mm + m;
    g_P[base + 0 * NM] = vre;
    g_P[base + 1 * NM] = vim;
    g_P[base + 2 * NM] = c2r;
    g_P[base + 3 * NM] = c2i;
    g_P[base + 4 * NM] = dre;
    g_P[base + 5 * NM] = dim;
}

// --------- kernel taps -------------------------------------------------------
__global__ void kern_gen(int path)
{
    int h = blockIdx.x;
    int tid = threadIdx.x;
    int w = tid >> 5, m = tid & 31;
    int base = path * 6 * NM + h * Mm + m;
    float ar  = g_P[base + 0 * NM];
    float ai  = g_P[base + 1 * NM];
    float c2r = g_P[base + 2 * NM];
    float c2i = g_P[base + 3 * NM];
    float dre = g_P[base + 4 * NM];
    float dim = g_P[base + 5 * NM];
    float l0 = (float)(w * 32);
    float e = expf(l0 * dre);
    float pr = e * cosf(l0 * dim);
    float pi = e * sinf(l0 * dim);
    float* kout = &g_kern[(path * 128 + h) * 384];
    if (tid < 128) kout[tid] = 0.f;
    if (tid < 6)   kout[378 + tid] = 0.f;
    for (int i = 0; i < 32; i++) {
        int l = w * 32 + i;
        float v = fmaf(c2r, pr, -c2i * pi);
        v += __shfl_xor_sync(0xffffffffu, v, 1);
        v += __shfl_xor_sync(0xffffffffu, v, 2);
        v += __shfl_xor_sync(0xffffffffu, v, 4);
        v += __shfl_xor_sync(0xffffffffu, v, 8);
        v += __shfl_xor_sync(0xffffffffu, v, 16);
        if (m == 0 && l < 250) kout[128 + l] = v;
        float t = pr;
        pr = fmaf(ar, t, -ai * pi);
        pi = fmaf(ai, t,  ar * pi);
    }
}

// --------- pack weights into per-fragment tf32 layout ------------------------
__global__ void pack_w(const float* __restrict__ ow, const float* __restrict__ lw,
                       int path)
{
    int idx = blockIdx.x * 256 + threadIdx.x;
    if (idx < 32768) {
        int j = idx & 3;
        int lane = (idx >> 2) & 31;
        int m = (idx >> 7) & 1;
        int ks = (idx >> 8) & 3;
        int w8 = (idx >> 10) & 7;
        int kc32 = (idx >> 13) & 3;
        int g = lane >> 2, tg = lane & 3;
        int row = m * 128 + 16 * w8 + g + ((j & 1) ? 8 : 0);
        int col = kc32 * 32 + ks * 8 + tg + ((j >> 1) ? 4 : 0);
        g_owf[path * 32768 + idx] = f2tf32(ow[row * 128 + col]);
    } else {
        int id2 = idx - 32768;
        int j = id2 & 3;
        int lane = (id2 >> 2) & 31;
        int ks = (id2 >> 7) & 3;
        int w8 = (id2 >> 9) & 7;
        int kc32 = (id2 >> 12) & 3;
        int g = lane >> 2, tg = lane & 3;
        int row = 16 * w8 + g + ((j & 1) ? 8 : 0);
        int col = kc32 * 32 + ks * 8 + tg + ((j >> 1) ? 4 : 0);
        g_lwf[path * 16384 + id2] = f2tf32(lw[row * 128 + col]);
    }
}

// ------- conv as causal Toeplitz GEMM; u retained in smem, in-place epilogue --
__global__ void conv_gemm(int path, const float* __restrict__ x,
                          const float* __restrict__ Dv)
{
    extern __shared__ char smr[];
    unsigned int* ksm = (unsigned int*)smr;             // 384 words
    unsigned int* usm = (unsigned int*)(smr + 1536);    // [64 seq][36]
    float*        ubuf = (float*)(smr + 10752);         // [64 seq][129] u -> y (in place)

    int h   = blockIdx.x;
    int ko0 = blockIdx.y * 128;
    int s0  = blockIdx.z * 64;
    int tid = threadIdx.x;
    int w = tid >> 5, lane = tid & 31;
    int g = lane >> 2, tg = lane & 3;

    const float* kern = &g_kern[(path * 128 + h) * 384];
    for (int i = tid; i < 384; i += 256) ksm[i] = f2tf32(kern[i]);

    float c[8][4];
    #pragma unroll
    for (int nt = 0; nt < 8; nt++)
        #pragma unroll
        for (int i = 0; i < 4; i++)
            c[nt][i] = 0.f;

    int nch = (blockIdx.y == 0) ? 4 : 8;
    for (int ch = 0; ch < nch; ch++) {
        int ki0 = ch * 32;
        __syncthreads();
        if (path == 0) {
            for (int idx = tid; idx < 32 * 64; idx += 256) {
                int kk = idx >> 6, srow = idx & 63;
                int seq = s0 + srow, l = ki0 + kk;
                float v = 0.f;
                if (seq < 1000 && l < 250) {
                    int b = seq / 250, s = seq - b * 250;
                    v = x[((b * 128 + h) * 250 + l) * 250 + s];
                }
                usm[srow * 36 + kk] = f2tf32(v);
                int rel = l - ko0;
                if (rel >= 0 && rel < 128)
                    ubuf[srow * 129 + rel] = v;
            }
        } else {
            for (int idx = tid; idx < 64 * 32; idx += 256) {
                int srow = idx >> 5, kk = idx & 31;
                int seq = s0 + srow, l = ki0 + kk;
                float v = 0.f;
                if (seq < 1000 && l < 250) {
                    int b = seq / 250, kq = seq - b * 250;
                    v = g_X1[b * PER_B + h * 62500 + kq * 250 + l];
                }
                usm[srow * 36 + kk] = f2tf32(v);
                int rel = l - ko0;
                if (rel >= 0 && rel < 128)
                    ubuf[srow * 129 + rel] = v;
            }
        }
        __syncthreads();
        #pragma unroll
        for (int ks = 0; ks < 4; ks++) {
            int kb = ks * 8;
            int aoff = 128 + ko0 + 16 * w - ki0 - kb;
            unsigned int fa0 = ksm[aoff + g - tg];
            unsigned int fa1 = ksm[aoff + 8 + g - tg];
            unsigned int fa2 = ksm[aoff + g - tg - 4];
            unsigned int fa3 = ksm[aoff + 8 + g - tg - 4];
            #pragma unroll
            for (int nt = 0; nt < 8; nt++) {
                unsigned int fb0 = usm[(nt * 8 + g) * 36 + kb + tg];
                unsigned int fb1 = usm[(nt * 8 + g) * 36 + kb + tg + 4];
                mma_tf32(c[nt][0], c[nt][1], c[nt][2], c[nt][3],
                         fa0, fa1, fa2, fa3, fb0, fb1);
            }
        }
    }
    __syncthreads();

    // epilogue IN PLACE: each fragment slot reads its own u and writes y back
    float Dh = Dv[h];
    #pragma unroll
    for (int nt = 0; nt < 8; nt++) {
        int col = nt * 8 + 2 * tg;         // seq local
        int row = 16 * w + g;              // kout local
        float u00 = ubuf[col * 129 + row];
        float u10 = ubuf[(col + 1) * 129 + row];
        float u08 = ubuf[col * 129 + row + 8];
        float u18 = ubuf[(col + 1) * 129 + row + 8];
        ubuf[col * 129 + row]           = gelu_f(fmaf(Dh, u00, c[nt][0]));
        ubuf[(col + 1) * 129 + row]     = gelu_f(fmaf(Dh, u10, c[nt][1]));
        ubuf[col * 129 + row + 8]       = gelu_f(fmaf(Dh, u08, c[nt][2]));
        ubuf[(col + 1) * 129 + row + 8] = gelu_f(fmaf(Dh, u18, c[nt][3]));
    }
    __syncthreads();

    // coalesced write along kout, tf32-truncated
    for (int idx = tid; idx < 64 * 128; idx += 256) {
        int srow = idx >> 7, k = idx & 127;
        int seq = s0 + srow, kout = ko0 + k;
        if (seq < 1000 && kout < 250)
            g_y[seq * SEQ_STRIDE + h * 250 + kout] =
                __uint_as_float(f2tf32(ubuf[srow * 129 + k]));
    }
}

// ------ FUSED: ow GEMM + GLU (smem) + lw GEMM + bias + GN stats, per seq -----
__global__ void fused_ow_lw(int path, const float* __restrict__ ob,
                            const float* __restrict__ lb)
{
    extern __shared__ unsigned int dynsm[];
    unsigned int* gsm  = dynsm;            // 32256 u32: [l][129]
    unsigned int* cbuf = dynsm + 32256;    // 2 x 8448 u32 per half
    __shared__ float rs[512], rs2[512];

    int seq  = blockIdx.x;
    int tid  = threadIdx.x;
    int w    = tid >> 5, lane = tid & 31;
    int half = tid >> 8;
    int lt   = tid & 255;
    int w8   = w & 7;
    int g = lane >> 2, tg = lane & 3;
    int yb = seq * SEQ_STRIDE;

    unsigned int* hbuf = cbuf + half * 8448;
    unsigned int hbase = (unsigned int)__cvta_generic_to_shared(hbuf);

    // ---------------- phase 1: z = ow@y+ob, GLU -> gsm ----------------
    for (int li = 0; li < 2; li++) {
        int l0 = li * 128 + half * 64;
        float c[2][8][4];
        #pragma unroll
        for (int m = 0; m < 2; m++)
            #pragma unroll
            for (int nt = 0; nt < 8; nt++)
                #pragma unroll
                for (int i = 0; i < 4; i++)
                    c[m][nt][i] = 0.f;

        __syncthreads();
        {
            #pragma unroll
            for (int j = 0; j < 4; j++) {
                int q = lt + 256 * j;
                int kk = q >> 5, pos = (q & 31) * 2;
                int lg = l0 + pos;
                int rem = 250 - lg;
                int bytes = (rem <= 0) ? 0 : (rem >= 2 ? 8 : 4);
                const float* src = (rem <= 0) ? g_y : &g_y[yb + kk * 250 + lg];
                cp_async8(hbase + (kk * 72 + pos) * 4, src, bytes);
            }
            cp_commit();
        }
        for (int kcid = 0; kcid < 4; kcid++) {
            cp_wait0();
            __syncthreads();
            if (kcid < 3) {
                int kcn = (kcid + 1) * 32;
                unsigned int dstb = hbase + (((kcid + 1) & 1) * 2304) * 4;
                #pragma unroll
                for (int j = 0; j < 4; j++) {
                    int q = lt + 256 * j;
                    int kk = q >> 5, pos = (q & 31) * 2;
                    int lg = l0 + pos;
                    int rem = 250 - lg;
                    int bytes = (rem <= 0) ? 0 : (rem >= 2 ? 8 : 4);
                    const float* src = (rem <= 0) ? g_y
                        : &g_y[yb + (kcn + kk) * 250 + lg];
                    cp_async8(dstb + (kk * 72 + pos) * 4, src, bytes);
                }
                cp_commit();
            }
            unsigned int* ybuf = hbuf + (kcid & 1) * 2304;
            int kc32 = kcid;
            #pragma unroll
            for (int ks = 0; ks < 4; ks++) {
                int kb = ks * 8;
                unsigned int fa0[2], fa1[2], fa2[2], fa3[2];
                #pragma unroll
                for (int m = 0; m < 2; m++) {
                    const uint4 Av = *(const uint4*)&g_owf[path * 32768 +
                        ((((kc32 * 8 + w8) * 4 + ks) * 2 + m) * 32 + lane) * 4];
                    fa0[m] = Av.x; fa1[m] = Av.y; fa2[m] = Av.z; fa3[m] = Av.w;
                }
                #pragma unroll
                for (int nt = 0; nt < 8; nt++) {
                    unsigned int fb0 = ybuf[(kb + tg) * 72 + nt * 8 + g];
                    unsigned int fb1 = ybuf[(kb + tg + 4) * 72 + nt * 8 + g];
                    #pragma unroll
                    for (int m = 0; m < 2; m++)
                        mma_tf32(c[m][nt][0], c[m][nt][1], c[m][nt][2], c[m][nt][3],
                                 fa0[m], fa1[m], fa2[m], fa3[m], fb0, fb1);
                }
            }
        }
        float ba0 = ob[16 * w8 + g],        ba8 = ob[16 * w8 + g + 8];
        float bb0 = ob[128 + 16 * w8 + g],  bb8 = ob[128 + 16 * w8 + g + 8];
        int rowA = 16 * w8 + g;
        #pragma unroll
        for (int nt = 0; nt < 8; nt++) {
            int col = nt * 8 + 2 * tg;
            if (l0 + col < 250) {
                float z1 = c[0][nt][0] + ba0, z2 = c[1][nt][0] + bb0;
                float z3 = c[0][nt][2] + ba8, z4 = c[1][nt][2] + bb8;
                gsm[(l0 + col) * 129 + rowA] =
                    f2tf32(__fdividef(z1, 1.f + __expf(-z2)));
                gsm[(l0 + col) * 129 + rowA + 8] =
                    f2tf32(__fdividef(z3, 1.f + __expf(-z4)));
            }
            if (l0 + col + 1 < 250) {
                float z1 = c[0][nt][1] + ba0, z2 = c[1][nt][1] + bb0;
                float z3 = c[0][nt][3] + ba8, z4 = c[1][nt][3] + bb8;
                gsm[(l0 + col + 1) * 129 + rowA] =
                    f2tf32(__fdividef(z1, 1.f + __expf(-z2)));
                gsm[(l0 + col + 1) * 129 + rowA + 8] =
                    f2tf32(__fdividef(z3, 1.f + __expf(-z4)));
            }
        }
    }
    __syncthreads();

    // ------------ phase 2: b2_flat = lw @ g_flat + lb, fused stats -----------
    float s_ = 0.f, ss_ = 0.f;
    for (int ri = 0; ri < 2; ri++) {
        int r0 = ri * 128 + half * 64;
        float c2[8][4];
        #pragma unroll
        for (int nt = 0; nt < 8; nt++)
            #pragma unroll
            for (int i = 0; i < 4; i++)
                c2[nt][i] = 0.f;

        for (int kc2 = 0; kc2 < 128; kc2 += 32) {
            __syncthreads();
            for (int idx = lt; idx < 64 * 32; idx += 256) {
                int r = idx >> 5, kk = idx & 31;
                int rg = r0 + r;
                unsigned int val = 0u;
                if (rg < 250) {
                    int o = rg * 128 + kc2 + kk;
                    int n = o / 250, l = o - n * 250;
                    val = gsm[l * 129 + n];
                }
                hbuf[r * 40 + kk] = val;
            }
            __syncthreads();
            int kc32 = kc2 >> 5;
            #pragma unroll
            for (int ks = 0; ks < 4; ks++) {
                int kb = ks * 8;
                const uint4 Av = *(const uint4*)&g_lwf[path * 16384 +
                    (((kc32 * 8 + w8) * 4 + ks) * 32 + lane) * 4];
                #pragma unroll
                for (int nt = 0; nt < 8; nt++) {
                    unsigned int fb0 = hbuf[(nt * 8 + g) * 40 + kb + tg];
                    unsigned int fb1 = hbuf[(nt * 8 + g) * 40 + kb + tg + 4];
                    mma_tf32(c2[nt][0], c2[nt][1], c2[nt][2], c2[nt][3],
                             Av.x, Av.y, Av.z, Av.w, fb0, fb1);
                }
            }
        }
        float* obuf = (float*)hbuf;
        float bv0 = lb[16 * w8 + g], bv8 = lb[16 * w8 + g + 8];
        int ocol = 16 * w8 + g;
        __syncthreads();
        #pragma unroll
        for (int nt = 0; nt < 8; nt++) {
            int trow = nt * 8 + 2 * tg;
            obuf[trow * 132 + ocol]           = c2[nt][0] + bv0;
            obuf[(trow + 1) * 132 + ocol]     = c2[nt][1] + bv0;
            obuf[trow * 132 + ocol + 8]       = c2[nt][2] + bv8;
            obuf[(trow + 1) * 132 + ocol + 8] = c2[nt][3] + bv8;
        }
        __syncthreads();
        for (int i4 = lt; i4 < 64 * 32; i4 += 256) {
            int r = i4 >> 5, c4 = i4 & 31;
            int rg = r0 + r;
            if (rg < 250) {
                float4 v = *(float4*)&obuf[r * 132 + c4 * 4];
                *(float4*)&g_b2[yb + rg * 128 + c4 * 4] = v;
                s_ += (v.x + v.y) + (v.z + v.w);
                ss_ = fmaf(v.x, v.x, ss_);
                ss_ = fmaf(v.y, v.y, ss_);
                ss_ = fmaf(v.z, v.z, ss_);
                ss_ = fmaf(v.w, v.w, ss_);
            }
        }
    }
    rs[tid] = s_; rs2[tid] = ss_;
    __syncthreads();
    for (int st = 256; st > 0; st >>= 1) {
        if (tid < st) { rs[tid] += rs[tid + st]; rs2[tid] += rs2[tid + st]; }
        __syncthreads();
    }
    if (tid == 0) {
        g_redl[seq * 2 + 0] = rs[0];
        g_redl[seq * 2 + 1] = rs2[0];
    }
}

// ------------- GroupNorm stats combine (deterministic) -----------------------
__global__ void red_combine()
{
    int b = blockIdx.x;
    int tid = threadIdx.x;
    float s = 0.f, ss = 0.f;
    for (int i = tid; i < 250; i += 256) {
        s  += g_redl[(b * 250 + i) * 2 + 0];
        ss += g_redl[(b * 250 + i) * 2 + 1];
    }
    __shared__ float sm[256], sm2[256];
    sm[tid] = s; sm2[tid] = ss;
    __syncthreads();
    for (int st = 128; st > 0; st >>= 1) {
        if (tid < st) { sm[tid] += sm[tid + st]; sm2[tid] += sm2[tid + st]; }
        __syncthreads();
    }
    if (tid == 0) {
        float inv = 1.f / (float)PER_B;
        float mu = sm[0] * inv;
        float var = sm2[0] * inv - mu * mu;
        g_stats[b * 2 + 0] = mu;
        g_stats[b * 2 + 1] = rsqrtf(var + 1e-8f);
    }
}

// -------- intra finalize (float2): transpose b2 -> [B,N,K,S], GN, + x --------
// block (16,16); tile 32 (s) x 32 (k)
__global__ void finalize_intra(const float* __restrict__ x,
                               const float* __restrict__ gg,
                               const float* __restrict__ gb)
{
    __shared__ float tile[32][33];
    int bh = blockIdx.x;
    int b = bh >> 7, n = bh & 127;
    int k0 = blockIdx.y * 32, s0 = blockIdx.z * 32;
    int tx = threadIdx.x, ty = threadIdx.y;
    float mu = g_stats[b * 2], istd = g_stats[b * 2 + 1];
    float ga = gg[n] * istd;
    float gbb = gb[n] - mu * ga;

    // load: tile[s_local][k_local], float2 along k
    #pragma unroll
    for (int i = 0; i < 2; i++) {
        int s = s0 + ty + 16 * i;
        int k = k0 + 2 * tx;
        if (s < 250 && k < 250) {
            float2 v = *(const float2*)&g_b2[(b * 250 + s) * SEQ_STRIDE + n * 250 + k];
            tile[ty + 16 * i][2 * tx]     = v.x;
            tile[ty + 16 * i][2 * tx + 1] = v.y;
        }
    }
    __syncthreads();
    // store: X1[...][k][s], float2 along s
    #pragma unroll
    for (int i = 0; i < 2; i++) {
        int k = k0 + ty + 16 * i;
        int s = s0 + 2 * tx;
        if (s < 250 && k < 250) {
            int xi = ((b * 128 + n) * 250 + k) * 250 + s;
            float2 xv = *(const float2*)&x[xi];
            float2 r;
            r.x = tile[2 * tx][ty + 16 * i] * ga + gbb + xv.x;
            r.y = tile[2 * tx + 1][ty + 16 * i] * ga + gbb + xv.y;
            *(float2*)&g_X1[xi] = r;
        }
    }
}

// ------------- inter finalize: GN + residual (float2) ------------------------
__global__ void finalize_inter(const float* __restrict__ gg,
                               const float* __restrict__ gb,
                               float* __restrict__ out)
{
    int idx2 = blockIdx.x * 256 + threadIdx.x;
    if (idx2 < TOT / 2) {
        int idx = idx2 * 2;
        int b = idx / PER_B;
        int rem = idx - b * PER_B;
        int n = rem / 62500;
        int rem2 = rem - n * 62500;
        int k = rem2 / 250;
        int s = rem2 - k * 250;
        float2 v2 = *(const float2*)&g_b2[(b * 250 + k) * SEQ_STRIDE + n * 250 + s];
        float2 x1 = *(const float2*)&g_X1[idx];
        float mu = g_stats[b * 2], istd = g_stats[b * 2 + 1];
        float ga = gg[n] * istd;
        float gbb = gb[n] - mu * ga;
        float2 r;
        r.x = v2.x * ga + gbb + x1.x;
        r.y = v2.y * ga + gbb + x1.y;
        *(float2*)&out[idx] = r;
    }
}

extern "C" void kernel_launch(void* const* d_in, const int* in_sizes, int n_in,
                              void* d_out, int out_size)
{
    const float* x = (const float*)d_in[0];
    const float* P[2][12];
    for (int p = 0; p < 2; p++)
        for (int i = 0; i < 12; i++)
            P[p][i] = (const float*)d_in[1 + p * 12 + i];
    float* out = (float*)d_out;

    cudaFuncSetAttribute(fused_ow_lw,
                         cudaFuncAttributeMaxDynamicSharedMemorySize, FUSED_SMEM);
    cudaFuncSetAttribute(conv_gemm,
                         cudaFuncAttributeMaxDynamicSharedMemorySize, CONV_SMEM);

    prep_params<<<128, 32>>>(P[0][0], P[0][1], P[0][2], P[0][3], P[0][4], 0);
    prep_params<<<128, 32>>>(P[1][0], P[1][1], P[1][2], P[1][3], P[1][4], 1);
    kern_gen<<<128, 256>>>(0);
    kern_gen<<<128, 256>>>(1);
    pack_w<<<192, 256>>>(P[0][6], P[0][8], 0);
    pack_w<<<192, 256>>>(P[1][6], P[1][8], 1);

    // ---- intra path ----
    conv_gemm<<<dim3(128, 2, 16), 256, CONV_SMEM>>>(0, x, P[0][5]);
    fused_ow_lw<<<NSEQ, 512, FUSED_SMEM>>>(0, P[0][7], P[0][9]);
    red_combine<<<4, 256>>>();
    finalize_intra<<<dim3(512, 8, 8), dim3(16, 16)>>>(x, P[0][10], P[0][11]);

    // ---- inter path ----
    conv_gemm<<<dim3(128, 2, 16), 256, CONV_SMEM>>>(1, x, P[1][5]);
    fused_ow_lw<<<NSEQ, 512, FUSED_SMEM>>>(1, P[1][7], P[1][9]);
    red_combine<<<4, 256>>>();
    finalize_inter<<<62500, 256>>>(P[1][10], P[1][11], out);
}

// round 15
// speedup vs baseline: 2.1883x; 1.1806x over previous
#include <cuda_runtime.h>
#include <stdint.h>
#include <math.h>

// Problem constants
#define Bb 4
#define Nn 128
#define Kk 250
#define Ss 250
#define Mm 32
#define NSEQ 1000
#define LSEQ 250
#define SEQ_STRIDE 32000
#define TOT 32000000
#define PER_B 8000000

#define FUSED_SMEM 196608
#define CONV_SMEM 68096   // ksm 1536 | usm 64*260*4 = 66560

__device__ float g_y[TOT];                  // holds tf32-truncated bit patterns
__device__ float g_b2[TOT];
__device__ float g_X1[TOT];
__device__ float g_kern[2 * 128 * 384];     // [path][h][128 pad + 250 taps + 6 pad]
__device__ unsigned int g_owf[2 * 32768];
__device__ unsigned int g_lwf[2 * 16384];
__device__ float g_redl[1000 * 2];
__device__ float g_stats[Bb * 2];

__device__ __forceinline__ unsigned int f2tf32(float f)
{
    unsigned int u;
    asm("cvt.rna.tf32.f32 %0, %1;" : "=r"(u) : "f"(f));
    return u;
}

__device__ __forceinline__ float gelu_f(float v)
{
    float t = 0.7978845608028654f * fmaf(0.044715f * v, v * v, v);
    float tc = fminf(fmaxf(t, -15.f), 15.f);
    float et = __expf(2.f * tc);
    float th = __fdividef(et - 1.f, et + 1.f);
    return 0.5f * v * (1.f + th);
}

__device__ __forceinline__ void mma_tf32(float& c0, float& c1, float& c2, float& c3,
                                         unsigned int fa0, unsigned int fa1,
                                         unsigned int fa2, unsigned int fa3,
                                         unsigned int fb0, unsigned int fb1)
{
    asm volatile("mma.sync.aligned.m16n8k8.row.col.f32.tf32.tf32.f32 "
                 "{%0,%1,%2,%3}, {%4,%5,%6,%7}, {%8,%9}, {%0,%1,%2,%3};"
                 : "+f"(c0), "+f"(c1), "+f"(c2), "+f"(c3)
                 : "r"(fa0), "r"(fa1), "r"(fa2), "r"(fa3), "r"(fb0), "r"(fb1));
}

__device__ __forceinline__ void cp_async8(unsigned int dst_smem, const void* src,
                                          int src_bytes)
{
    asm volatile("cp.async.ca.shared.global [%0], [%1], 8, %2;"
                 :: "r"(dst_smem), "l"(src), "r"(src_bytes));
}
__device__ __forceinline__ void cp_commit()
{
    asm volatile("cp.async.commit_group;");
}
__device__ __forceinline__ void cp_wait0()
{
    asm volatile("cp.async.wait_group 0;");
}

// --------- kern_gen with fused param prep (no g_P round trip) ----------------
__global__ void kern_gen(const float* __restrict__ log_dt,
                         const float* __restrict__ logA_re,
                         const float* __restrict__ A_im,
                         const float* __restrict__ C_re,
                         const float* __restrict__ C_im,
                         int path)
{
    int h = blockIdx.x;
    int tid = threadIdx.x;
    int w = tid >> 5, m = tid & 31;

    // per-thread param computation (redundant across warps; trivial cost)
    float dt  = expf(log_dt[h]);
    float Are = -expf(logA_re[h * Mm + m]);
    float Aim = A_im[h * Mm + m];
    float dre = dt * Are, dim = dt * Aim;
    float e0  = expf(dre);
    float ar  = e0 * cosf(dim);
    float ai  = e0 * sinf(dim);
    float nre = ar - 1.0f, nim = ai;
    float d2  = Are * Are + Aim * Aim;
    float qre = (nre * Are + nim * Aim) / d2;
    float qim = (nim * Are - nre * Aim) / d2;
    float cr  = C_re[h * Mm + m], ci = C_im[h * Mm + m];
    float c2r = 2.0f * (cr * qre - ci * qim);
    float c2i = 2.0f * (cr * qim + ci * qre);

    float l0 = (float)(w * 32);
    float e = expf(l0 * dre);
    float pr = e * cosf(l0 * dim);
    float pi = e * sinf(l0 * dim);
    float* kout = &g_kern[(path * 128 + h) * 384];
    if (tid < 128) kout[tid] = 0.f;
    if (tid < 6)   kout[378 + tid] = 0.f;
    for (int i = 0; i < 32; i++) {
        int l = w * 32 + i;
        float v = fmaf(c2r, pr, -c2i * pi);
        v += __shfl_xor_sync(0xffffffffu, v, 1);
        v += __shfl_xor_sync(0xffffffffu, v, 2);
        v += __shfl_xor_sync(0xffffffffu, v, 4);
        v += __shfl_xor_sync(0xffffffffu, v, 8);
        v += __shfl_xor_sync(0xffffffffu, v, 16);
        if (m == 0 && l < 250) kout[128 + l] = v;
        float t = pr;
        pr = fmaf(ar, t, -ai * pi);
        pi = fmaf(ai, t,  ar * pi);
    }
}

// --------- pack weights (both paths, one launch) -----------------------------
__global__ void pack_w(const float* __restrict__ ow0, const float* __restrict__ lw0,
                       const float* __restrict__ ow1, const float* __restrict__ lw1)
{
    int gidx = blockIdx.x * 256 + threadIdx.x;
    int path = gidx >= 49152;
    int idx  = gidx - path * 49152;
    const float* ow = path ? ow1 : ow0;
    const float* lw = path ? lw1 : lw0;
    if (idx < 32768) {
        int j = idx & 3;
        int lane = (idx >> 2) & 31;
        int m = (idx >> 7) & 1;
        int ks = (idx >> 8) & 3;
        int w8 = (idx >> 10) & 7;
        int kc32 = (idx >> 13) & 3;
        int g = lane >> 2, tg = lane & 3;
        int row = m * 128 + 16 * w8 + g + ((j & 1) ? 8 : 0);
        int col = kc32 * 32 + ks * 8 + tg + ((j >> 1) ? 4 : 0);
        g_owf[path * 32768 + idx] = f2tf32(ow[row * 128 + col]);
    } else {
        int id2 = idx - 32768;
        int j = id2 & 3;
        int lane = (id2 >> 2) & 31;
        int ks = (id2 >> 7) & 3;
        int w8 = (id2 >> 9) & 7;
        int kc32 = (id2 >> 12) & 3;
        int g = lane >> 2, tg = lane & 3;
        int row = 16 * w8 + g + ((j & 1) ? 8 : 0);
        int col = kc32 * 32 + ks * 8 + tg + ((j >> 1) ? 4 : 0);
        g_lwf[path * 16384 + id2] = f2tf32(lw[row * 128 + col]);
    }
}

// ------- conv: one-shot resident u, sequential kout halves -------------------
// grid (h, 16 seq-tiles), 256 thr. usm [64 seq][260] tf32 (slots >=250 zero).
__global__ void __launch_bounds__(256, 3)
conv_gemm(int path, const float* __restrict__ x, const float* __restrict__ Dv)
{
    extern __shared__ char smr[];
    unsigned int* ksm = (unsigned int*)smr;             // 384 words
    unsigned int* usm = (unsigned int*)(smr + 1536);    // [64][260]

    int h   = blockIdx.x;
    int s0  = blockIdx.y * 64;
    int tid = threadIdx.x;
    int w = tid >> 5, lane = tid & 31;
    int g = lane >> 2, tg = lane & 3;

    const float* kern = &g_kern[(path * 128 + h) * 384];
    for (int i = tid; i < 384; i += 256) ksm[i] = f2tf32(kern[i]);

    // ---- stage all u once (tf32 bits; l>=250 zero) ----
    if (path == 0) {
        // x[b][h][l][s]: coalesced along s (srow), transposed store
        for (int idx = tid; idx < 256 * 64; idx += 256) {
            int kk = idx >> 6, srow = idx & 63;
            int seq = s0 + srow;
            float v = 0.f;
            if (seq < 1000 && kk < 250) {
                int b = seq / 250, s = seq - b * 250;
                v = x[((b * 128 + h) * 250 + kk) * 250 + s];
            }
            usm[srow * 260 + kk] = f2tf32(v);
        }
    } else {
        // g_X1[b][h][kq][l]: coalesced along l (kk)
        for (int idx = tid; idx < 64 * 256; idx += 256) {
            int srow = idx >> 8, kk = idx & 255;
            int seq = s0 + srow;
            float v = 0.f;
            if (seq < 1000 && kk < 250) {
                int b = seq / 250, kq = seq - b * 250;
                v = g_X1[b * PER_B + h * 62500 + kq * 250 + kk];
            }
            usm[srow * 260 + kk] = f2tf32(v);
        }
    }
    __syncthreads();

    float Dh = Dv[h];

    // mh=1 first (uses l 0..249), then mh=0 (uses l 0..127, untouched by mh=1 epi)
    for (int mh = 1; mh >= 0; mh--) {
        float c[8][4];
        #pragma unroll
        for (int nt = 0; nt < 8; nt++)
            #pragma unroll
            for (int i = 0; i < 4; i++)
                c[nt][i] = 0.f;

        int nch = mh ? 8 : 4;
        for (int ch = 0; ch < nch; ch++) {
            int ki0 = ch * 32;
            #pragma unroll
            for (int ks = 0; ks < 4; ks++) {
                int kb = ks * 8;
                int aoff = 128 + mh * 128 + 16 * w - ki0 - kb;
                unsigned int fa0 = ksm[aoff + g - tg];
                unsigned int fa1 = ksm[aoff + 8 + g - tg];
                unsigned int fa2 = ksm[aoff + g - tg - 4];
                unsigned int fa3 = ksm[aoff + 8 + g - tg - 4];
                #pragma unroll
                for (int nt = 0; nt < 8; nt++) {
                    unsigned int fb0 = usm[(nt * 8 + g) * 260 + ki0 + kb + tg];
                    unsigned int fb1 = usm[(nt * 8 + g) * 260 + ki0 + kb + tg + 4];
                    mma_tf32(c[nt][0], c[nt][1], c[nt][2], c[nt][3],
                             fa0, fa1, fa2, fa3, fb0, fb1);
                }
            }
        }
        __syncthreads();   // all MMA reads of usm done before in-place epilogue

        // in-place epilogue: y = gelu(c + Dh * u), u = tf32 bits in usm
        int base = mh * 128;
        #pragma unroll
        for (int nt = 0; nt < 8; nt++) {
            int col = nt * 8 + 2 * tg;         // seq local
            int row = 16 * w + g;              // kout local
            float u00 = __uint_as_float(usm[col * 260 + base + row]);
            float u10 = __uint_as_float(usm[(col + 1) * 260 + base + row]);
            float u08 = __uint_as_float(usm[col * 260 + base + row + 8]);
            float u18 = __uint_as_float(usm[(col + 1) * 260 + base + row + 8]);
            usm[col * 260 + base + row] =
                __float_as_uint(gelu_f(fmaf(Dh, u00, c[nt][0])));
            usm[(col + 1) * 260 + base + row] =
                __float_as_uint(gelu_f(fmaf(Dh, u10, c[nt][1])));
            usm[col * 260 + base + row + 8] =
                __float_as_uint(gelu_f(fmaf(Dh, u08, c[nt][2])));
            usm[(col + 1) * 260 + base + row + 8] =
                __float_as_uint(gelu_f(fmaf(Dh, u18, c[nt][3])));
        }
        __syncthreads();

        // coalesced g_y write, tf32-truncated
        for (int idx = tid; idx < 64 * 128; idx += 256) {
            int srow = idx >> 7, k = idx & 127;
            int seq = s0 + srow, kout = base + k;
            if (seq < 1000 && kout < 250)
                g_y[seq * SEQ_STRIDE + h * 250 + kout] = __uint_as_float(
                    f2tf32(__uint_as_float(usm[srow * 260 + base + k])));
        }
    }
}

// ------ FUSED: ow GEMM + GLU (smem) + lw GEMM + bias + GN stats, per seq -----
__global__ void fused_ow_lw(int path, const float* __restrict__ ob,
                            const float* __restrict__ lb)
{
    extern __shared__ unsigned int dynsm[];
    unsigned int* gsm  = dynsm;            // 32256 u32: [l][129]
    unsigned int* cbuf = dynsm + 32256;    // 2 x 8448 u32 per half
    __shared__ float rs[512], rs2[512];

    int seq  = blockIdx.x;
    int tid  = threadIdx.x;
    int w    = tid >> 5, lane = tid & 31;
    int half = tid >> 8;
    int lt   = tid & 255;
    int w8   = w & 7;
    int g = lane >> 2, tg = lane & 3;
    int yb = seq * SEQ_STRIDE;

    unsigned int* hbuf = cbuf + half * 8448;
    unsigned int hbase = (unsigned int)__cvta_generic_to_shared(hbuf);

    // ---------------- phase 1: z = ow@y+ob, GLU -> gsm ----------------
    for (int li = 0; li < 2; li++) {
        int l0 = li * 128 + half * 64;
        float c[2][8][4];
        #pragma unroll
        for (int m = 0; m < 2; m++)
            #pragma unroll
            for (int nt = 0; nt < 8; nt++)
                #pragma unroll
                for (int i = 0; i < 4; i++)
                    c[m][nt][i] = 0.f;

        __syncthreads();
        {
            #pragma unroll
            for (int j = 0; j < 4; j++) {
                int q = lt + 256 * j;
                int kk = q >> 5, pos = (q & 31) * 2;
                int lg = l0 + pos;
                int rem = 250 - lg;
                int bytes = (rem <= 0) ? 0 : (rem >= 2 ? 8 : 4);
                const float* src = (rem <= 0) ? g_y : &g_y[yb + kk * 250 + lg];
                cp_async8(hbase + (kk * 72 + pos) * 4, src, bytes);
            }
            cp_commit();
        }
        for (int kcid = 0; kcid < 4; kcid++) {
            cp_wait0();
            __syncthreads();
            if (kcid < 3) {
                int kcn = (kcid + 1) * 32;
                unsigned int dstb = hbase + (((kcid + 1) & 1) * 2304) * 4;
                #pragma unroll
                for (int j = 0; j < 4; j++) {
                    int q = lt + 256 * j;
                    int kk = q >> 5, pos = (q & 31) * 2;
                    int lg = l0 + pos;
                    int rem = 250 - lg;
                    int bytes = (rem <= 0) ? 0 : (rem >= 2 ? 8 : 4);
                    const float* src = (rem <= 0) ? g_y
                        : &g_y[yb + (kcn + kk) * 250 + lg];
                    cp_async8(dstb + (kk * 72 + pos) * 4, src, bytes);
                }
                cp_commit();
            }
            unsigned int* ybuf = hbuf + (kcid & 1) * 2304;
            int kc32 = kcid;
            #pragma unroll
            for (int ks = 0; ks < 4; ks++) {
                int kb = ks * 8;
                unsigned int fa0[2], fa1[2], fa2[2], fa3[2];
                #pragma unroll
                for (int m = 0; m < 2; m++) {
                    const uint4 Av = *(const uint4*)&g_owf[path * 32768 +
                        ((((kc32 * 8 + w8) * 4 + ks) * 2 + m) * 32 + lane) * 4];
                    fa0[m] = Av.x; fa1[m] = Av.y; fa2[m] = Av.z; fa3[m] = Av.w;
                }
                #pragma unroll
                for (int nt = 0; nt < 8; nt++) {
                    unsigned int fb0 = ybuf[(kb + tg) * 72 + nt * 8 + g];
                    unsigned int fb1 = ybuf[(kb + tg + 4) * 72 + nt * 8 + g];
                    #pragma unroll
                    for (int m = 0; m < 2; m++)
                        mma_tf32(c[m][nt][0], c[m][nt][1], c[m][nt][2], c[m][nt][3],
                                 fa0[m], fa1[m], fa2[m], fa3[m], fb0, fb1);
                }
            }
        }
        float ba0 = ob[16 * w8 + g],        ba8 = ob[16 * w8 + g + 8];
        float bb0 = ob[128 + 16 * w8 + g],  bb8 = ob[128 + 16 * w8 + g + 8];
        int rowA = 16 * w8 + g;
        #pragma unroll
        for (int nt = 0; nt < 8; nt++) {
            int col = nt * 8 + 2 * tg;
            if (l0 + col < 250) {
                float z1 = c[0][nt][0] + ba0, z2 = c[1][nt][0] + bb0;
                float z3 = c[0][nt][2] + ba8, z4 = c[1][nt][2] + bb8;
                gsm[(l0 + col) * 129 + rowA] =
                    f2tf32(__fdividef(z1, 1.f + __expf(-z2)));
                gsm[(l0 + col) * 129 + rowA + 8] =
                    f2tf32(__fdividef(z3, 1.f + __expf(-z4)));
            }
            if (l0 + col + 1 < 250) {
                float z1 = c[0][nt][1] + ba0, z2 = c[1][nt][1] + bb0;
                float z3 = c[0][nt][3] + ba8, z4 = c[1][nt][3] + bb8;
                gsm[(l0 + col + 1) * 129 + rowA] =
                    f2tf32(__fdividef(z1, 1.f + __expf(-z2)));
                gsm[(l0 + col + 1) * 129 + rowA + 8] =
                    f2tf32(__fdividef(z3, 1.f + __expf(-z4)));
            }
        }
    }
    __syncthreads();

    // ------------ phase 2: b2_flat = lw @ g_flat + lb, fused stats -----------
    float s_ = 0.f, ss_ = 0.f;
    for (int ri = 0; ri < 2; ri++) {
        int r0 = ri * 128 + half * 64;
        float c2[8][4];
        #pragma unroll
        for (int nt = 0; nt < 8; nt++)
            #pragma unroll
            for (int i = 0; i < 4; i++)
                c2[nt][i] = 0.f;

        for (int kc2 = 0; kc2 < 128; kc2 += 32) {
            __syncthreads();
            for (int idx = lt; idx < 64 * 32; idx += 256) {
                int r = idx >> 5, kk = idx & 31;
                int rg = r0 + r;
                unsigned int val = 0u;
                if (rg < 250) {
                    int o = rg * 128 + kc2 + kk;
                    int n = o / 250, l = o - n * 250;
                    val = gsm[l * 129 + n];
                }
                hbuf[r * 40 + kk] = val;
            }
            __syncthreads();
            int kc32 = kc2 >> 5;
            #pragma unroll
            for (int ks = 0; ks < 4; ks++) {
                int kb = ks * 8;
                const uint4 Av = *(const uint4*)&g_lwf[path * 16384 +
                    (((kc32 * 8 + w8) * 4 + ks) * 32 + lane) * 4];
                #pragma unroll
                for (int nt = 0; nt < 8; nt++) {
                    unsigned int fb0 = hbuf[(nt * 8 + g) * 40 + kb + tg];
                    unsigned int fb1 = hbuf[(nt * 8 + g) * 40 + kb + tg + 4];
                    mma_tf32(c2[nt][0], c2[nt][1], c2[nt][2], c2[nt][3],
                             Av.x, Av.y, Av.z, Av.w, fb0, fb1);
                }
            }
        }
        float* obuf = (float*)hbuf;
        float bv0 = lb[16 * w8 + g], bv8 = lb[16 * w8 + g + 8];
        int ocol = 16 * w8 + g;
        __syncthreads();
        #pragma unroll
        for (int nt = 0; nt < 8; nt++) {
            int trow = nt * 8 + 2 * tg;
            obuf[trow * 132 + ocol]           = c2[nt][0] + bv0;
            obuf[(trow + 1) * 132 + ocol]     = c2[nt][1] + bv0;
            obuf[trow * 132 + ocol + 8]       = c2[nt][2] + bv8;
            obuf[(trow + 1) * 132 + ocol + 8] = c2[nt][3] + bv8;
        }
        __syncthreads();
        for (int i4 = lt; i4 < 64 * 32; i4 += 256) {
            int r = i4 >> 5, c4 = i4 & 31;
            int rg = r0 + r;
            if (rg < 250) {
                float4 v = *(float4*)&obuf[r * 132 + c4 * 4];
                *(float4*)&g_b2[yb + rg * 128 + c4 * 4] = v;
                s_ += (v.x + v.y) + (v.z + v.w);
                ss_ = fmaf(v.x, v.x, ss_);
                ss_ = fmaf(v.y, v.y, ss_);
                ss_ = fmaf(v.z, v.z, ss_);
                ss_ = fmaf(v.w, v.w, ss_);
            }
        }
    }
    rs[tid] = s_; rs2[tid] = ss_;
    __syncthreads();
    for (int st = 256; st > 0; st >>= 1) {
        if (tid < st) { rs[tid] += rs[tid + st]; rs2[tid] += rs2[tid + st]; }
        __syncthreads();
    }
    if (tid == 0) {
        g_redl[seq * 2 + 0] = rs[0];
        g_redl[seq * 2 + 1] = rs2[0];
    }
}

// ------------- GroupNorm stats combine (deterministic) -----------------------
__global__ void red_combine()
{
    int b = blockIdx.x;
    int tid = threadIdx.x;
    float s = 0.f, ss = 0.f;
    for (int i = tid; i < 250; i += 256) {
        s  += g_redl[(b * 250 + i) * 2 + 0];
        ss += g_redl[(b * 250 + i) * 2 + 1];
    }
    __shared__ float sm[256], sm2[256];
    sm[tid] = s; sm2[tid] = ss;
    __syncthreads();
    for (int st = 128; st > 0; st >>= 1) {
        if (tid < st) { sm[tid] += sm[tid + st]; sm2[tid] += sm2[tid + st]; }
        __syncthreads();
    }
    if (tid == 0) {
        float inv = 1.f / (float)PER_B;
        float mu = sm[0] * inv;
        float var = sm2[0] * inv - mu * mu;
        g_stats[b * 2 + 0] = mu;
        g_stats[b * 2 + 1] = rsqrtf(var + 1e-8f);
    }
}

// -------- intra finalize (float2): transpose b2 -> [B,N,K,S], GN, + x --------
__global__ void finalize_intra(const float* __restrict__ x,
                               const float* __restrict__ gg,
                               const float* __restrict__ gb)
{
    __shared__ float tile[32][33];
    int bh = blockIdx.x;
    int b = bh >> 7, n = bh & 127;
    int k0 = blockIdx.y * 32, s0 = blockIdx.z * 32;
    int tx = threadIdx.x, ty = threadIdx.y;
    float mu = g_stats[b * 2], istd = g_stats[b * 2 + 1];
    float ga = gg[n] * istd;
    float gbb = gb[n] - mu * ga;

    #pragma unroll
    for (int i = 0; i < 2; i++) {
        int s = s0 + ty + 16 * i;
        int k = k0 + 2 * tx;
        if (s < 250 && k < 250) {
            float2 v = *(const float2*)&g_b2[(b * 250 + s) * SEQ_STRIDE + n * 250 + k];
            tile[ty + 16 * i][2 * tx]     = v.x;
            tile[ty + 16 * i][2 * tx + 1] = v.y;
        }
    }
    __syncthreads();
    #pragma unroll
    for (int i = 0; i < 2; i++) {
        int k = k0 + ty + 16 * i;
        int s = s0 + 2 * tx;
        if (s < 250 && k < 250) {
            int xi = ((b * 128 + n) * 250 + k) * 250 + s;
            float2 xv = *(const float2*)&x[xi];
            float2 r;
            r.x = tile[2 * tx][ty + 16 * i] * ga + gbb + xv.x;
            r.y = tile[2 * tx + 1][ty + 16 * i] * ga + gbb + xv.y;
            *(float2*)&g_X1[xi] = r;
        }
    }
}

// ------------- inter finalize: GN + residual (float2) ------------------------
__global__ void finalize_inter(const float* __restrict__ gg,
                               const float* __restrict__ gb,
                               float* __restrict__ out)
{
    int idx2 = blockIdx.x * 256 + threadIdx.x;
    if (idx2 < TOT / 2) {
        int idx = idx2 * 2;
        int b = idx / PER_B;
        int rem = idx - b * PER_B;
        int n = rem / 62500;
        int rem2 = rem - n * 62500;
        int k = rem2 / 250;
        int s = rem2 - k * 250;
        float2 v2 = *(const float2*)&g_b2[(b * 250 + k) * SEQ_STRIDE + n * 250 + s];
        float2 x1 = *(const float2*)&g_X1[idx];
        float mu = g_stats[b * 2], istd = g_stats[b * 2 + 1];
        float ga = gg[n] * istd;
        float gbb = gb[n] - mu * ga;
        float2 r;
        r.x = v2.x * ga + gbb + x1.x;
        r.y = v2.y * ga + gbb + x1.y;
        *(float2*)&out[idx] = r;
    }
}

extern "C" void kernel_launch(void* const* d_in, const int* in_sizes, int n_in,
                              void* d_out, int out_size)
{
    const float* x = (const float*)d_in[0];
    const float* P[2][12];
    for (int p = 0; p < 2; p++)
        for (int i = 0; i < 12; i++)
            P[p][i] = (const float*)d_in[1 + p * 12 + i];
    float* out = (float*)d_out;

    cudaFuncSetAttribute(fused_ow_lw,
                         cudaFuncAttributeMaxDynamicSharedMemorySize, FUSED_SMEM);
    cudaFuncSetAttribute(conv_gemm,
                         cudaFuncAttributeMaxDynamicSharedMemorySize, CONV_SMEM);

    kern_gen<<<128, 256>>>(P[0][0], P[0][1], P[0][2], P[0][3], P[0][4], 0);
    kern_gen<<<128, 256>>>(P[1][0], P[1][1], P[1][2], P[1][3], P[1][4], 1);
    pack_w<<<384, 256>>>(P[0][6], P[0][8], P[1][6], P[1][8]);

    // ---- intra path ----
    conv_gemm<<<dim3(128, 16), 256, CONV_SMEM>>>(0, x, P[0][5]);
    fused_ow_lw<<<NSEQ, 512, FUSED_SMEM>>>(0, P[0][7], P[0][9]);
    red_combine<<<4, 256>>>();
    finalize_intra<<<dim3(512, 8, 8), dim3(16, 16)>>>(x, P[0][10], P[0][11]);

    // ---- inter path ----
    conv_gemm<<<dim3(128, 16), 256, CONV_SMEM>>>(1, x, P[1][5]);
    fused_ow_lw<<<NSEQ, 512, FUSED_SMEM>>>(1, P[1][7], P[1][9]);
    red_combine<<<4, 256>>>();
    finalize_inter<<<62500, 256>>>(P[1][10], P[1][11], out);
}

// round 16
// speedup vs baseline: 2.3061x; 1.0538x over previous
#include <cuda_runtime.h>
#include <stdint.h>
#include <math.h>

// Problem constants
#define Bb 4
#define Nn 128
#define Kk 250
#define Ss 250
#define Mm 32
#define NSEQ 1000
#define LSEQ 250
#define SEQ_STRIDE 32000
#define TOT 32000000
#define PER_B 8000000

#define FUSED_SMEM 196608
#define CONV_SMEM 68096   // ksm 1536 | usm 64*260*4 = 66560

__device__ float g_y[TOT];                  // holds tf32-truncated bit patterns
__device__ float g_b2[TOT];
__device__ float g_X1[TOT];
__device__ float g_kern[2 * 128 * 384];
__device__ unsigned int g_owf[2 * 32768];
__device__ unsigned int g_lwf[2 * 16384];
__device__ float g_redl[1000 * 2];
__device__ float g_stats[Bb * 2];

__device__ __forceinline__ unsigned int f2tf32(float f)
{
    unsigned int u;
    asm("cvt.rna.tf32.f32 %0, %1;" : "=r"(u) : "f"(f));
    return u;
}

__device__ __forceinline__ float gelu_f(float v)
{
    float t = 0.7978845608028654f * fmaf(0.044715f * v, v * v, v);
    float tc = fminf(fmaxf(t, -15.f), 15.f);
    float et = __expf(2.f * tc);
    float th = __fdividef(et - 1.f, et + 1.f);
    return 0.5f * v * (1.f + th);
}

__device__ __forceinline__ void mma_tf32(float& c0, float& c1, float& c2, float& c3,
                                         unsigned int fa0, unsigned int fa1,
                                         unsigned int fa2, unsigned int fa3,
                                         unsigned int fb0, unsigned int fb1)
{
    asm volatile("mma.sync.aligned.m16n8k8.row.col.f32.tf32.tf32.f32 "
                 "{%0,%1,%2,%3}, {%4,%5,%6,%7}, {%8,%9}, {%0,%1,%2,%3};"
                 : "+f"(c0), "+f"(c1), "+f"(c2), "+f"(c3)
                 : "r"(fa0), "r"(fa1), "r"(fa2), "r"(fa3), "r"(fb0), "r"(fb1));
}

__device__ __forceinline__ void cp_async8(unsigned int dst_smem, const void* src,
                                          int src_bytes)
{
    asm volatile("cp.async.ca.shared.global [%0], [%1], 8, %2;"
                 :: "r"(dst_smem), "l"(src), "r"(src_bytes));
}
__device__ __forceinline__ void cp_commit()
{
    asm volatile("cp.async.commit_group;");
}
__device__ __forceinline__ void cp_wait0()
{
    asm volatile("cp.async.wait_group 0;");
}

// --------- kern_gen with fused param prep ------------------------------------
__global__ void kern_gen(const float* __restrict__ log_dt,
                         const float* __restrict__ logA_re,
                         const float* __restrict__ A_im,
                         const float* __restrict__ C_re,
                         const float* __restrict__ C_im,
                         int path)
{
    int h = blockIdx.x;
    int tid = threadIdx.x;
    int w = tid >> 5, m = tid & 31;

    float dt  = expf(log_dt[h]);
    float Are = -expf(logA_re[h * Mm + m]);
    float Aim = A_im[h * Mm + m];
    float dre = dt * Are, dim = dt * Aim;
    float e0  = expf(dre);
    float ar  = e0 * cosf(dim);
    float ai  = e0 * sinf(dim);
    float nre = ar - 1.0f, nim = ai;
    float d2  = Are * Are + Aim * Aim;
    float qre = (nre * Are + nim * Aim) / d2;
    float qim = (nim * Are - nre * Aim) / d2;
    float cr  = C_re[h * Mm + m], ci = C_im[h * Mm + m];
    float c2r = 2.0f * (cr * qre - ci * qim);
    float c2i = 2.0f * (cr * qim + ci * qre);

    float l0 = (float)(w * 32);
    float e = expf(l0 * dre);
    float pr = e * cosf(l0 * dim);
    float pi = e * sinf(l0 * dim);
    float* kout = &g_kern[(path * 128 + h) * 384];
    if (tid < 128) kout[tid] = 0.f;
    if (tid < 6)   kout[378 + tid] = 0.f;
    for (int i = 0; i < 32; i++) {
        int l = w * 32 + i;
        float v = fmaf(c2r, pr, -c2i * pi);
        v += __shfl_xor_sync(0xffffffffu, v, 1);
        v += __shfl_xor_sync(0xffffffffu, v, 2);
        v += __shfl_xor_sync(0xffffffffu, v, 4);
        v += __shfl_xor_sync(0xffffffffu, v, 8);
        v += __shfl_xor_sync(0xffffffffu, v, 16);
        if (m == 0 && l < 250) kout[128 + l] = v;
        float t = pr;
        pr = fmaf(ar, t, -ai * pi);
        pi = fmaf(ai, t,  ar * pi);
    }
}

// --------- pack weights (both paths, one launch) -----------------------------
__global__ void pack_w(const float* __restrict__ ow0, const float* __restrict__ lw0,
                       const float* __restrict__ ow1, const float* __restrict__ lw1)
{
    int gidx = blockIdx.x * 256 + threadIdx.x;
    int path = gidx >= 49152;
    int idx  = gidx - path * 49152;
    const float* ow = path ? ow1 : ow0;
    const float* lw = path ? lw1 : lw0;
    if (idx < 32768) {
        int j = idx & 3;
        int lane = (idx >> 2) & 31;
        int m = (idx >> 7) & 1;
        int ks = (idx >> 8) & 3;
        int w8 = (idx >> 10) & 7;
        int kc32 = (idx >> 13) & 3;
        int g = lane >> 2, tg = lane & 3;
        int row = m * 128 + 16 * w8 + g + ((j & 1) ? 8 : 0);
        int col = kc32 * 32 + ks * 8 + tg + ((j >> 1) ? 4 : 0);
        g_owf[path * 32768 + idx] = f2tf32(ow[row * 128 + col]);
    } else {
        int id2 = idx - 32768;
        int j = id2 & 3;
        int lane = (id2 >> 2) & 31;
        int ks = (id2 >> 7) & 3;
        int w8 = (id2 >> 9) & 7;
        int kc32 = (id2 >> 12) & 3;
        int g = lane >> 2, tg = lane & 3;
        int row = 16 * w8 + g + ((j & 1) ? 8 : 0);
        int col = kc32 * 32 + ks * 8 + tg + ((j >> 1) ? 4 : 0);
        g_lwf[path * 16384 + id2] = f2tf32(lw[row * 128 + col]);
    }
}

// ------- conv: compile-time unrolled MMA over resident u ---------------------
template<int MH, int NCH>
__device__ __forceinline__ void conv_mma_half(const unsigned int* ksm,
                                              const unsigned int* usm,
                                              int w, int g, int tg, float c[8][4])
{
    #pragma unroll
    for (int ch = 0; ch < NCH; ch++) {
        int ki0 = ch * 32;
        #pragma unroll
        for (int ks = 0; ks < 4; ks++) {
            int kb = ks * 8;
            int aoff = 128 + MH * 128 + 16 * w - ki0 - kb;
            unsigned int fa0 = ksm[aoff + g - tg];
            unsigned int fa1 = ksm[aoff + 8 + g - tg];
            unsigned int fa2 = ksm[aoff + g - tg - 4];
            unsigned int fa3 = ksm[aoff + 8 + g - tg - 4];
            #pragma unroll
            for (int nt = 0; nt < 8; nt++) {
                unsigned int fb0 = usm[(nt * 8 + g) * 260 + ki0 + kb + tg];
                unsigned int fb1 = usm[(nt * 8 + g) * 260 + ki0 + kb + tg + 4];
                mma_tf32(c[nt][0], c[nt][1], c[nt][2], c[nt][3],
                         fa0, fa1, fa2, fa3, fb0, fb1);
            }
        }
    }
}

// grid (h, 16 seq-tiles), 256 thr. usm [64 seq][260] tf32 bits.
__global__ void __launch_bounds__(256, 3)
conv_gemm(int path, const float* __restrict__ x, const float* __restrict__ Dv)
{
    extern __shared__ char smr[];
    unsigned int* ksm = (unsigned int*)smr;             // 384 words
    unsigned int* usm = (unsigned int*)(smr + 1536);    // [64][260]

    int h   = blockIdx.x;
    int s0  = blockIdx.y * 64;
    int tid = threadIdx.x;
    int w = tid >> 5, lane = tid & 31;
    int g = lane >> 2, tg = lane & 3;

    const float* kern = &g_kern[(path * 128 + h) * 384];
    for (int i = tid; i < 384; i += 256) ksm[i] = f2tf32(kern[i]);

    if (path == 0) {
        for (int idx = tid; idx < 256 * 64; idx += 256) {
            int kk = idx >> 6, srow = idx & 63;
            int seq = s0 + srow;
            float v = 0.f;
            if (seq < 1000 && kk < 250) {
                int b = seq / 250, s = seq - b * 250;
                v = x[((b * 128 + h) * 250 + kk) * 250 + s];
            }
            usm[srow * 260 + kk] = f2tf32(v);
        }
    } else {
        for (int idx = tid; idx < 64 * 256; idx += 256) {
            int srow = idx >> 8, kk = idx & 255;
            int seq = s0 + srow;
            float v = 0.f;
            if (seq < 1000 && kk < 250) {
                int b = seq / 250, kq = seq - b * 250;
                v = g_X1[b * PER_B + h * 62500 + kq * 250 + kk];
            }
            usm[srow * 260 + kk] = f2tf32(v);
        }
    }
    __syncthreads();

    float Dh = Dv[h];

    // mh=1 first (reads l 0..249), then mh=0 (reads l 0..127)
    #pragma unroll
    for (int mh = 1; mh >= 0; mh--) {
        float c[8][4];
        #pragma unroll
        for (int nt = 0; nt < 8; nt++)
            #pragma unroll
            for (int i = 0; i < 4; i++)
                c[nt][i] = 0.f;

        if (mh) conv_mma_half<1, 8>(ksm, usm, w, g, tg, c);
        else    conv_mma_half<0, 4>(ksm, usm, w, g, tg, c);
        __syncthreads();

        int base = mh * 128;
        #pragma unroll
        for (int nt = 0; nt < 8; nt++) {
            int col = nt * 8 + 2 * tg;
            int row = 16 * w + g;
            float u00 = __uint_as_float(usm[col * 260 + base + row]);
            float u10 = __uint_as_float(usm[(col + 1) * 260 + base + row]);
            float u08 = __uint_as_float(usm[col * 260 + base + row + 8]);
            float u18 = __uint_as_float(usm[(col + 1) * 260 + base + row + 8]);
            usm[col * 260 + base + row] =
                __float_as_uint(gelu_f(fmaf(Dh, u00, c[nt][0])));
            usm[(col + 1) * 260 + base + row] =
                __float_as_uint(gelu_f(fmaf(Dh, u10, c[nt][1])));
            usm[col * 260 + base + row + 8] =
                __float_as_uint(gelu_f(fmaf(Dh, u08, c[nt][2])));
            usm[(col + 1) * 260 + base + row + 8] =
                __float_as_uint(gelu_f(fmaf(Dh, u18, c[nt][3])));
        }
        __syncthreads();

        for (int idx = tid; idx < 64 * 128; idx += 256) {
            int srow = idx >> 7, k = idx & 127;
            int seq = s0 + srow, kout = base + k;
            if (seq < 1000 && kout < 250)
                g_y[seq * SEQ_STRIDE + h * 250 + kout] = __uint_as_float(
                    f2tf32(__uint_as_float(usm[srow * 260 + base + k])));
        }
    }
}

// ------ FUSED: ow GEMM + GLU (linear gsm) + lw GEMM + bias + GN stats --------
__global__ void fused_ow_lw(int path, const float* __restrict__ ob,
                            const float* __restrict__ lb)
{
    extern __shared__ unsigned int dynsm[];
    unsigned int* gsm  = dynsm;            // 32000 u32: linear p = n*250 + l
    unsigned int* cbuf = dynsm + 32000;    // 2 x 8448 u32 per half
    __shared__ float rs[512], rs2[512];

    int seq  = blockIdx.x;
    int tid  = threadIdx.x;
    int w    = tid >> 5, lane = tid & 31;
    int half = tid >> 8;
    int lt   = tid & 255;
    int w8   = w & 7;
    int g = lane >> 2, tg = lane & 3;
    int yb = seq * SEQ_STRIDE;

    unsigned int* hbuf = cbuf + half * 8448;
    unsigned int hbase = (unsigned int)__cvta_generic_to_shared(hbuf);

    // ---------------- phase 1: z = ow@y+ob, GLU -> gsm (linear) --------------
    for (int li = 0; li < 2; li++) {
        int l0 = li * 128 + half * 64;
        float c[2][8][4];
        #pragma unroll
        for (int m = 0; m < 2; m++)
            #pragma unroll
            for (int nt = 0; nt < 8; nt++)
                #pragma unroll
                for (int i = 0; i < 4; i++)
                    c[m][nt][i] = 0.f;

        __syncthreads();
        {
            #pragma unroll
            for (int j = 0; j < 4; j++) {
                int q = lt + 256 * j;
                int kk = q >> 5, pos = (q & 31) * 2;
                int lg = l0 + pos;
                int rem = 250 - lg;
                int bytes = (rem <= 0) ? 0 : (rem >= 2 ? 8 : 4);
                const float* src = (rem <= 0) ? g_y : &g_y[yb + kk * 250 + lg];
                cp_async8(hbase + (kk * 72 + pos) * 4, src, bytes);
            }
            cp_commit();
        }
        for (int kcid = 0; kcid < 4; kcid++) {
            cp_wait0();
            __syncthreads();
            if (kcid < 3) {
                int kcn = (kcid + 1) * 32;
                unsigned int dstb = hbase + (((kcid + 1) & 1) * 2304) * 4;
                #pragma unroll
                for (int j = 0; j < 4; j++) {
                    int q = lt + 256 * j;
                    int kk = q >> 5, pos = (q & 31) * 2;
                    int lg = l0 + pos;
                    int rem = 250 - lg;
                    int bytes = (rem <= 0) ? 0 : (rem >= 2 ? 8 : 4);
                    const float* src = (rem <= 0) ? g_y
                        : &g_y[yb + (kcn + kk) * 250 + lg];
                    cp_async8(dstb + (kk * 72 + pos) * 4, src, bytes);
                }
                cp_commit();
            }
            unsigned int* ybuf = hbuf + (kcid & 1) * 2304;
            int kc32 = kcid;
            #pragma unroll
            for (int ks = 0; ks < 4; ks++) {
                int kb = ks * 8;
                unsigned int fa0[2], fa1[2], fa2[2], fa3[2];
                #pragma unroll
                for (int m = 0; m < 2; m++) {
                    const uint4 Av = *(const uint4*)&g_owf[path * 32768 +
                        ((((kc32 * 8 + w8) * 4 + ks) * 2 + m) * 32 + lane) * 4];
                    fa0[m] = Av.x; fa1[m] = Av.y; fa2[m] = Av.z; fa3[m] = Av.w;
                }
                #pragma unroll
                for (int nt = 0; nt < 8; nt++) {
                    unsigned int fb0 = ybuf[(kb + tg) * 72 + nt * 8 + g];
                    unsigned int fb1 = ybuf[(kb + tg + 4) * 72 + nt * 8 + g];
                    #pragma unroll
                    for (int m = 0; m < 2; m++)
                        mma_tf32(c[m][nt][0], c[m][nt][1], c[m][nt][2], c[m][nt][3],
                                 fa0[m], fa1[m], fa2[m], fa3[m], fb0, fb1);
                }
            }
        }
        float ba0 = ob[16 * w8 + g],        ba8 = ob[16 * w8 + g + 8];
        float bb0 = ob[128 + 16 * w8 + g],  bb8 = ob[128 + 16 * w8 + g + 8];
        int rowA = 16 * w8 + g;
        #pragma unroll
        for (int nt = 0; nt < 8; nt++) {
            int col = nt * 8 + 2 * tg;
            if (l0 + col < 250) {
                float z1 = c[0][nt][0] + ba0, z2 = c[1][nt][0] + bb0;
                float z3 = c[0][nt][2] + ba8, z4 = c[1][nt][2] + bb8;
                gsm[rowA * 250 + l0 + col] =
                    f2tf32(__fdividef(z1, 1.f + __expf(-z2)));
                gsm[(rowA + 8) * 250 + l0 + col] =
                    f2tf32(__fdividef(z3, 1.f + __expf(-z4)));
            }
            if (l0 + col + 1 < 250) {
                float z1 = c[0][nt][1] + ba0, z2 = c[1][nt][1] + bb0;
                float z3 = c[0][nt][3] + ba8, z4 = c[1][nt][3] + bb8;
                gsm[rowA * 250 + l0 + col + 1] =
                    f2tf32(__fdividef(z1, 1.f + __expf(-z2)));
                gsm[(rowA + 8) * 250 + l0 + col + 1] =
                    f2tf32(__fdividef(z3, 1.f + __expf(-z4)));
            }
        }
    }
    __syncthreads();

    // ------------ phase 2: b2_flat = lw @ g_flat + lb, fused stats -----------
    // key: flat element (rg, kk) == gsm[rg*128 + kc2 + kk] (pure linear view)
    float s_ = 0.f, ss_ = 0.f;
    for (int ri = 0; ri < 2; ri++) {
        int r0 = ri * 128 + half * 64;
        float c2[8][4];
        #pragma unroll
        for (int nt = 0; nt < 8; nt++)
            #pragma unroll
            for (int i = 0; i < 4; i++)
                c2[nt][i] = 0.f;

        __syncthreads();   // hbuf free (prev obuf reads / phase-1 ybuf done)
        for (int idx = lt; idx < 64 * 32; idx += 256) {
            int r = idx >> 5, kk = idx & 31;
            int rg = r0 + r;
            hbuf[r * 40 + kk] = (rg < 250) ? gsm[rg * 128 + kk] : 0u;
        }
        __syncthreads();
        for (int kc = 0; kc < 4; kc++) {
            if (kc < 3) {
                unsigned int* nb = hbuf + ((kc + 1) & 1) * 2560;
                int kcn = (kc + 1) * 32;
                for (int idx = lt; idx < 64 * 32; idx += 256) {
                    int r = idx >> 5, kk = idx & 31;
                    int rg = r0 + r;
                    nb[r * 40 + kk] = (rg < 250) ? gsm[rg * 128 + kcn + kk] : 0u;
                }
            }
            unsigned int* cb = hbuf + (kc & 1) * 2560;
            #pragma unroll
            for (int ks = 0; ks < 4; ks++) {
                int kb = ks * 8;
                const uint4 Av = *(const uint4*)&g_lwf[path * 16384 +
                    (((kc * 8 + w8) * 4 + ks) * 32 + lane) * 4];
                #pragma unroll
                for (int nt = 0; nt < 8; nt++) {
                    unsigned int fb0 = cb[(nt * 8 + g) * 40 + kb + tg];
                    unsigned int fb1 = cb[(nt * 8 + g) * 40 + kb + tg + 4];
                    mma_tf32(c2[nt][0], c2[nt][1], c2[nt][2], c2[nt][3],
                             Av.x, Av.y, Av.z, Av.w, fb0, fb1);
                }
            }
            __syncthreads();
        }
        float* obuf = (float*)hbuf;
        float bv0 = lb[16 * w8 + g], bv8 = lb[16 * w8 + g + 8];
        int ocol = 16 * w8 + g;
        #pragma unroll
        for (int nt = 0; nt < 8; nt++) {
            int trow = nt * 8 + 2 * tg;
            obuf[trow * 132 + ocol]           = c2[nt][0] + bv0;
            obuf[(trow + 1) * 132 + ocol]     = c2[nt][1] + bv0;
            obuf[trow * 132 + ocol + 8]       = c2[nt][2] + bv8;
            obuf[(trow + 1) * 132 + ocol + 8] = c2[nt][3] + bv8;
        }
        __syncthreads();
        for (int i4 = lt; i4 < 64 * 32; i4 += 256) {
            int r = i4 >> 5, c4 = i4 & 31;
            int rg = r0 + r;
            if (rg < 250) {
                float4 v = *(float4*)&obuf[r * 132 + c4 * 4];
                *(float4*)&g_b2[yb + rg * 128 + c4 * 4] = v;
                s_ += (v.x + v.y) + (v.z + v.w);
                ss_ = fmaf(v.x, v.x, ss_);
                ss_ = fmaf(v.y, v.y, ss_);
                ss_ = fmaf(v.z, v.z, ss_);
                ss_ = fmaf(v.w, v.w, ss_);
            }
        }
    }
    rs[tid] = s_; rs2[tid] = ss_;
    __syncthreads();
    for (int st = 256; st > 0; st >>= 1) {
        if (tid < st) { rs[tid] += rs[tid + st]; rs2[tid] += rs2[tid + st]; }
        __syncthreads();
    }
    if (tid == 0) {
        g_redl[seq * 2 + 0] = rs[0];
        g_redl[seq * 2 + 1] = rs2[0];
    }
}

// ------------- GroupNorm stats combine (deterministic) -----------------------
__global__ void red_combine()
{
    int b = blockIdx.x;
    int tid = threadIdx.x;
    float s = 0.f, ss = 0.f;
    for (int i = tid; i < 250; i += 256) {
        s  += g_redl[(b * 250 + i) * 2 + 0];
        ss += g_redl[(b * 250 + i) * 2 + 1];
    }
    __shared__ float sm[256], sm2[256];
    sm[tid] = s; sm2[tid] = ss;
    __syncthreads();
    for (int st = 128; st > 0; st >>= 1) {
        if (tid < st) { sm[tid] += sm[tid + st]; sm2[tid] += sm2[tid + st]; }
        __syncthreads();
    }
    if (tid == 0) {
        float inv = 1.f / (float)PER_B;
        float mu = sm[0] * inv;
        float var = sm2[0] * inv - mu * mu;
        g_stats[b * 2 + 0] = mu;
        g_stats[b * 2 + 1] = rsqrtf(var + 1e-8f);
    }
}

// -------- intra finalize (float2): transpose b2 -> [B,N,K,S], GN, + x --------
__global__ void finalize_intra(const float* __restrict__ x,
                               const float* __restrict__ gg,
                               const float* __restrict__ gb)
{
    __shared__ float tile[32][33];
    int bh = blockIdx.x;
    int b = bh >> 7, n = bh & 127;
    int k0 = blockIdx.y * 32, s0 = blockIdx.z * 32;
    int tx = threadIdx.x, ty = threadIdx.y;
    float mu = g_stats[b * 2], istd = g_stats[b * 2 + 1];
    float ga = gg[n] * istd;
    float gbb = gb[n] - mu * ga;

    #pragma unroll
    for (int i = 0; i < 2; i++) {
        int s = s0 + ty + 16 * i;
        int k = k0 + 2 * tx;
        if (s < 250 && k < 250) {
            float2 v = *(const float2*)&g_b2[(b * 250 + s) * SEQ_STRIDE + n * 250 + k];
            tile[ty + 16 * i][2 * tx]     = v.x;
            tile[ty + 16 * i][2 * tx + 1] = v.y;
        }
    }
    __syncthreads();
    #pragma unroll
    for (int i = 0; i < 2; i++) {
        int k = k0 + ty + 16 * i;
        int s = s0 + 2 * tx;
        if (s < 250 && k < 250) {
            int xi = ((b * 128 + n) * 250 + k) * 250 + s;
            float2 xv = *(const float2*)&x[xi];
            float2 r;
            r.x = tile[2 * tx][ty + 16 * i] * ga + gbb + xv.x;
            r.y = tile[2 * tx + 1][ty + 16 * i] * ga + gbb + xv.y;
            *(float2*)&g_X1[xi] = r;
        }
    }
}

// ------------- inter finalize: GN + residual (float2) ------------------------
__global__ void finalize_inter(const float* __restrict__ gg,
                               const float* __restrict__ gb,
                               float* __restrict__ out)
{
    int idx2 = blockIdx.x * 256 + threadIdx.x;
    if (idx2 < TOT / 2) {
        int idx = idx2 * 2;
        int b = idx / PER_B;
        int rem = idx - b * PER_B;
        int n = rem / 62500;
        int rem2 = rem - n * 62500;
        int k = rem2 / 250;
        int s = rem2 - k * 250;
        float2 v2 = *(const float2*)&g_b2[(b * 250 + k) * SEQ_STRIDE + n * 250 + s];
        float2 x1 = *(const float2*)&g_X1[idx];
        float mu = g_stats[b * 2], istd = g_stats[b * 2 + 1];
        float ga = gg[n] * istd;
        float gbb = gb[n] - mu * ga;
        float2 r;
        r.x = v2.x * ga + gbb + x1.x;
        r.y = v2.y * ga + gbb + x1.y;
        *(float2*)&out[idx] = r;
    }
}

extern "C" void kernel_launch(void* const* d_in, const int* in_sizes, int n_in,
                              void* d_out, int out_size)
{
    const float* x = (const float*)d_in[0];
    const float* P[2][12];
    for (int p = 0; p < 2; p++)
        for (int i = 0; i < 12; i++)
            P[p][i] = (const float*)d_in[1 + p * 12 + i];
    float* out = (float*)d_out;

    cudaFuncSetAttribute(fused_ow_lw,
                         cudaFuncAttributeMaxDynamicSharedMemorySize, FUSED_SMEM);
    cudaFuncSetAttribute(conv_gemm,
                         cudaFuncAttributeMaxDynamicSharedMemorySize, CONV_SMEM);

    kern_gen<<<128, 256>>>(P[0][0], P[0][1], P[0][2], P[0][3], P[0][4], 0);
    kern_gen<<<128, 256>>>(P[1][0], P[1][1], P[1][2], P[1][3], P[1][4], 1);
    pack_w<<<384, 256>>>(P[0][6], P[0][8], P[1][6], P[1][8]);

    // ---- intra path ----
    conv_gemm<<<dim3(128, 16), 256, CONV_SMEM>>>(0, x, P[0][5]);
    fused_ow_lw<<<NSEQ, 512, FUSED_SMEM>>>(0, P[0][7], P[0][9]);
    red_combine<<<4, 256>>>();
    finalize_intra<<<dim3(512, 8, 8), dim3(16, 16)>>>(x, P[0][10], P[0][11]);

    // ---- inter path ----
    conv_gemm<<<dim3(128, 16), 256, CONV_SMEM>>>(1, x, P[1][5]);
    fused_ow_lw<<<NSEQ, 512, FUSED_SMEM>>>(1, P[1][7], P[1][9]);
    red_combine<<<4, 256>>>();
    finalize_inter<<<62500, 256>>>(P[1][10], P[1][11], out);
}